// round 7
// baseline (speedup 1.0000x reference)
#include <cuda_runtime.h>
#include <math.h>

#define BB   2
#define TT   64
#define CCB  32
#define HW   4096
#define CHW  131072
#define NHD  4
#define XD   8
#define HIDC 170
#define QKVC 192
#define PINC 340

// ---------------- scratch (static device, allocation-free) ----------------
__device__ float g_qkv  [BB*QKVC*CHW];           // 201 MB
__device__ float g_qkvdw[BB*QKVC*CHW];           // 201 MB
__device__ float g_xa   [BB*TT*CHW];             //  64 MB
__device__ float g_pin  [BB*PINC*CHW];           // 356 MB
__device__ float g_prod [BB*HIDC*CHW];           // 178 MB
__device__ float g_gram [BB*NHD*80];
__device__ float g_weff [BB*TT*TT];
__device__ float g_pool [BB*TT];
__device__ float g_se   [BB*TT];

__device__ __forceinline__ float warp_sum(float v){
    v += __shfl_xor_sync(0xffffffffu, v, 16);
    v += __shfl_xor_sync(0xffffffffu, v, 8);
    v += __shfl_xor_sync(0xffffffffu, v, 4);
    v += __shfl_xor_sync(0xffffffffu, v, 2);
    v += __shfl_xor_sync(0xffffffffu, v, 1);
    return v;
}

// ---------------- K0: zero small accumulators ----------------
__global__ void k_init(){
    int t = threadIdx.x;
    if (t < BB*NHD*80) g_gram[t] = 0.f;
    if (t < BB*TT)     g_pool[t] = 0.f;
}

// ---------------- K1: LN(channel) + 1x1 conv 64 -> 192 ----------------
__global__ void __launch_bounds__(256) k_ln_qkv(const float* __restrict__ x,
                                                const float* __restrict__ gam,
                                                const float* __restrict__ bet,
                                                const float* __restrict__ qw){
    extern __shared__ float wsh[];               // [64][192] transposed
    __shared__ float gsh[TT], bsh[TT];
    int tid = threadIdx.x;
    for (int i = tid; i < TT*QKVC; i += 256){
        int t = i / QKVC, o = i - t*QKVC;
        wsh[i] = qw[o*TT + t];
    }
    if (tid < TT){ gsh[tid] = gam[tid]; bsh[tid] = bet[tid]; }
    __syncthreads();

    int b = blockIdx.x >> 9;                     // 512 blocks per batch
    int p = ((blockIdx.x & 511) << 8) + tid;
    const float* xb = x + (size_t)b*TT*CHW + p;

    float xn[TT];
    float mean = 0.f;
#pragma unroll
    for (int t = 0; t < TT; t++){ xn[t] = xb[(size_t)t*CHW]; mean += xn[t]; }
    mean *= (1.f/TT);
    float var = 0.f;
#pragma unroll
    for (int t = 0; t < TT; t++){ float d = xn[t]-mean; var += d*d; }
    float rstd = rsqrtf(var*(1.f/TT) + 1e-5f);
#pragma unroll
    for (int t = 0; t < TT; t++) xn[t] = (xn[t]-mean)*rstd*gsh[t] + bsh[t];

    float* ob = g_qkv + (size_t)b*QKVC*CHW + p;
    for (int og = 0; og < QKVC; og += 8){
        float acc[8];
#pragma unroll
        for (int i = 0; i < 8; i++) acc[i] = 0.f;
#pragma unroll
        for (int t = 0; t < TT; t++){
            float xv = xn[t];
#pragma unroll
            for (int q = 0; q < 2; q++){
                float4 w = *(const float4*)&wsh[t*QKVC + og + 4*q];
                acc[4*q+0] = fmaf(w.x, xv, acc[4*q+0]);
                acc[4*q+1] = fmaf(w.y, xv, acc[4*q+1]);
                acc[4*q+2] = fmaf(w.z, xv, acc[4*q+2]);
                acc[4*q+3] = fmaf(w.w, xv, acc[4*q+3]);
            }
        }
#pragma unroll
        for (int i = 0; i < 8; i++) ob[(size_t)(og+i)*CHW] = acc[i];
    }
}

// ---------------- K2: depthwise 3x3 over (H,W), 192 channels ----------------
__global__ void __launch_bounds__(256) k_dw2d(const float* __restrict__ dww){
    int tid = threadIdx.x;
    int j   = tid & 63;
    int sub = tid >> 6;
    int plane = blockIdx.x*4 + sub;              // ((b*192+ch)*32 + c)
    int ch = (plane >> 5) % QKVC;
    const float* ip = g_qkv   + (size_t)plane*HW;
    float*       op = g_qkvdw + (size_t)plane*HW;
    float wv[9];
#pragma unroll
    for (int k = 0; k < 9; k++) wv[k] = __ldg(&dww[ch*9 + k]);
    bool lok = (j > 0), rok = (j < 63);
    float m0=0.f,m1=0.f,m2=0.f;
    float c0 = lok ? ip[j-1] : 0.f;
    float c1 = ip[j];
    float c2 = rok ? ip[j+1] : 0.f;
    for (int h = 0; h < 64; h++){
        float p0, p1, p2;
        if (h < 63){
            const float* r = ip + (h+1)*64;
            p0 = lok ? r[j-1] : 0.f; p1 = r[j]; p2 = rok ? r[j+1] : 0.f;
        } else { p0 = p1 = p2 = 0.f; }
        float o = wv[0]*m0 + wv[1]*m1 + wv[2]*m2
                + wv[3]*c0 + wv[4]*c1 + wv[5]*c2
                + wv[6]*p0 + wv[7]*p1 + wv[8]*p2;
        op[h*64 + j] = o;
        m0=c0; m1=c1; m2=c2; c0=p0; c1=p1; c2=p2;
    }
}

// ---------------- K3: per-head 8x8 Gram + row self-dots ----------------
__global__ void __launch_bounds__(256) k_gram(){
    int tid = threadIdx.x;
    int chunk = blockIdx.x;                       // 64 chunks of 2048 positions
    int n = blockIdx.y, b = blockIdx.z;
    const float* qb = g_qkvdw + ((size_t)b*QKVC + 16*n)*CHW;
    const float* kb = qb + (size_t)64*CHW;

    float S[XD][XD], qq[XD], kk[XD];
#pragma unroll
    for (int xi = 0; xi < XD; xi++){
        qq[xi] = 0.f; kk[xi] = 0.f;
#pragma unroll
        for (int yi = 0; yi < XD; yi++) S[xi][yi] = 0.f;
    }
    int pbase = chunk*2048 + tid;
    for (int pp = 0; pp < 8; pp++){
        int p = pbase + pp*256;
#pragma unroll
        for (int par = 0; par < 2; par++){
            float qv[XD], kv[XD];
#pragma unroll
            for (int xi = 0; xi < XD; xi++){
                qv[xi] = qb[(size_t)(2*xi + par)*CHW + p];
                kv[xi] = kb[(size_t)(2*xi + par)*CHW + p];
            }
#pragma unroll
            for (int xi = 0; xi < XD; xi++){
                qq[xi] = fmaf(qv[xi], qv[xi], qq[xi]);
                kk[xi] = fmaf(kv[xi], kv[xi], kk[xi]);
#pragma unroll
                for (int yi = 0; yi < XD; yi++)
                    S[xi][yi] = fmaf(qv[xi], kv[yi], S[xi][yi]);
            }
        }
    }
    float* acc = g_gram + (b*NHD + n)*80;
    int lane = tid & 31;
#pragma unroll
    for (int xi = 0; xi < XD; xi++){
#pragma unroll
        for (int yi = 0; yi < XD; yi++){
            float v = warp_sum(S[xi][yi]);
            if (lane == 0) atomicAdd(&acc[xi*8 + yi], v);
        }
        float vq = warp_sum(qq[xi]);
        float vk = warp_sum(kk[xi]);
        if (lane == 0){ atomicAdd(&acc[64 + xi], vq); atomicAdd(&acc[72 + xi], vk); }
    }
}

// ---------------- K4: softmax + effective 64x64 channel matrix ----------------
__global__ void k_weff(const float* __restrict__ temp, const float* __restrict__ aw){
    int b = blockIdx.x, tid = threadIdx.x;
    __shared__ float att[NHD][XD][XD];
    __shared__ float qn[NHD][XD], kn[NHD][XD];
    const float* G = g_gram + b*NHD*80;
    if (tid < 64){
        int i = tid & 31, n = i >> 3, xx = i & 7;
        if (tid < 32) qn[n][xx] = fmaxf(sqrtf(G[n*80 + 64 + xx]), 1e-12f);
        else          kn[n][xx] = fmaxf(sqrtf(G[n*80 + 72 + xx]), 1e-12f);
    }
    __syncthreads();
    if (tid < 32){
        int n = tid >> 3, xx = tid & 7;
        float tpn = temp[n];
        float sc[XD], mx = -1e30f;
#pragma unroll
        for (int y = 0; y < XD; y++){
            sc[y] = G[n*80 + xx*8 + y] / (qn[n][xx]*kn[n][y]) * tpn;
            mx = fmaxf(mx, sc[y]);
        }
        float sum = 0.f;
#pragma unroll
        for (int y = 0; y < XD; y++){ sc[y] = expf(sc[y]-mx); sum += sc[y]; }
        float inv = 1.f/sum;
#pragma unroll
        for (int y = 0; y < XD; y++) att[n][xx][y] = sc[y]*inv;
    }
    __syncthreads();
    for (int e = tid; e < TT*TT; e += blockDim.x){
        int to = e >> 6, tv = e & 63;
        int n = tv >> 4, p = tv & 1, y = (tv >> 1) & 7;
        float s = 0.f;
#pragma unroll
        for (int xx = 0; xx < XD; xx++)
            s = fmaf(aw[to*64 + 16*n + 2*xx + p], att[n][xx][y], s);
        g_weff[b*4096 + e] = s;
    }
}

// ---------------- K5: x + W_eff @ V  (attention epilogue, fused) ----------------
__global__ void __launch_bounds__(256) k_apply(const float* __restrict__ x){
    __shared__ float wsh[TT*TT];                  // [tv][to]
    int tid = threadIdx.x;
    int b = blockIdx.x >> 9;
    for (int i = tid; i < TT*TT; i += 256){
        int tv = i >> 6, to = i & 63;
        wsh[i] = g_weff[b*4096 + to*64 + tv];
    }
    __syncthreads();
    int p = ((blockIdx.x & 511) << 8) + tid;
    const float* vb = g_qkvdw + ((size_t)b*QKVC + 128)*CHW + p;
    float acc[TT];
#pragma unroll
    for (int o = 0; o < TT; o++) acc[o] = 0.f;
    for (int tv = 0; tv < TT; tv++){
        float v = vb[(size_t)tv*CHW];
        const float4* wp = (const float4*)&wsh[tv*TT];
#pragma unroll
        for (int q = 0; q < 16; q++){
            float4 w = wp[q];
            acc[4*q+0] = fmaf(w.x, v, acc[4*q+0]);
            acc[4*q+1] = fmaf(w.y, v, acc[4*q+1]);
            acc[4*q+2] = fmaf(w.z, v, acc[4*q+2]);
            acc[4*q+3] = fmaf(w.w, v, acc[4*q+3]);
        }
    }
    const float* xb = x    + (size_t)b*TT*CHW + p;
    float*       ob = g_xa + (size_t)b*TT*CHW + p;
#pragma unroll
    for (int o = 0; o < TT; o++) ob[(size_t)o*CHW] = acc[o] + xb[(size_t)o*CHW];
}

// ---------------- K6: LN(channel) + 1x1 conv 64 -> 340 ----------------
__global__ void __launch_bounds__(256) k_ln_pin(const float* __restrict__ gam,
                                                const float* __restrict__ bet,
                                                const float* __restrict__ pw){
    extern __shared__ float wsh[];                // [64][340] transposed
    __shared__ float gsh[TT], bsh[TT];
    int tid = threadIdx.x;
    for (int i = tid; i < TT*PINC; i += 256){
        int t = i / PINC, o = i - t*PINC;
        wsh[i] = pw[o*TT + t];
    }
    if (tid < TT){ gsh[tid] = gam[tid]; bsh[tid] = bet[tid]; }
    __syncthreads();

    int b = blockIdx.x >> 9;
    int p = ((blockIdx.x & 511) << 8) + tid;
    const float* xb = g_xa + (size_t)b*TT*CHW + p;

    float xn[TT];
    float mean = 0.f;
#pragma unroll
    for (int t = 0; t < TT; t++){ xn[t] = xb[(size_t)t*CHW]; mean += xn[t]; }
    mean *= (1.f/TT);
    float var = 0.f;
#pragma unroll
    for (int t = 0; t < TT; t++){ float d = xn[t]-mean; var += d*d; }
    float rstd = rsqrtf(var*(1.f/TT) + 1e-5f);
#pragma unroll
    for (int t = 0; t < TT; t++) xn[t] = (xn[t]-mean)*rstd*gsh[t] + bsh[t];

    float* ob = g_pin + (size_t)b*PINC*CHW + p;
    for (int og = 0; og < PINC; og += 20){
        float acc[20];
#pragma unroll
        for (int i = 0; i < 20; i++) acc[i] = 0.f;
#pragma unroll
        for (int t = 0; t < TT; t++){
            float xv = xn[t];
#pragma unroll
            for (int q = 0; q < 5; q++){
                float4 w = *(const float4*)&wsh[t*PINC + og + 4*q];
                acc[4*q+0] = fmaf(w.x, xv, acc[4*q+0]);
                acc[4*q+1] = fmaf(w.y, xv, acc[4*q+1]);
                acc[4*q+2] = fmaf(w.z, xv, acc[4*q+2]);
                acc[4*q+3] = fmaf(w.w, xv, acc[4*q+3]);
            }
        }
#pragma unroll
        for (int i = 0; i < 20; i++) ob[(size_t)(og+i)*CHW] = acc[i];
    }
}

// ---------------- K7: depthwise 3x3x3 + exact GELU gating ----------------
__device__ __forceinline__ void load_row3(const float* base, int cz, int h, int w,
                                          bool c0ok, bool c2ok, bool lok, bool rok,
                                          float r[9]){
#pragma unroll
    for (int cc = 0; cc < 3; cc++){
        bool cok = (cc == 0) ? c0ok : ((cc == 2) ? c2ok : true);
        const float* ptr = base + (size_t)(cz + cc - 1)*HW + h*64;
        r[cc*3+0] = (cok && lok) ? ptr[w-1] : 0.f;
        r[cc*3+1] =  cok         ? ptr[w]   : 0.f;
        r[cc*3+2] = (cok && rok) ? ptr[w+1] : 0.f;
    }
}

__global__ void __launch_bounds__(64) k_dw3d(const float* __restrict__ dww){
    int w  = threadIdx.x;
    int cz = blockIdx.x, j = blockIdx.y, b = blockIdx.z;
    const float* b1 = g_pin + (size_t)(b*PINC + j)*CHW;
    const float* b2 = g_pin + (size_t)(b*PINC + j + HIDC)*CHW;
    float* op = g_prod + ((size_t)(b*HIDC + j)*CCB + cz)*HW;

    float w1[27], w2[27];
#pragma unroll
    for (int k = 0; k < 27; k++){
        w1[k] = __ldg(&dww[j*27 + k]);
        w2[k] = __ldg(&dww[(j + HIDC)*27 + k]);
    }
    bool lok = (w > 0), rok = (w < 63);
    bool c0ok = (cz > 0), c2ok = (cz < 31);

    float rm1[9], rc1[9], rp1[9], rm2[9], rc2[9], rp2[9];
#pragma unroll
    for (int k = 0; k < 9; k++){ rm1[k] = 0.f; rm2[k] = 0.f; }
    load_row3(b1, cz, 0, w, c0ok, c2ok, lok, rok, rc1);
    load_row3(b2, cz, 0, w, c0ok, c2ok, lok, rok, rc2);

    for (int h = 0; h < 64; h++){
        if (h < 63){
            load_row3(b1, cz, h+1, w, c0ok, c2ok, lok, rok, rp1);
            load_row3(b2, cz, h+1, w, c0ok, c2ok, lok, rok, rp2);
        } else {
#pragma unroll
            for (int k = 0; k < 9; k++){ rp1[k] = 0.f; rp2[k] = 0.f; }
        }
        float a1 = 0.f, a2 = 0.f;
#pragma unroll
        for (int cc = 0; cc < 3; cc++){
#pragma unroll
            for (int kw = 0; kw < 3; kw++){
                a1 = fmaf(w1[cc*9 + 0*3 + kw], rm1[cc*3+kw], a1);
                a1 = fmaf(w1[cc*9 + 1*3 + kw], rc1[cc*3+kw], a1);
                a1 = fmaf(w1[cc*9 + 2*3 + kw], rp1[cc*3+kw], a1);
                a2 = fmaf(w2[cc*9 + 0*3 + kw], rm2[cc*3+kw], a2);
                a2 = fmaf(w2[cc*9 + 1*3 + kw], rc2[cc*3+kw], a2);
                a2 = fmaf(w2[cc*9 + 2*3 + kw], rp2[cc*3+kw], a2);
            }
        }
        float g = 0.5f*a1*(1.f + erff(a1*0.70710678118654752f));
        op[h*64 + w] = g*a2;
#pragma unroll
        for (int k = 0; k < 9; k++){
            rm1[k] = rc1[k]; rc1[k] = rp1[k];
            rm2[k] = rc2[k]; rc2[k] = rp2[k];
        }
    }
}

// ---------------- K8: 1x1 conv 170->64 + residual + SE pooling partials ----------------
__global__ void __launch_bounds__(256) k_pout(const float* __restrict__ pw,
                                              float* __restrict__ dout){
    __shared__ float wsh[HIDC*TT];                // [t][o]
    __shared__ float pool[TT];
    int tid = threadIdx.x;
    for (int i = tid; i < HIDC*TT; i += 256){
        int t = i >> 6, o = i & 63;
        wsh[i] = pw[o*HIDC + t];
    }
    if (tid < TT) pool[tid] = 0.f;
    __syncthreads();

    int b = blockIdx.x >> 9;
    int p = ((blockIdx.x & 511) << 8) + tid;
    const float* pr = g_prod + (size_t)b*HIDC*CHW + p;

    float acc[TT];
#pragma unroll
    for (int o = 0; o < TT; o++) acc[o] = 0.f;
#pragma unroll 2
    for (int t = 0; t < HIDC; t++){
        float v = pr[(size_t)t*CHW];
        const float4* wp = (const float4*)&wsh[t*TT];
#pragma unroll
        for (int q = 0; q < 16; q++){
            float4 w = wp[q];
            acc[4*q+0] = fmaf(w.x, v, acc[4*q+0]);
            acc[4*q+1] = fmaf(w.y, v, acc[4*q+1]);
            acc[4*q+2] = fmaf(w.z, v, acc[4*q+2]);
            acc[4*q+3] = fmaf(w.w, v, acc[4*q+3]);
        }
    }
    const float* xb = g_xa + (size_t)b*TT*CHW + p;
    float*       ob = dout + (size_t)b*TT*CHW + p;
    int lane = tid & 31;
#pragma unroll
    for (int o = 0; o < TT; o++){
        float r = acc[o] + xb[(size_t)o*CHW];
        ob[(size_t)o*CHW] = r;
        float v = warp_sum(r);
        if (lane == 0) atomicAdd(&pool[o], v);
    }
    __syncthreads();
    if (tid < TT) atomicAdd(&g_pool[b*TT + tid], pool[tid]);
}

// ---------------- K9: SE gate ----------------
__global__ void k_se(const float* __restrict__ sew, const float* __restrict__ seb){
    int tid = threadIdx.x;
    if (tid >= BB*TT) return;
    int b = tid >> 6, o = tid & 63;
    float s = 0.f;
#pragma unroll
    for (int t = 0; t < TT; t++)
        s = fmaf(sew[o*TT + t], g_pool[b*TT + t]*(1.f/131072.f), s);
    s += seb[o];
    g_se[b*TT + o] = 1.f/(1.f + expf(-s));
}

// ---------------- K10: in-place SE scale ----------------
__global__ void k_final(float* __restrict__ dout){
    int idx = blockIdx.x*256 + threadIdx.x;        // float4 index, 4,194,304 total
    float4* o4 = (float4*)dout;
    float s = g_se[idx >> 15];                     // 32768 float4 per channel
    float4 v = o4[idx];
    v.x *= s; v.y *= s; v.z *= s; v.w *= s;
    o4[idx] = v;
}

// ---------------- launch ----------------
extern "C" void kernel_launch(void* const* d_in, const int* in_sizes, int n_in,
                              void* d_out, int out_size){
    const float* x     = (const float*)d_in[0];
    const float* n1g   = (const float*)d_in[1];
    const float* n1b   = (const float*)d_in[2];
    const float* temp  = (const float*)d_in[3];
    const float* qkvw  = (const float*)d_in[4];
    const float* qkvdw = (const float*)d_in[5];
    const float* aow   = (const float*)d_in[6];
    const float* n2g   = (const float*)d_in[7];
    const float* n2b   = (const float*)d_in[8];
    const float* pinw  = (const float*)d_in[9];
    const float* dww   = (const float*)d_in[10];
    const float* poutw = (const float*)d_in[11];
    const float* sew   = (const float*)d_in[12];
    const float* seb   = (const float*)d_in[13];
    float* out = (float*)d_out;

    cudaFuncSetAttribute(k_ln_pin, cudaFuncAttributeMaxDynamicSharedMemorySize,
                         TT*PINC*(int)sizeof(float));
    cudaFuncSetAttribute(k_ln_qkv, cudaFuncAttributeMaxDynamicSharedMemorySize,
                         TT*QKVC*(int)sizeof(float));

    k_init  <<<1, 1024>>>();
    k_ln_qkv<<<1024, 256, TT*QKVC*sizeof(float)>>>(x, n1g, n1b, qkvw);
    k_dw2d  <<<3072, 256>>>(qkvdw);
    k_gram  <<<dim3(64, NHD, BB), 256>>>();
    k_weff  <<<BB, 256>>>(temp, aow);
    k_apply <<<1024, 256>>>(x);
    k_ln_pin<<<1024, 256, TT*PINC*sizeof(float)>>>(n2g, n2b, pinw);
    k_dw3d  <<<dim3(CCB, HIDC, BB), 64>>>(dww);
    k_pout  <<<1024, 256>>>(poutw, out);
    k_se    <<<1, 128>>>(sew, seb);
    k_final <<<16384, 256>>>(out);
}

// round 8
// speedup vs baseline: 1.0451x; 1.0451x over previous
#include <cuda_runtime.h>
#include <math.h>

#define BB   2
#define TT   64
#define CCB  32
#define HW   4096
#define CHW  131072
#define NHD  4
#define XD   8
#define HIDC 170
#define QKVC 192
#define PINC 340

typedef unsigned long long u64;

// ---------------- packed f32x2 helpers ----------------
__device__ __forceinline__ u64 pack2f(float a, float b){
    u64 r;
    asm("mov.b64 %0, {%1, %2};" : "=l"(r)
        : "r"(__float_as_uint(a)), "r"(__float_as_uint(b)));
    return r;
}
__device__ __forceinline__ u64 pack_dup(float a){
    unsigned ai = __float_as_uint(a);
    u64 r;
    asm("mov.b64 %0, {%1, %1};" : "=l"(r) : "r"(ai));
    return r;
}
__device__ __forceinline__ void fma2(u64 &d, u64 a, u64 b){
    asm("fma.rn.f32x2 %0, %1, %2, %0;" : "+l"(d) : "l"(a), "l"(b));
}
__device__ __forceinline__ float2 unpack2(u64 v){
    unsigned lo, hi;
    asm("mov.b64 {%0, %1}, %2;" : "=r"(lo), "=r"(hi) : "l"(v));
    float2 f; f.x = __uint_as_float(lo); f.y = __uint_as_float(hi);
    return f;
}

// ---------------- scratch (static device, allocation-free) ----------------
__device__ float g_qkv  [BB*QKVC*CHW];
__device__ float g_qkvdw[BB*QKVC*CHW];
__device__ float g_xa   [BB*TT*CHW];
__device__ float g_pin  [BB*PINC*CHW];
__device__ float g_prod [BB*HIDC*CHW];
__device__ float g_gram [BB*NHD*80];
__device__ float g_weff [BB*TT*TT];
__device__ float g_pool [BB*TT];
__device__ float g_se   [BB*TT];

__device__ __forceinline__ float warp_sum(float v){
    v += __shfl_xor_sync(0xffffffffu, v, 16);
    v += __shfl_xor_sync(0xffffffffu, v, 8);
    v += __shfl_xor_sync(0xffffffffu, v, 4);
    v += __shfl_xor_sync(0xffffffffu, v, 2);
    v += __shfl_xor_sync(0xffffffffu, v, 1);
    return v;
}

// ---------------- K0: zero small accumulators ----------------
__global__ void k_init(){
    int t = threadIdx.x;
    if (t < BB*NHD*80) g_gram[t] = 0.f;
    if (t < BB*TT)     g_pool[t] = 0.f;
}

// ---------------- K1: LN(channel) + 1x1 conv 64 -> 192 (f32x2) ----------------
__global__ void __launch_bounds__(256) k_ln_qkv(const float* __restrict__ x,
                                                const float* __restrict__ gam,
                                                const float* __restrict__ bet,
                                                const float* __restrict__ qw){
    extern __shared__ float wsh[];               // [64][192] transposed
    __shared__ float gsh[TT], bsh[TT];
    int tid = threadIdx.x;
    for (int i = tid; i < TT*QKVC; i += 256){
        int t = i / QKVC, o = i - t*QKVC;
        wsh[i] = qw[o*TT + t];
    }
    if (tid < TT){ gsh[tid] = gam[tid]; bsh[tid] = bet[tid]; }
    __syncthreads();

    int b = blockIdx.x >> 9;
    int p = ((blockIdx.x & 511) << 8) + tid;
    const float* xb = x + (size_t)b*TT*CHW + p;

    float xn[TT];
    float mean = 0.f;
#pragma unroll
    for (int t = 0; t < TT; t++){ xn[t] = xb[(size_t)t*CHW]; mean += xn[t]; }
    mean *= (1.f/TT);
    float var = 0.f;
#pragma unroll
    for (int t = 0; t < TT; t++){ float d = xn[t]-mean; var += d*d; }
    float rstd = rsqrtf(var*(1.f/TT) + 1e-5f);
#pragma unroll
    for (int t = 0; t < TT; t++) xn[t] = (xn[t]-mean)*rstd*gsh[t] + bsh[t];

    float* ob = g_qkv + (size_t)b*QKVC*CHW + p;
    for (int og = 0; og < QKVC; og += 16){
        u64 acc[8];
#pragma unroll
        for (int i = 0; i < 8; i++) acc[i] = 0ull;
#pragma unroll
        for (int t = 0; t < TT; t++){
            u64 xv2 = pack_dup(xn[t]);
            const ulonglong2* wp = (const ulonglong2*)&wsh[t*QKVC + og];
#pragma unroll
            for (int q = 0; q < 4; q++){
                ulonglong2 w = wp[q];
                fma2(acc[2*q  ], w.x, xv2);
                fma2(acc[2*q+1], w.y, xv2);
            }
        }
#pragma unroll
        for (int i = 0; i < 8; i++){
            float2 f = unpack2(acc[i]);
            ob[(size_t)(og+2*i  )*CHW] = f.x;
            ob[(size_t)(og+2*i+1)*CHW] = f.y;
        }
    }
}

// ---------------- K2: depthwise 3x3 over (H,W), 192 channels ----------------
__global__ void __launch_bounds__(256) k_dw2d(const float* __restrict__ dww){
    int tid = threadIdx.x;
    int j   = tid & 63;
    int sub = tid >> 6;
    int plane = blockIdx.x*4 + sub;
    int ch = (plane >> 5) % QKVC;
    const float* ip = g_qkv   + (size_t)plane*HW;
    float*       op = g_qkvdw + (size_t)plane*HW;
    float wv[9];
#pragma unroll
    for (int k = 0; k < 9; k++) wv[k] = __ldg(&dww[ch*9 + k]);
    bool lok = (j > 0), rok = (j < 63);
    float m0=0.f,m1=0.f,m2=0.f;
    float c0 = lok ? ip[j-1] : 0.f;
    float c1 = ip[j];
    float c2 = rok ? ip[j+1] : 0.f;
    for (int h = 0; h < 64; h++){
        float p0, p1, p2;
        if (h < 63){
            const float* r = ip + (h+1)*64;
            p0 = lok ? r[j-1] : 0.f; p1 = r[j]; p2 = rok ? r[j+1] : 0.f;
        } else { p0 = p1 = p2 = 0.f; }
        float o = wv[0]*m0 + wv[1]*m1 + wv[2]*m2
                + wv[3]*c0 + wv[4]*c1 + wv[5]*c2
                + wv[6]*p0 + wv[7]*p1 + wv[8]*p2;
        op[h*64 + j] = o;
        m0=c0; m1=c1; m2=c2; c0=p0; c1=p1; c2=p2;
    }
}

// ---------------- K3: per-head 8x8 Gram + row self-dots ----------------
__global__ void __launch_bounds__(256) k_gram(){
    int tid = threadIdx.x;
    int chunk = blockIdx.x;
    int n = blockIdx.y, b = blockIdx.z;
    const float* qb = g_qkvdw + ((size_t)b*QKVC + 16*n)*CHW;
    const float* kb = qb + (size_t)64*CHW;

    float S[XD][XD], qq[XD], kk[XD];
#pragma unroll
    for (int xi = 0; xi < XD; xi++){
        qq[xi] = 0.f; kk[xi] = 0.f;
#pragma unroll
        for (int yi = 0; yi < XD; yi++) S[xi][yi] = 0.f;
    }
    int pbase = chunk*2048 + tid;
    for (int pp = 0; pp < 8; pp++){
        int p = pbase + pp*256;
#pragma unroll
        for (int par = 0; par < 2; par++){
            float qv[XD], kv[XD];
#pragma unroll
            for (int xi = 0; xi < XD; xi++){
                qv[xi] = qb[(size_t)(2*xi + par)*CHW + p];
                kv[xi] = kb[(size_t)(2*xi + par)*CHW + p];
            }
#pragma unroll
            for (int xi = 0; xi < XD; xi++){
                qq[xi] = fmaf(qv[xi], qv[xi], qq[xi]);
                kk[xi] = fmaf(kv[xi], kv[xi], kk[xi]);
#pragma unroll
                for (int yi = 0; yi < XD; yi++)
                    S[xi][yi] = fmaf(qv[xi], kv[yi], S[xi][yi]);
            }
        }
    }
    float* acc = g_gram + (b*NHD + n)*80;
    int lane = tid & 31;
#pragma unroll
    for (int xi = 0; xi < XD; xi++){
#pragma unroll
        for (int yi = 0; yi < XD; yi++){
            float v = warp_sum(S[xi][yi]);
            if (lane == 0) atomicAdd(&acc[xi*8 + yi], v);
        }
        float vq = warp_sum(qq[xi]);
        float vk = warp_sum(kk[xi]);
        if (lane == 0){ atomicAdd(&acc[64 + xi], vq); atomicAdd(&acc[72 + xi], vk); }
    }
}

// ---------------- K4: softmax + effective 64x64 channel matrix ----------------
__global__ void k_weff(const float* __restrict__ temp, const float* __restrict__ aw){
    int b = blockIdx.x, tid = threadIdx.x;
    __shared__ float att[NHD][XD][XD];
    __shared__ float qn[NHD][XD], kn[NHD][XD];
    const float* G = g_gram + b*NHD*80;
    if (tid < 64){
        int i = tid & 31, n = i >> 3, xx = i & 7;
        if (tid < 32) qn[n][xx] = fmaxf(sqrtf(G[n*80 + 64 + xx]), 1e-12f);
        else          kn[n][xx] = fmaxf(sqrtf(G[n*80 + 72 + xx]), 1e-12f);
    }
    __syncthreads();
    if (tid < 32){
        int n = tid >> 3, xx = tid & 7;
        float tpn = temp[n];
        float sc[XD], mx = -1e30f;
#pragma unroll
        for (int y = 0; y < XD; y++){
            sc[y] = G[n*80 + xx*8 + y] / (qn[n][xx]*kn[n][y]) * tpn;
            mx = fmaxf(mx, sc[y]);
        }
        float sum = 0.f;
#pragma unroll
        for (int y = 0; y < XD; y++){ sc[y] = expf(sc[y]-mx); sum += sc[y]; }
        float inv = 1.f/sum;
#pragma unroll
        for (int y = 0; y < XD; y++) att[n][xx][y] = sc[y]*inv;
    }
    __syncthreads();
    for (int e = tid; e < TT*TT; e += blockDim.x){
        int to = e >> 6, tv = e & 63;
        int n = tv >> 4, p = tv & 1, y = (tv >> 1) & 7;
        float s = 0.f;
#pragma unroll
        for (int xx = 0; xx < XD; xx++)
            s = fmaf(aw[to*64 + 16*n + 2*xx + p], att[n][xx][y], s);
        g_weff[b*4096 + e] = s;
    }
}

// ---------------- K5: x + W_eff @ V (f32x2) ----------------
__global__ void __launch_bounds__(256) k_apply(const float* __restrict__ x){
    __shared__ float wsh[TT*TT];                  // [tv][to]
    int tid = threadIdx.x;
    int b = blockIdx.x >> 9;
    for (int i = tid; i < TT*TT; i += 256){
        int tv = i >> 6, to = i & 63;
        wsh[i] = g_weff[b*4096 + to*64 + tv];
    }
    __syncthreads();
    int p = ((blockIdx.x & 511) << 8) + tid;
    const float* vb = g_qkvdw + ((size_t)b*QKVC + 128)*CHW + p;
    u64 acc[32];
#pragma unroll
    for (int i = 0; i < 32; i++) acc[i] = 0ull;
    for (int tv = 0; tv < TT; tv++){
        u64 v2 = pack_dup(vb[(size_t)tv*CHW]);
        const ulonglong2* wp = (const ulonglong2*)&wsh[tv*TT];
#pragma unroll
        for (int q = 0; q < 16; q++){
            ulonglong2 w = wp[q];
            fma2(acc[2*q  ], w.x, v2);
            fma2(acc[2*q+1], w.y, v2);
        }
    }
    const float* xb = x    + (size_t)b*TT*CHW + p;
    float*       ob = g_xa + (size_t)b*TT*CHW + p;
#pragma unroll
    for (int i = 0; i < 32; i++){
        float2 f = unpack2(acc[i]);
        ob[(size_t)(2*i  )*CHW] = f.x + xb[(size_t)(2*i  )*CHW];
        ob[(size_t)(2*i+1)*CHW] = f.y + xb[(size_t)(2*i+1)*CHW];
    }
}

// ---------------- K6: LN(channel) + 1x1 conv 64 -> 340 (f32x2) ----------------
__global__ void __launch_bounds__(256) k_ln_pin(const float* __restrict__ gam,
                                                const float* __restrict__ bet,
                                                const float* __restrict__ pw){
    extern __shared__ float wsh[];                // [64][340] transposed
    __shared__ float gsh[TT], bsh[TT];
    int tid = threadIdx.x;
    for (int i = tid; i < TT*PINC; i += 256){
        int t = i / PINC, o = i - t*PINC;
        wsh[i] = pw[o*TT + t];
    }
    if (tid < TT){ gsh[tid] = gam[tid]; bsh[tid] = bet[tid]; }
    __syncthreads();

    int b = blockIdx.x >> 9;
    int p = ((blockIdx.x & 511) << 8) + tid;
    const float* xb = g_xa + (size_t)b*TT*CHW + p;

    float xn[TT];
    float mean = 0.f;
#pragma unroll
    for (int t = 0; t < TT; t++){ xn[t] = xb[(size_t)t*CHW]; mean += xn[t]; }
    mean *= (1.f/TT);
    float var = 0.f;
#pragma unroll
    for (int t = 0; t < TT; t++){ float d = xn[t]-mean; var += d*d; }
    float rstd = rsqrtf(var*(1.f/TT) + 1e-5f);
#pragma unroll
    for (int t = 0; t < TT; t++) xn[t] = (xn[t]-mean)*rstd*gsh[t] + bsh[t];

    float* ob = g_pin + (size_t)b*PINC*CHW + p;
    for (int og = 0; og < PINC; og += 20){
        u64 acc[10];
#pragma unroll
        for (int i = 0; i < 10; i++) acc[i] = 0ull;
#pragma unroll
        for (int t = 0; t < TT; t++){
            u64 xv2 = pack_dup(xn[t]);
            const ulonglong2* wp = (const ulonglong2*)&wsh[t*PINC + og];
#pragma unroll
            for (int q = 0; q < 5; q++){
                ulonglong2 w = wp[q];
                fma2(acc[2*q  ], w.x, xv2);
                fma2(acc[2*q+1], w.y, xv2);
            }
        }
#pragma unroll
        for (int i = 0; i < 10; i++){
            float2 f = unpack2(acc[i]);
            ob[(size_t)(og+2*i  )*CHW] = f.x;
            ob[(size_t)(og+2*i+1)*CHW] = f.y;
        }
    }
}

// ---------------- K7: depthwise 3x3x3 + exact GELU gating (f32x2 pair) ----------------
__device__ __forceinline__ void load_row3p(const float* __restrict__ b1,
                                           const float* __restrict__ b2,
                                           int cz, int h, int w,
                                           bool c0ok, bool c2ok, bool lok, bool rok,
                                           u64 r[9]){
#pragma unroll
    for (int cc = 0; cc < 3; cc++){
        bool cok = (cc == 0) ? c0ok : ((cc == 2) ? c2ok : true);
        size_t off = (size_t)(cz + cc - 1)*HW + h*64;
        const float* p1 = b1 + off;
        const float* p2 = b2 + off;
        float a0 = (cok && lok) ? p1[w-1] : 0.f;
        float b0 = (cok && lok) ? p2[w-1] : 0.f;
        float a1 =  cok         ? p1[w]   : 0.f;
        float bm =  cok         ? p2[w]   : 0.f;
        float a2 = (cok && rok) ? p1[w+1] : 0.f;
        float b2v= (cok && rok) ? p2[w+1] : 0.f;
        r[cc*3+0] = pack2f(a0, b0);
        r[cc*3+1] = pack2f(a1, bm);
        r[cc*3+2] = pack2f(a2, b2v);
    }
}

__global__ void __launch_bounds__(64) k_dw3d(const float* __restrict__ dww){
    int w  = threadIdx.x;
    int cz = blockIdx.x, j = blockIdx.y, b = blockIdx.z;
    const float* b1 = g_pin + (size_t)(b*PINC + j)*CHW;
    const float* b2 = g_pin + (size_t)(b*PINC + j + HIDC)*CHW;
    float* op = g_prod + ((size_t)(b*HIDC + j)*CCB + cz)*HW;

    u64 wp[27];
#pragma unroll
    for (int k = 0; k < 27; k++)
        wp[k] = pack2f(__ldg(&dww[j*27 + k]), __ldg(&dww[(j + HIDC)*27 + k]));

    bool lok = (w > 0), rok = (w < 63);
    bool c0ok = (cz > 0), c2ok = (cz < 31);

    u64 rm[9], rc[9], rp[9];
#pragma unroll
    for (int k = 0; k < 9; k++) rm[k] = 0ull;
    load_row3p(b1, b2, cz, 0, w, c0ok, c2ok, lok, rok, rc);

    for (int h = 0; h < 64; h++){
        if (h < 63){
            load_row3p(b1, b2, cz, h+1, w, c0ok, c2ok, lok, rok, rp);
        } else {
#pragma unroll
            for (int k = 0; k < 9; k++) rp[k] = 0ull;
        }
        u64 acc = 0ull;
#pragma unroll
        for (int cc = 0; cc < 3; cc++){
#pragma unroll
            for (int kw = 0; kw < 3; kw++){
                fma2(acc, wp[cc*9 + 0*3 + kw], rm[cc*3+kw]);
                fma2(acc, wp[cc*9 + 1*3 + kw], rc[cc*3+kw]);
                fma2(acc, wp[cc*9 + 2*3 + kw], rp[cc*3+kw]);
            }
        }
        float2 a = unpack2(acc);
        float g = 0.5f*a.x*(1.f + erff(a.x*0.70710678118654752f));
        op[h*64 + w] = g*a.y;
#pragma unroll
        for (int k = 0; k < 9; k++){ rm[k] = rc[k]; rc[k] = rp[k]; }
    }
}

// ---------------- K8: 1x1 conv 170->64 + residual + SE pooling (f32x2) ----------------
__global__ void __launch_bounds__(256) k_pout(const float* __restrict__ pw,
                                              float* __restrict__ dout){
    __shared__ float wsh[HIDC*TT];                // [t][o]
    __shared__ float pool[TT];
    int tid = threadIdx.x;
    for (int i = tid; i < HIDC*TT; i += 256){
        int t = i >> 6, o = i & 63;
        wsh[i] = pw[o*HIDC + t];
    }
    if (tid < TT) pool[tid] = 0.f;
    __syncthreads();

    int b = blockIdx.x >> 9;
    int p = ((blockIdx.x & 511) << 8) + tid;
    const float* pr = g_prod + (size_t)b*HIDC*CHW + p;

    u64 acc[32];
#pragma unroll
    for (int i = 0; i < 32; i++) acc[i] = 0ull;
#pragma unroll 2
    for (int t = 0; t < HIDC; t++){
        u64 v2 = pack_dup(pr[(size_t)t*CHW]);
        const ulonglong2* wp = (const ulonglong2*)&wsh[t*TT];
#pragma unroll
        for (int q = 0; q < 16; q++){
            ulonglong2 w = wp[q];
            fma2(acc[2*q  ], w.x, v2);
            fma2(acc[2*q+1], w.y, v2);
        }
    }
    const float* xb = g_xa + (size_t)b*TT*CHW + p;
    float*       ob = dout + (size_t)b*TT*CHW + p;
    int lane = tid & 31;
#pragma unroll
    for (int i = 0; i < 32; i++){
        float2 f = unpack2(acc[i]);
        float r0 = f.x + xb[(size_t)(2*i  )*CHW];
        float r1 = f.y + xb[(size_t)(2*i+1)*CHW];
        ob[(size_t)(2*i  )*CHW] = r0;
        ob[(size_t)(2*i+1)*CHW] = r1;
        float v0 = warp_sum(r0);
        float v1 = warp_sum(r1);
        if (lane == 0){ atomicAdd(&pool[2*i], v0); atomicAdd(&pool[2*i+1], v1); }
    }
    __syncthreads();
    if (tid < TT) atomicAdd(&g_pool[b*TT + tid], pool[tid]);
}

// ---------------- K9: SE gate ----------------
__global__ void k_se(const float* __restrict__ sew, const float* __restrict__ seb){
    int tid = threadIdx.x;
    if (tid >= BB*TT) return;
    int b = tid >> 6, o = tid & 63;
    float s = 0.f;
#pragma unroll
    for (int t = 0; t < TT; t++)
        s = fmaf(sew[o*TT + t], g_pool[b*TT + t]*(1.f/131072.f), s);
    s += seb[o];
    g_se[b*TT + o] = 1.f/(1.f + expf(-s));
}

// ---------------- K10: in-place SE scale ----------------
__global__ void k_final(float* __restrict__ dout){
    int idx = blockIdx.x*256 + threadIdx.x;
    float4* o4 = (float4*)dout;
    float s = g_se[idx >> 15];
    float4 v = o4[idx];
    v.x *= s; v.y *= s; v.z *= s; v.w *= s;
    o4[idx] = v;
}

// ---------------- launch ----------------
extern "C" void kernel_launch(void* const* d_in, const int* in_sizes, int n_in,
                              void* d_out, int out_size){
    const float* x     = (const float*)d_in[0];
    const float* n1g   = (const float*)d_in[1];
    const float* n1b   = (const float*)d_in[2];
    const float* temp  = (const float*)d_in[3];
    const float* qkvw  = (const float*)d_in[4];
    const float* qkvdw = (const float*)d_in[5];
    const float* aow   = (const float*)d_in[6];
    const float* n2g   = (const float*)d_in[7];
    const float* n2b   = (const float*)d_in[8];
    const float* pinw  = (const float*)d_in[9];
    const float* dww   = (const float*)d_in[10];
    const float* poutw = (const float*)d_in[11];
    const float* sew   = (const float*)d_in[12];
    const float* seb   = (const float*)d_in[13];
    float* out = (float*)d_out;

    cudaFuncSetAttribute(k_ln_pin, cudaFuncAttributeMaxDynamicSharedMemorySize,
                         TT*PINC*(int)sizeof(float));
    cudaFuncSetAttribute(k_ln_qkv, cudaFuncAttributeMaxDynamicSharedMemorySize,
                         TT*QKVC*(int)sizeof(float));

    k_init  <<<1, 1024>>>();
    k_ln_qkv<<<1024, 256, TT*QKVC*sizeof(float)>>>(x, n1g, n1b, qkvw);
    k_dw2d  <<<3072, 256>>>(qkvdw);
    k_gram  <<<dim3(64, NHD, BB), 256>>>();
    k_weff  <<<BB, 256>>>(temp, aow);
    k_apply <<<1024, 256>>>(x);
    k_ln_pin<<<1024, 256, TT*PINC*sizeof(float)>>>(n2g, n2b, pinw);
    k_dw3d  <<<dim3(CCB, HIDC, BB), 64>>>(dww);
    k_pout  <<<1024, 256>>>(poutw, out);
    k_se    <<<1, 128>>>(sew, seb);
    k_final <<<16384, 256>>>(out);
}

// round 9
// speedup vs baseline: 1.0464x; 1.0012x over previous
#include <cuda_runtime.h>
#include <math.h>

#define BB   2
#define TT   64
#define CCB  32
#define HW   4096
#define CHW  131072
#define NHD  4
#define XD   8
#define HIDC 170
#define QKVC 192
#define PINC 340

typedef unsigned long long u64;

// ---------------- packed f32x2 helpers ----------------
__device__ __forceinline__ u64 pack2f(float a, float b){
    u64 r;
    asm("mov.b64 %0, {%1, %2};" : "=l"(r)
        : "r"(__float_as_uint(a)), "r"(__float_as_uint(b)));
    return r;
}
__device__ __forceinline__ u64 pack_dup(float a){
    unsigned ai = __float_as_uint(a);
    u64 r;
    asm("mov.b64 %0, {%1, %1};" : "=l"(r) : "r"(ai));
    return r;
}
__device__ __forceinline__ void fma2(u64 &d, u64 a, u64 b){
    asm("fma.rn.f32x2 %0, %1, %2, %0;" : "+l"(d) : "l"(a), "l"(b));
}
__device__ __forceinline__ float2 unpack2(u64 v){
    unsigned lo, hi;
    asm("mov.b64 {%0, %1}, %2;" : "=r"(lo), "=r"(hi) : "l"(v));
    float2 f; f.x = __uint_as_float(lo); f.y = __uint_as_float(hi);
    return f;
}

// ---------------- scratch (static device, allocation-free) ----------------
__device__ float g_qkv  [BB*QKVC*CHW];
__device__ float g_qkvdw[BB*QKVC*CHW];
__device__ float g_xa   [BB*TT*CHW];
__device__ float g_pin  [BB*PINC*CHW];
__device__ float g_prod [BB*HIDC*CHW];
__device__ float g_gram [BB*NHD*80];
__device__ float g_weff [BB*TT*TT];
__device__ float g_pool [BB*TT];
__device__ float g_se   [BB*TT];

__device__ __forceinline__ float warp_sum(float v){
    v += __shfl_xor_sync(0xffffffffu, v, 16);
    v += __shfl_xor_sync(0xffffffffu, v, 8);
    v += __shfl_xor_sync(0xffffffffu, v, 4);
    v += __shfl_xor_sync(0xffffffffu, v, 2);
    v += __shfl_xor_sync(0xffffffffu, v, 1);
    return v;
}

// ---------------- K0: zero small accumulators ----------------
__global__ void k_init(){
    int t = threadIdx.x;
    if (t < BB*NHD*80) g_gram[t] = 0.f;
    if (t < BB*TT)     g_pool[t] = 0.f;
}

// ---------------- K1: LN(channel) + 1x1 conv 64 -> 192 (f32x2) ----------------
__global__ void __launch_bounds__(256) k_ln_qkv(const float* __restrict__ x,
                                                const float* __restrict__ gam,
                                                const float* __restrict__ bet,
                                                const float* __restrict__ qw){
    extern __shared__ float wsh[];               // [64][192] transposed
    __shared__ float gsh[TT], bsh[TT];
    int tid = threadIdx.x;
    for (int i = tid; i < TT*QKVC; i += 256){
        int t = i / QKVC, o = i - t*QKVC;
        wsh[i] = qw[o*TT + t];
    }
    if (tid < TT){ gsh[tid] = gam[tid]; bsh[tid] = bet[tid]; }
    __syncthreads();

    int b = blockIdx.x >> 9;
    int p = ((blockIdx.x & 511) << 8) + tid;
    const float* xb = x + (size_t)b*TT*CHW + p;

    float xn[TT];
    float mean = 0.f;
#pragma unroll
    for (int t = 0; t < TT; t++){ xn[t] = xb[(size_t)t*CHW]; mean += xn[t]; }
    mean *= (1.f/TT);
    float var = 0.f;
#pragma unroll
    for (int t = 0; t < TT; t++){ float d = xn[t]-mean; var += d*d; }
    float rstd = rsqrtf(var*(1.f/TT) + 1e-5f);
#pragma unroll
    for (int t = 0; t < TT; t++) xn[t] = (xn[t]-mean)*rstd*gsh[t] + bsh[t];

    float* ob = g_qkv + (size_t)b*QKVC*CHW + p;
    for (int og = 0; og < QKVC; og += 16){
        u64 acc[8];
#pragma unroll
        for (int i = 0; i < 8; i++) acc[i] = 0ull;
#pragma unroll
        for (int t = 0; t < TT; t++){
            u64 xv2 = pack_dup(xn[t]);
            const ulonglong2* wp = (const ulonglong2*)&wsh[t*QKVC + og];
#pragma unroll
            for (int q = 0; q < 4; q++){
                ulonglong2 w = wp[q];
                fma2(acc[2*q  ], w.x, xv2);
                fma2(acc[2*q+1], w.y, xv2);
            }
        }
#pragma unroll
        for (int i = 0; i < 8; i++){
            float2 f = unpack2(acc[i]);
            ob[(size_t)(og+2*i  )*CHW] = f.x;
            ob[(size_t)(og+2*i+1)*CHW] = f.y;
        }
    }
}

// ---------------- K2: depthwise 3x3 over (H,W), 192 channels ----------------
__global__ void __launch_bounds__(256) k_dw2d(const float* __restrict__ dww){
    int tid = threadIdx.x;
    int j   = tid & 63;
    int sub = tid >> 6;
    int plane = blockIdx.x*4 + sub;
    int ch = (plane >> 5) % QKVC;
    const float* ip = g_qkv   + (size_t)plane*HW;
    float*       op = g_qkvdw + (size_t)plane*HW;
    float wv[9];
#pragma unroll
    for (int k = 0; k < 9; k++) wv[k] = __ldg(&dww[ch*9 + k]);
    bool lok = (j > 0), rok = (j < 63);
    float m0=0.f,m1=0.f,m2=0.f;
    float c0 = lok ? ip[j-1] : 0.f;
    float c1 = ip[j];
    float c2 = rok ? ip[j+1] : 0.f;
    for (int h = 0; h < 64; h++){
        float p0, p1, p2;
        if (h < 63){
            const float* r = ip + (h+1)*64;
            p0 = lok ? r[j-1] : 0.f; p1 = r[j]; p2 = rok ? r[j+1] : 0.f;
        } else { p0 = p1 = p2 = 0.f; }
        float o = wv[0]*m0 + wv[1]*m1 + wv[2]*m2
                + wv[3]*c0 + wv[4]*c1 + wv[5]*c2
                + wv[6]*p0 + wv[7]*p1 + wv[8]*p2;
        op[h*64 + j] = o;
        m0=c0; m1=c1; m2=c2; c0=p0; c1=p1; c2=p2;
    }
}

// ---------------- K3: per-head 8x8 Gram + row self-dots ----------------
__global__ void __launch_bounds__(256) k_gram(){
    int tid = threadIdx.x;
    int chunk = blockIdx.x;
    int n = blockIdx.y, b = blockIdx.z;
    const float* qb = g_qkvdw + ((size_t)b*QKVC + 16*n)*CHW;
    const float* kb = qb + (size_t)64*CHW;

    float S[XD][XD], qq[XD], kk[XD];
#pragma unroll
    for (int xi = 0; xi < XD; xi++){
        qq[xi] = 0.f; kk[xi] = 0.f;
#pragma unroll
        for (int yi = 0; yi < XD; yi++) S[xi][yi] = 0.f;
    }
    int pbase = chunk*2048 + tid;
    for (int pp = 0; pp < 8; pp++){
        int p = pbase + pp*256;
#pragma unroll
        for (int par = 0; par < 2; par++){
            float qv[XD], kv[XD];
#pragma unroll
            for (int xi = 0; xi < XD; xi++){
                qv[xi] = qb[(size_t)(2*xi + par)*CHW + p];
                kv[xi] = kb[(size_t)(2*xi + par)*CHW + p];
            }
#pragma unroll
            for (int xi = 0; xi < XD; xi++){
                qq[xi] = fmaf(qv[xi], qv[xi], qq[xi]);
                kk[xi] = fmaf(kv[xi], kv[xi], kk[xi]);
#pragma unroll
                for (int yi = 0; yi < XD; yi++)
                    S[xi][yi] = fmaf(qv[xi], kv[yi], S[xi][yi]);
            }
        }
    }
    float* acc = g_gram + (b*NHD + n)*80;
    int lane = tid & 31;
#pragma unroll
    for (int xi = 0; xi < XD; xi++){
#pragma unroll
        for (int yi = 0; yi < XD; yi++){
            float v = warp_sum(S[xi][yi]);
            if (lane == 0) atomicAdd(&acc[xi*8 + yi], v);
        }
        float vq = warp_sum(qq[xi]);
        float vk = warp_sum(kk[xi]);
        if (lane == 0){ atomicAdd(&acc[64 + xi], vq); atomicAdd(&acc[72 + xi], vk); }
    }
}

// ---------------- K4: softmax + effective 64x64 channel matrix ----------------
__global__ void k_weff(const float* __restrict__ temp, const float* __restrict__ aw){
    int b = blockIdx.x, tid = threadIdx.x;
    __shared__ float att[NHD][XD][XD];
    __shared__ float qn[NHD][XD], kn[NHD][XD];
    const float* G = g_gram + b*NHD*80;
    if (tid < 64){
        int i = tid & 31, n = i >> 3, xx = i & 7;
        if (tid < 32) qn[n][xx] = fmaxf(sqrtf(G[n*80 + 64 + xx]), 1e-12f);
        else          kn[n][xx] = fmaxf(sqrtf(G[n*80 + 72 + xx]), 1e-12f);
    }
    __syncthreads();
    if (tid < 32){
        int n = tid >> 3, xx = tid & 7;
        float tpn = temp[n];
        float sc[XD], mx = -1e30f;
#pragma unroll
        for (int y = 0; y < XD; y++){
            sc[y] = G[n*80 + xx*8 + y] / (qn[n][xx]*kn[n][y]) * tpn;
            mx = fmaxf(mx, sc[y]);
        }
        float sum = 0.f;
#pragma unroll
        for (int y = 0; y < XD; y++){ sc[y] = expf(sc[y]-mx); sum += sc[y]; }
        float inv = 1.f/sum;
#pragma unroll
        for (int y = 0; y < XD; y++) att[n][xx][y] = sc[y]*inv;
    }
    __syncthreads();
    for (int e = tid; e < TT*TT; e += blockDim.x){
        int to = e >> 6, tv = e & 63;
        int n = tv >> 4, p = tv & 1, y = (tv >> 1) & 7;
        float s = 0.f;
#pragma unroll
        for (int xx = 0; xx < XD; xx++)
            s = fmaf(aw[to*64 + 16*n + 2*xx + p], att[n][xx][y], s);
        g_weff[b*4096 + e] = s;
    }
}

// ---------------- K5: x + W_eff @ V (f32x2) ----------------
__global__ void __launch_bounds__(256) k_apply(const float* __restrict__ x){
    __shared__ float wsh[TT*TT];                  // [tv][to]
    int tid = threadIdx.x;
    int b = blockIdx.x >> 9;
    for (int i = tid; i < TT*TT; i += 256){
        int tv = i >> 6, to = i & 63;
        wsh[i] = g_weff[b*4096 + to*64 + tv];
    }
    __syncthreads();
    int p = ((blockIdx.x & 511) << 8) + tid;
    const float* vb = g_qkvdw + ((size_t)b*QKVC + 128)*CHW + p;
    u64 acc[32];
#pragma unroll
    for (int i = 0; i < 32; i++) acc[i] = 0ull;
    for (int tv = 0; tv < TT; tv++){
        u64 v2 = pack_dup(vb[(size_t)tv*CHW]);
        const ulonglong2* wp = (const ulonglong2*)&wsh[tv*TT];
#pragma unroll
        for (int q = 0; q < 16; q++){
            ulonglong2 w = wp[q];
            fma2(acc[2*q  ], w.x, v2);
            fma2(acc[2*q+1], w.y, v2);
        }
    }
    const float* xb = x    + (size_t)b*TT*CHW + p;
    float*       ob = g_xa + (size_t)b*TT*CHW + p;
#pragma unroll
    for (int i = 0; i < 32; i++){
        float2 f = unpack2(acc[i]);
        ob[(size_t)(2*i  )*CHW] = f.x + xb[(size_t)(2*i  )*CHW];
        ob[(size_t)(2*i+1)*CHW] = f.y + xb[(size_t)(2*i+1)*CHW];
    }
}

// ---------------- K6: LN(channel) + 1x1 conv 64 -> 340 (f32x2) ----------------
__global__ void __launch_bounds__(256) k_ln_pin(const float* __restrict__ gam,
                                                const float* __restrict__ bet,
                                                const float* __restrict__ pw){
    extern __shared__ float wsh[];                // [64][340] transposed
    __shared__ float gsh[TT], bsh[TT];
    int tid = threadIdx.x;
    for (int i = tid; i < TT*PINC; i += 256){
        int t = i / PINC, o = i - t*PINC;
        wsh[i] = pw[o*TT + t];
    }
    if (tid < TT){ gsh[tid] = gam[tid]; bsh[tid] = bet[tid]; }
    __syncthreads();

    int b = blockIdx.x >> 9;
    int p = ((blockIdx.x & 511) << 8) + tid;
    const float* xb = g_xa + (size_t)b*TT*CHW + p;

    float xn[TT];
    float mean = 0.f;
#pragma unroll
    for (int t = 0; t < TT; t++){ xn[t] = xb[(size_t)t*CHW]; mean += xn[t]; }
    mean *= (1.f/TT);
    float var = 0.f;
#pragma unroll
    for (int t = 0; t < TT; t++){ float d = xn[t]-mean; var += d*d; }
    float rstd = rsqrtf(var*(1.f/TT) + 1e-5f);
#pragma unroll
    for (int t = 0; t < TT; t++) xn[t] = (xn[t]-mean)*rstd*gsh[t] + bsh[t];

    float* ob = g_pin + (size_t)b*PINC*CHW + p;
    for (int og = 0; og < PINC; og += 20){
        u64 acc[10];
#pragma unroll
        for (int i = 0; i < 10; i++) acc[i] = 0ull;
#pragma unroll
        for (int t = 0; t < TT; t++){
            u64 xv2 = pack_dup(xn[t]);
            const ulonglong2* wp = (const ulonglong2*)&wsh[t*PINC + og];
#pragma unroll
            for (int q = 0; q < 5; q++){
                ulonglong2 w = wp[q];
                fma2(acc[2*q  ], w.x, xv2);
                fma2(acc[2*q+1], w.y, xv2);
            }
        }
#pragma unroll
        for (int i = 0; i < 10; i++){
            float2 f = unpack2(acc[i]);
            ob[(size_t)(og+2*i  )*CHW] = f.x;
            ob[(size_t)(og+2*i+1)*CHW] = f.y;
        }
    }
}

// ---------------- K7: depthwise 3x3x3 + exact GELU gating (f32x2 pair) ----------------
__device__ __forceinline__ void load_row3p(const float* __restrict__ b1,
                                           const float* __restrict__ b2,
                                           int cz, int h, int w,
                                           bool c0ok, bool c2ok, bool lok, bool rok,
                                           u64 r[9]){
#pragma unroll
    for (int cc = 0; cc < 3; cc++){
        bool cok = (cc == 0) ? c0ok : ((cc == 2) ? c2ok : true);
        size_t off = (size_t)(cz + cc - 1)*HW + h*64;
        const float* p1 = b1 + off;
        const float* p2 = b2 + off;
        float a0 = (cok && lok) ? p1[w-1] : 0.f;
        float b0 = (cok && lok) ? p2[w-1] : 0.f;
        float a1 =  cok         ? p1[w]   : 0.f;
        float bm =  cok         ? p2[w]   : 0.f;
        float a2 = (cok && rok) ? p1[w+1] : 0.f;
        float b2v= (cok && rok) ? p2[w+1] : 0.f;
        r[cc*3+0] = pack2f(a0, b0);
        r[cc*3+1] = pack2f(a1, bm);
        r[cc*3+2] = pack2f(a2, b2v);
    }
}

__global__ void __launch_bounds__(64) k_dw3d(const float* __restrict__ dww){
    int w  = threadIdx.x;
    int cz = blockIdx.x, j = blockIdx.y, b = blockIdx.z;
    const float* b1 = g_pin + (size_t)(b*PINC + j)*CHW;
    const float* b2 = g_pin + (size_t)(b*PINC + j + HIDC)*CHW;
    float* op = g_prod + ((size_t)(b*HIDC + j)*CCB + cz)*HW;

    u64 wp[27];
#pragma unroll
    for (int k = 0; k < 27; k++)
        wp[k] = pack2f(__ldg(&dww[j*27 + k]), __ldg(&dww[(j + HIDC)*27 + k]));

    bool lok = (w > 0), rok = (w < 63);
    bool c0ok = (cz > 0), c2ok = (cz < 31);

    u64 rm[9], rc[9], rp[9];
#pragma unroll
    for (int k = 0; k < 9; k++) rm[k] = 0ull;
    load_row3p(b1, b2, cz, 0, w, c0ok, c2ok, lok, rok, rc);

    for (int h = 0; h < 64; h++){
        if (h < 63){
            load_row3p(b1, b2, cz, h+1, w, c0ok, c2ok, lok, rok, rp);
        } else {
#pragma unroll
            for (int k = 0; k < 9; k++) rp[k] = 0ull;
        }
        u64 acc = 0ull;
#pragma unroll
        for (int cc = 0; cc < 3; cc++){
#pragma unroll
            for (int kw = 0; kw < 3; kw++){
                fma2(acc, wp[cc*9 + 0*3 + kw], rm[cc*3+kw]);
                fma2(acc, wp[cc*9 + 1*3 + kw], rc[cc*3+kw]);
                fma2(acc, wp[cc*9 + 2*3 + kw], rp[cc*3+kw]);
            }
        }
        float2 a = unpack2(acc);
        float g = 0.5f*a.x*(1.f + erff(a.x*0.70710678118654752f));
        op[h*64 + w] = g*a.y;
#pragma unroll
        for (int k = 0; k < 9; k++){ rm[k] = rc[k]; rc[k] = rp[k]; }
    }
}

// ---------------- K8: 1x1 conv 170->64 + residual + SE pooling (f32x2) ----------------
__global__ void __launch_bounds__(256) k_pout(const float* __restrict__ pw,
                                              float* __restrict__ dout){
    __shared__ float wsh[HIDC*TT];                // [t][o]
    __shared__ float pool[TT];
    int tid = threadIdx.x;
    for (int i = tid; i < HIDC*TT; i += 256){
        int t = i >> 6, o = i & 63;
        wsh[i] = pw[o*HIDC + t];
    }
    if (tid < TT) pool[tid] = 0.f;
    __syncthreads();

    int b = blockIdx.x >> 9;
    int p = ((blockIdx.x & 511) << 8) + tid;
    const float* pr = g_prod + (size_t)b*HIDC*CHW + p;

    u64 acc[32];
#pragma unroll
    for (int i = 0; i < 32; i++) acc[i] = 0ull;
#pragma unroll 2
    for (int t = 0; t < HIDC; t++){
        u64 v2 = pack_dup(pr[(size_t)t*CHW]);
        const ulonglong2* wp = (const ulonglong2*)&wsh[t*TT];
#pragma unroll
        for (int q = 0; q < 16; q++){
            ulonglong2 w = wp[q];
            fma2(acc[2*q  ], w.x, v2);
            fma2(acc[2*q+1], w.y, v2);
        }
    }
    const float* xb = g_xa + (size_t)b*TT*CHW + p;
    float*       ob = dout + (size_t)b*TT*CHW + p;
    int lane = tid & 31;
#pragma unroll
    for (int i = 0; i < 32; i++){
        float2 f = unpack2(acc[i]);
        float r0 = f.x + xb[(size_t)(2*i  )*CHW];
        float r1 = f.y + xb[(size_t)(2*i+1)*CHW];
        ob[(size_t)(2*i  )*CHW] = r0;
        ob[(size_t)(2*i+1)*CHW] = r1;
        float v0 = warp_sum(r0);
        float v1 = warp_sum(r1);
        if (lane == 0){ atomicAdd(&pool[2*i], v0); atomicAdd(&pool[2*i+1], v1); }
    }
    __syncthreads();
    if (tid < TT) atomicAdd(&g_pool[b*TT + tid], pool[tid]);
}

// ---------------- K9: SE gate ----------------
__global__ void k_se(const float* __restrict__ sew, const float* __restrict__ seb){
    int tid = threadIdx.x;
    if (tid >= BB*TT) return;
    int b = tid >> 6, o = tid & 63;
    float s = 0.f;
#pragma unroll
    for (int t = 0; t < TT; t++)
        s = fmaf(sew[o*TT + t], g_pool[b*TT + t]*(1.f/131072.f), s);
    s += seb[o];
    g_se[b*TT + o] = 1.f/(1.f + expf(-s));
}

// ---------------- K10: in-place SE scale ----------------
__global__ void k_final(float* __restrict__ dout){
    int idx = blockIdx.x*256 + threadIdx.x;
    float4* o4 = (float4*)dout;
    float s = g_se[idx >> 15];
    float4 v = o4[idx];
    v.x *= s; v.y *= s; v.z *= s; v.w *= s;
    o4[idx] = v;
}

// ---------------- launch ----------------
extern "C" void kernel_launch(void* const* d_in, const int* in_sizes, int n_in,
                              void* d_out, int out_size){
    const float* x     = (const float*)d_in[0];
    const float* n1g   = (const float*)d_in[1];
    const float* n1b   = (const float*)d_in[2];
    const float* temp  = (const float*)d_in[3];
    const float* qkvw  = (const float*)d_in[4];
    const float* qkvdw = (const float*)d_in[5];
    const float* aow   = (const float*)d_in[6];
    const float* n2g   = (const float*)d_in[7];
    const float* n2b   = (const float*)d_in[8];
    const float* pinw  = (const float*)d_in[9];
    const float* dww   = (const float*)d_in[10];
    const float* poutw = (const float*)d_in[11];
    const float* sew   = (const float*)d_in[12];
    const float* seb   = (const float*)d_in[13];
    float* out = (float*)d_out;

    cudaFuncSetAttribute(k_ln_pin, cudaFuncAttributeMaxDynamicSharedMemorySize,
                         TT*PINC*(int)sizeof(float));
    cudaFuncSetAttribute(k_ln_qkv, cudaFuncAttributeMaxDynamicSharedMemorySize,
                         TT*QKVC*(int)sizeof(float));

    k_init  <<<1, 1024>>>();
    k_ln_qkv<<<1024, 256, TT*QKVC*sizeof(float)>>>(x, n1g, n1b, qkvw);
    k_dw2d  <<<3072, 256>>>(qkvdw);
    k_gram  <<<dim3(64, NHD, BB), 256>>>();
    k_weff  <<<BB, 256>>>(temp, aow);
    k_apply <<<1024, 256>>>(x);
    k_ln_pin<<<1024, 256, TT*PINC*sizeof(float)>>>(n2g, n2b, pinw);
    k_dw3d  <<<dim3(CCB, HIDC, BB), 64>>>(dww);
    k_pout  <<<1024, 256>>>(poutw, out);
    k_se    <<<1, 128>>>(sew, seb);
    k_final <<<16384, 256>>>(out);
}

// round 11
// speedup vs baseline: 1.2030x; 1.1496x over previous
#include <cuda_runtime.h>
#include <cuda_fp16.h>
#include <math.h>

#define BB   2
#define TT   64
#define CCB  32
#define HW   4096
#define CHW  131072
#define NHD  4
#define XD   8
#define HIDC 170
#define QKVC 192
#define PINC 340

typedef unsigned long long u64;
typedef __half f16;

// ---------------- packed f32x2 helpers ----------------
__device__ __forceinline__ u64 pack2f(float a, float b){
    u64 r;
    asm("mov.b64 %0, {%1, %2};" : "=l"(r)
        : "r"(__float_as_uint(a)), "r"(__float_as_uint(b)));
    return r;
}
__device__ __forceinline__ u64 pack_dup(float a){
    unsigned ai = __float_as_uint(a);
    u64 r;
    asm("mov.b64 %0, {%1, %1};" : "=l"(r) : "r"(ai));
    return r;
}
__device__ __forceinline__ void fma2(u64 &d, u64 a, u64 b){
    asm("fma.rn.f32x2 %0, %1, %2, %0;" : "+l"(d) : "l"(a), "l"(b));
}
__device__ __forceinline__ float2 unpack2(u64 v){
    unsigned lo, hi;
    asm("mov.b64 {%0, %1}, %2;" : "=r"(lo), "=r"(hi) : "l"(v));
    float2 f; f.x = __uint_as_float(lo); f.y = __uint_as_float(hi);
    return f;
}

// ---------------- scratch (static device, allocation-free) ----------------
__device__ f16   g_qkv  [BB*QKVC*CHW];           // 100 MB
__device__ f16   g_qkvdw[BB*QKVC*CHW];           // 100 MB
__device__ float g_xa   [BB*TT*CHW];             //  64 MB (fp32: residual carrier)
__device__ f16   g_pin  [BB*PINC*CHW];           // 178 MB
__device__ f16   g_prod [BB*HIDC*CHW];           //  89 MB
__device__ float g_gram [BB*NHD*80];
__device__ float g_weff [BB*TT*TT];
__device__ float g_pool [BB*TT];
__device__ float g_se   [BB*TT];

__device__ __forceinline__ float warp_sum(float v){
    v += __shfl_xor_sync(0xffffffffu, v, 16);
    v += __shfl_xor_sync(0xffffffffu, v, 8);
    v += __shfl_xor_sync(0xffffffffu, v, 4);
    v += __shfl_xor_sync(0xffffffffu, v, 2);
    v += __shfl_xor_sync(0xffffffffu, v, 1);
    return v;
}

// ---------------- K0: zero small accumulators ----------------
__global__ void k_init(){
    int t = threadIdx.x;
    if (t < BB*NHD*80) g_gram[t] = 0.f;
    if (t < BB*TT)     g_pool[t] = 0.f;
}

// ---------------- K1: LN(channel) + 1x1 conv 64 -> 192 (f32x2, fp16 out) ----------------
__global__ void __launch_bounds__(256) k_ln_qkv(const float* __restrict__ x,
                                                const float* __restrict__ gam,
                                                const float* __restrict__ bet,
                                                const float* __restrict__ qw){
    extern __shared__ float wsh[];               // [64][192] transposed
    __shared__ float gsh[TT], bsh[TT];
    int tid = threadIdx.x;
    for (int i = tid; i < TT*QKVC; i += 256){
        int t = i / QKVC, o = i - t*QKVC;
        wsh[i] = qw[o*TT + t];
    }
    if (tid < TT){ gsh[tid] = gam[tid]; bsh[tid] = bet[tid]; }
    __syncthreads();

    int b = blockIdx.x >> 9;
    int p = ((blockIdx.x & 511) << 8) + tid;
    const float* xb = x + (size_t)b*TT*CHW + p;

    float xn[TT];
    float mean = 0.f;
#pragma unroll
    for (int t = 0; t < TT; t++){ xn[t] = xb[(size_t)t*CHW]; mean += xn[t]; }
    mean *= (1.f/TT);
    float var = 0.f;
#pragma unroll
    for (int t = 0; t < TT; t++){ float d = xn[t]-mean; var += d*d; }
    float rstd = rsqrtf(var*(1.f/TT) + 1e-5f);
#pragma unroll
    for (int t = 0; t < TT; t++) xn[t] = (xn[t]-mean)*rstd*gsh[t] + bsh[t];

    f16* ob = g_qkv + (size_t)b*QKVC*CHW + p;
    for (int og = 0; og < QKVC; og += 16){
        u64 acc[8];
#pragma unroll
        for (int i = 0; i < 8; i++) acc[i] = 0ull;
#pragma unroll
        for (int t = 0; t < TT; t++){
            u64 xv2 = pack_dup(xn[t]);
            const ulonglong2* wp = (const ulonglong2*)&wsh[t*QKVC + og];
#pragma unroll
            for (int q = 0; q < 4; q++){
                ulonglong2 w = wp[q];
                fma2(acc[2*q  ], w.x, xv2);
                fma2(acc[2*q+1], w.y, xv2);
            }
        }
#pragma unroll
        for (int i = 0; i < 8; i++){
            float2 f = unpack2(acc[i]);
            ob[(size_t)(og+2*i  )*CHW] = __float2half_rn(f.x);
            ob[(size_t)(og+2*i+1)*CHW] = __float2half_rn(f.y);
        }
    }
}

// ---------------- K2: depthwise 3x3 over (H,W), 192 channels (fp16 io) ----------------
__global__ void __launch_bounds__(256) k_dw2d(const float* __restrict__ dww){
    int tid = threadIdx.x;
    int j   = tid & 63;
    int sub = tid >> 6;
    int plane = blockIdx.x*4 + sub;
    int ch = (plane >> 5) % QKVC;
    const f16* ip = g_qkv   + (size_t)plane*HW;
    f16*       op = g_qkvdw + (size_t)plane*HW;
    float wv[9];
#pragma unroll
    for (int k = 0; k < 9; k++) wv[k] = __ldg(&dww[ch*9 + k]);
    bool lok = (j > 0), rok = (j < 63);
    float m0=0.f,m1=0.f,m2=0.f;
    float c0 = lok ? __half2float(ip[j-1]) : 0.f;
    float c1 = __half2float(ip[j]);
    float c2 = rok ? __half2float(ip[j+1]) : 0.f;
    for (int h = 0; h < 64; h++){
        float p0, p1, p2;
        if (h < 63){
            const f16* r = ip + (h+1)*64;
            p0 = lok ? __half2float(r[j-1]) : 0.f;
            p1 = __half2float(r[j]);
            p2 = rok ? __half2float(r[j+1]) : 0.f;
        } else { p0 = p1 = p2 = 0.f; }
        float o = wv[0]*m0 + wv[1]*m1 + wv[2]*m2
                + wv[3]*c0 + wv[4]*c1 + wv[5]*c2
                + wv[6]*p0 + wv[7]*p1 + wv[8]*p2;
        op[h*64 + j] = __float2half_rn(o);
        m0=c0; m1=c1; m2=c2; c0=p0; c1=p1; c2=p2;
    }
}

// ---------------- K3: per-head 8x8 Gram + row self-dots (fp16 in) ----------------
__global__ void __launch_bounds__(256) k_gram(){
    int tid = threadIdx.x;
    int chunk = blockIdx.x;
    int n = blockIdx.y, b = blockIdx.z;
    const f16* qb = g_qkvdw + ((size_t)b*QKVC + 16*n)*CHW;
    const f16* kb = qb + (size_t)64*CHW;

    float S[XD][XD], qq[XD], kk[XD];
#pragma unroll
    for (int xi = 0; xi < XD; xi++){
        qq[xi] = 0.f; kk[xi] = 0.f;
#pragma unroll
        for (int yi = 0; yi < XD; yi++) S[xi][yi] = 0.f;
    }
    int pbase = chunk*2048 + tid;
    for (int pp = 0; pp < 8; pp++){
        int p = pbase + pp*256;
#pragma unroll
        for (int par = 0; par < 2; par++){
            float qv[XD], kv[XD];
#pragma unroll
            for (int xi = 0; xi < XD; xi++){
                qv[xi] = __half2float(qb[(size_t)(2*xi + par)*CHW + p]);
                kv[xi] = __half2float(kb[(size_t)(2*xi + par)*CHW + p]);
            }
#pragma unroll
            for (int xi = 0; xi < XD; xi++){
                qq[xi] = fmaf(qv[xi], qv[xi], qq[xi]);
                kk[xi] = fmaf(kv[xi], kv[xi], kk[xi]);
#pragma unroll
                for (int yi = 0; yi < XD; yi++)
                    S[xi][yi] = fmaf(qv[xi], kv[yi], S[xi][yi]);
            }
        }
    }
    float* acc = g_gram + (b*NHD + n)*80;
    int lane = tid & 31;
#pragma unroll
    for (int xi = 0; xi < XD; xi++){
#pragma unroll
        for (int yi = 0; yi < XD; yi++){
            float v = warp_sum(S[xi][yi]);
            if (lane == 0) atomicAdd(&acc[xi*8 + yi], v);
        }
        float vq = warp_sum(qq[xi]);
        float vk = warp_sum(kk[xi]);
        if (lane == 0){ atomicAdd(&acc[64 + xi], vq); atomicAdd(&acc[72 + xi], vk); }
    }
}

// ---------------- K4: softmax + effective 64x64 channel matrix ----------------
__global__ void k_weff(const float* __restrict__ temp, const float* __restrict__ aw){
    int b = blockIdx.x, tid = threadIdx.x;
    __shared__ float att[NHD][XD][XD];
    __shared__ float qn[NHD][XD], kn[NHD][XD];
    const float* G = g_gram + b*NHD*80;
    if (tid < 64){
        int i = tid & 31, n = i >> 3, xx = i & 7;
        if (tid < 32) qn[n][xx] = fmaxf(sqrtf(G[n*80 + 64 + xx]), 1e-12f);
        else          kn[n][xx] = fmaxf(sqrtf(G[n*80 + 72 + xx]), 1e-12f);
    }
    __syncthreads();
    if (tid < 32){
        int n = tid >> 3, xx = tid & 7;
        float tpn = temp[n];
        float sc[XD], mx = -1e30f;
#pragma unroll
        for (int y = 0; y < XD; y++){
            sc[y] = G[n*80 + xx*8 + y] / (qn[n][xx]*kn[n][y]) * tpn;
            mx = fmaxf(mx, sc[y]);
        }
        float sum = 0.f;
#pragma unroll
        for (int y = 0; y < XD; y++){ sc[y] = expf(sc[y]-mx); sum += sc[y]; }
        float inv = 1.f/sum;
#pragma unroll
        for (int y = 0; y < XD; y++) att[n][xx][y] = sc[y]*inv;
    }
    __syncthreads();
    for (int e = tid; e < TT*TT; e += blockDim.x){
        int to = e >> 6, tv = e & 63;
        int n = tv >> 4, p = tv & 1, y = (tv >> 1) & 7;
        float s = 0.f;
#pragma unroll
        for (int xx = 0; xx < XD; xx++)
            s = fmaf(aw[to*64 + 16*n + 2*xx + p], att[n][xx][y], s);
        g_weff[b*4096 + e] = s;
    }
}

// ---------------- K5: x + W_eff @ V (f32x2, fp16 V) ----------------
__global__ void __launch_bounds__(256) k_apply(const float* __restrict__ x){
    __shared__ float wsh[TT*TT];                  // [tv][to]
    int tid = threadIdx.x;
    int b = blockIdx.x >> 9;
    for (int i = tid; i < TT*TT; i += 256){
        int tv = i >> 6, to = i & 63;
        wsh[i] = g_weff[b*4096 + to*64 + tv];
    }
    __syncthreads();
    int p = ((blockIdx.x & 511) << 8) + tid;
    const f16* vb = g_qkvdw + ((size_t)b*QKVC + 128)*CHW + p;
    u64 acc[32];
#pragma unroll
    for (int i = 0; i < 32; i++) acc[i] = 0ull;
    for (int tv = 0; tv < TT; tv++){
        u64 v2 = pack_dup(__half2float(vb[(size_t)tv*CHW]));
        const ulonglong2* wp = (const ulonglong2*)&wsh[tv*TT];
#pragma unroll
        for (int q = 0; q < 16; q++){
            ulonglong2 w = wp[q];
            fma2(acc[2*q  ], w.x, v2);
            fma2(acc[2*q+1], w.y, v2);
        }
    }
    const float* xb = x    + (size_t)b*TT*CHW + p;
    float*       ob = g_xa + (size_t)b*TT*CHW + p;
#pragma unroll
    for (int i = 0; i < 32; i++){
        float2 f = unpack2(acc[i]);
        ob[(size_t)(2*i  )*CHW] = f.x + xb[(size_t)(2*i  )*CHW];
        ob[(size_t)(2*i+1)*CHW] = f.y + xb[(size_t)(2*i+1)*CHW];
    }
}

// ---------------- K6: LN(channel) + 1x1 conv 64 -> 340 (f32x2, fp16 out) ----------------
__global__ void __launch_bounds__(256) k_ln_pin(const float* __restrict__ gam,
                                                const float* __restrict__ bet,
                                                const float* __restrict__ pw){
    extern __shared__ float wsh[];                // [64][340] transposed
    __shared__ float gsh[TT], bsh[TT];
    int tid = threadIdx.x;
    for (int i = tid; i < TT*PINC; i += 256){
        int t = i / PINC, o = i - t*PINC;
        wsh[i] = pw[o*TT + t];
    }
    if (tid < TT){ gsh[tid] = gam[tid]; bsh[tid] = bet[tid]; }
    __syncthreads();

    int b = blockIdx.x >> 9;
    int p = ((blockIdx.x & 511) << 8) + tid;
    const float* xb = g_xa + (size_t)b*TT*CHW + p;

    float xn[TT];
    float mean = 0.f;
#pragma unroll
    for (int t = 0; t < TT; t++){ xn[t] = xb[(size_t)t*CHW]; mean += xn[t]; }
    mean *= (1.f/TT);
    float var = 0.f;
#pragma unroll
    for (int t = 0; t < TT; t++){ float d = xn[t]-mean; var += d*d; }
    float rstd = rsqrtf(var*(1.f/TT) + 1e-5f);
#pragma unroll
    for (int t = 0; t < TT; t++) xn[t] = (xn[t]-mean)*rstd*gsh[t] + bsh[t];

    f16* ob = g_pin + (size_t)b*PINC*CHW + p;
    for (int og = 0; og < PINC; og += 20){
        u64 acc[10];
#pragma unroll
        for (int i = 0; i < 10; i++) acc[i] = 0ull;
#pragma unroll
        for (int t = 0; t < TT; t++){
            u64 xv2 = pack_dup(xn[t]);
            const ulonglong2* wp = (const ulonglong2*)&wsh[t*PINC + og];
#pragma unroll
            for (int q = 0; q < 5; q++){
                ulonglong2 w = wp[q];
                fma2(acc[2*q  ], w.x, xv2);
                fma2(acc[2*q+1], w.y, xv2);
            }
        }
#pragma unroll
        for (int i = 0; i < 10; i++){
            float2 f = unpack2(acc[i]);
            ob[(size_t)(og+2*i  )*CHW] = __float2half_rn(f.x);
            ob[(size_t)(og+2*i+1)*CHW] = __float2half_rn(f.y);
        }
    }
}

// ---------------- K7: tiled depthwise 3x3x3 + exact GELU gating ----------------
// grid (8 h-tiles, HIDC, BB), 64 threads (one per w). Rotating 3-slice smem
// ring over the c dimension: each g_pin plane row is read from DRAM exactly
// once per h-tile.
__device__ __forceinline__ void dw3d_load_slice(const f16* __restrict__ b1,
                                                const f16* __restrict__ b2,
                                                int c, int h0, int w,
                                                u64 (*sl)[10][66], int s){
    if (c < 0 || c >= CCB){
#pragma unroll
        for (int r = 0; r < 10; r++) sl[s][r][w+1] = 0ull;
        return;
    }
    const f16* p1 = b1 + (size_t)c*HW;
    const f16* p2 = b2 + (size_t)c*HW;
#pragma unroll
    for (int r = 0; r < 10; r++){
        int h = h0 - 1 + r;
        float a = 0.f, bb = 0.f;
        if (h >= 0 && h < 64){
            a  = __half2float(p1[h*64 + w]);
            bb = __half2float(p2[h*64 + w]);
        }
        sl[s][r][w+1] = pack2f(a, bb);
    }
}

__global__ void __launch_bounds__(64) k_dw3d(const float* __restrict__ dww){
    __shared__ u64 sl[3][10][66];
    int w  = threadIdx.x;
    int h0 = blockIdx.x * 8;
    int j  = blockIdx.y, b = blockIdx.z;
    const f16* b1 = g_pin + (size_t)(b*PINC + j)*CHW;
    const f16* b2 = g_pin + (size_t)(b*PINC + j + HIDC)*CHW;
    f16* op = g_prod + ((size_t)(b*HIDC + j)*CCB)*HW;

    u64 wp[27];
#pragma unroll
    for (int k = 0; k < 27; k++)
        wp[k] = pack2f(__ldg(&dww[j*27 + k]), __ldg(&dww[(j + HIDC)*27 + k]));

    // zero padding columns of all 3 buffers (never written again)
    if (w < 60){ int s = w/20, rr = (w%20)>>1; sl[s][rr][(w&1)*65] = 0ull; }

    dw3d_load_slice(b1, b2, -1, h0, w, sl, 0);
    dw3d_load_slice(b1, b2,  0, h0, w, sl, 1);

    for (int cz = 0; cz < 32; cz++){
        __syncthreads();
        dw3d_load_slice(b1, b2, cz+1, h0, w, sl, (cz+2)%3);
        __syncthreads();

        u64 rr_[3][9];
#pragma unroll
        for (int dc = 0; dc < 3; dc++){
            int buf = (cz + dc) % 3;
#pragma unroll
            for (int dw = 0; dw < 3; dw++){
                rr_[0][dc*3+dw] = sl[buf][0][w+dw];
                rr_[1][dc*3+dw] = sl[buf][1][w+dw];
            }
        }
#pragma unroll
        for (int hh = 0; hh < 8; hh++){
            int inw = (hh+2)%3;
#pragma unroll
            for (int dc = 0; dc < 3; dc++){
                int buf = (cz + dc) % 3;
#pragma unroll
                for (int dw = 0; dw < 3; dw++)
                    rr_[inw][dc*3+dw] = sl[buf][hh+2][w+dw];
            }
            const u64* rm = rr_[hh%3];
            const u64* rc = rr_[(hh+1)%3];
            const u64* rp = rr_[inw];
            u64 acc = 0ull;
#pragma unroll
            for (int dc = 0; dc < 3; dc++){
#pragma unroll
                for (int dw = 0; dw < 3; dw++){
                    fma2(acc, wp[dc*9 + 0*3 + dw], rm[dc*3+dw]);
                    fma2(acc, wp[dc*9 + 1*3 + dw], rc[dc*3+dw]);
                    fma2(acc, wp[dc*9 + 2*3 + dw], rp[dc*3+dw]);
                }
            }
            float2 a = unpack2(acc);
            float g = 0.5f*a.x*(1.f + erff(a.x*0.70710678118654752f));
            op[(size_t)cz*HW + (h0+hh)*64 + w] = __float2half_rn(g*a.y);
        }
    }
}

// ---------------- K8: 1x1 conv 170->64 + residual + SE pooling (fp16 in) ----------------
__global__ void __launch_bounds__(256) k_pout(const float* __restrict__ pw,
                                              float* __restrict__ dout){
    __shared__ float wsh[HIDC*TT];                // [t][o]
    __shared__ float pool[TT];
    int tid = threadIdx.x;
    for (int i = tid; i < HIDC*TT; i += 256){
        int t = i >> 6, o = i & 63;
        wsh[i] = pw[o*HIDC + t];
    }
    if (tid < TT) pool[tid] = 0.f;
    __syncthreads();

    int b = blockIdx.x >> 9;
    int p = ((blockIdx.x & 511) << 8) + tid;
    const f16* pr = g_prod + (size_t)b*HIDC*CHW + p;

    u64 acc[32];
#pragma unroll
    for (int i = 0; i < 32; i++) acc[i] = 0ull;
#pragma unroll 2
    for (int t = 0; t < HIDC; t++){
        u64 v2 = pack_dup(__half2float(pr[(size_t)t*CHW]));
        const ulonglong2* wp = (const ulonglong2*)&wsh[t*TT];
#pragma unroll
        for (int q = 0; q < 16; q++){
            ulonglong2 w = wp[q];
            fma2(acc[2*q  ], w.x, v2);
            fma2(acc[2*q+1], w.y, v2);
        }
    }
    const float* xb = g_xa + (size_t)b*TT*CHW + p;
    float*       ob = dout + (size_t)b*TT*CHW + p;
    int lane = tid & 31;
#pragma unroll
    for (int i = 0; i < 32; i++){
        float2 f = unpack2(acc[i]);
        float r0 = f.x + xb[(size_t)(2*i  )*CHW];
        float r1 = f.y + xb[(size_t)(2*i+1)*CHW];
        ob[(size_t)(2*i  )*CHW] = r0;
        ob[(size_t)(2*i+1)*CHW] = r1;
        float v0 = warp_sum(r0);
        float v1 = warp_sum(r1);
        if (lane == 0){ atomicAdd(&pool[2*i], v0); atomicAdd(&pool[2*i+1], v1); }
    }
    __syncthreads();
    if (tid < TT) atomicAdd(&g_pool[b*TT + tid], pool[tid]);
}

// ---------------- K9: SE gate ----------------
__global__ void k_se(const float* __restrict__ sew, const float* __restrict__ seb){
    int tid = threadIdx.x;
    if (tid >= BB*TT) return;
    int b = tid >> 6, o = tid & 63;
    float s = 0.f;
#pragma unroll
    for (int t = 0; t < TT; t++)
        s = fmaf(sew[o*TT + t], g_pool[b*TT + t]*(1.f/131072.f), s);
    s += seb[o];
    g_se[b*TT + o] = 1.f/(1.f + expf(-s));
}

// ---------------- K10: in-place SE scale ----------------
__global__ void k_final(float* __restrict__ dout){
    int idx = blockIdx.x*256 + threadIdx.x;
    float4* o4 = (float4*)dout;
    float s = g_se[idx >> 15];
    float4 v = o4[idx];
    v.x *= s; v.y *= s; v.z *= s; v.w *= s;
    o4[idx] = v;
}

// ---------------- launch ----------------
extern "C" void kernel_launch(void* const* d_in, const int* in_sizes, int n_in,
                              void* d_out, int out_size){
    const float* x     = (const float*)d_in[0];
    const float* n1g   = (const float*)d_in[1];
    const float* n1b   = (const float*)d_in[2];
    const float* temp  = (const float*)d_in[3];
    const float* qkvw  = (const float*)d_in[4];
    const float* qkvdw = (const float*)d_in[5];
    const float* aow   = (const float*)d_in[6];
    const float* n2g   = (const float*)d_in[7];
    const float* n2b   = (const float*)d_in[8];
    const float* pinw  = (const float*)d_in[9];
    const float* dww   = (const float*)d_in[10];
    const float* poutw = (const float*)d_in[11];
    const float* sew   = (const float*)d_in[12];
    const float* seb   = (const float*)d_in[13];
    float* out = (float*)d_out;

    cudaFuncSetAttribute(k_ln_pin, cudaFuncAttributeMaxDynamicSharedMemorySize,
                         TT*PINC*(int)sizeof(float));
    cudaFuncSetAttribute(k_ln_qkv, cudaFuncAttributeMaxDynamicSharedMemorySize,
                         TT*QKVC*(int)sizeof(float));

    k_init  <<<1, 1024>>>();
    k_ln_qkv<<<1024, 256, TT*QKVC*sizeof(float)>>>(x, n1g, n1b, qkvw);
    k_dw2d  <<<3072, 256>>>(qkvdw);
    k_gram  <<<dim3(64, NHD, BB), 256>>>();
    k_weff  <<<BB, 256>>>(temp, aow);
    k_apply <<<1024, 256>>>(x);
    k_ln_pin<<<1024, 256, TT*PINC*sizeof(float)>>>(n2g, n2b, pinw);
    k_dw3d  <<<dim3(8, HIDC, BB), 64>>>(dww);
    k_pout  <<<1024, 256>>>(poutw, out);
    k_se    <<<1, 128>>>(sew, seb);
    k_final <<<16384, 256>>>(out);
}

// round 12
// speedup vs baseline: 1.2558x; 1.0439x over previous
#include <cuda_runtime.h>
#include <cuda_fp16.h>
#include <math.h>

#define BB   2
#define TT   64
#define CCB  32
#define HW   4096
#define CHW  131072
#define NHD  4
#define XD   8
#define HIDC 170
#define QKVC 192
#define PINC 340

typedef unsigned long long u64;
typedef __half f16;

// ---------------- packed f32x2 helpers ----------------
__device__ __forceinline__ u64 pack2f(float a, float b){
    u64 r;
    asm("mov.b64 %0, {%1, %2};" : "=l"(r)
        : "r"(__float_as_uint(a)), "r"(__float_as_uint(b)));
    return r;
}
__device__ __forceinline__ u64 pack_dup(float a){
    unsigned ai = __float_as_uint(a);
    u64 r;
    asm("mov.b64 %0, {%1, %1};" : "=l"(r) : "r"(ai));
    return r;
}
__device__ __forceinline__ void fma2(u64 &d, u64 a, u64 b){
    asm("fma.rn.f32x2 %0, %1, %2, %0;" : "+l"(d) : "l"(a), "l"(b));
}
__device__ __forceinline__ float2 unpack2(u64 v){
    unsigned lo, hi;
    asm("mov.b64 {%0, %1}, %2;" : "=r"(lo), "=r"(hi) : "l"(v));
    float2 f; f.x = __uint_as_float(lo); f.y = __uint_as_float(hi);
    return f;
}

// ---------------- scratch (static device, allocation-free) ----------------
__device__ f16   g_qkv  [BB*QKVC*CHW];
__device__ f16   g_qkvdw[BB*QKVC*CHW];
__device__ float g_xa   [BB*TT*CHW];
__device__ f16   g_pin  [BB*PINC*CHW];
__device__ f16   g_prod [BB*HIDC*CHW];
__device__ float g_gram [BB*NHD*80];
__device__ float g_weff [BB*TT*TT];
__device__ float g_pool [BB*TT];
__device__ float g_se   [BB*TT];

__device__ __forceinline__ float warp_sum(float v){
    v += __shfl_xor_sync(0xffffffffu, v, 16);
    v += __shfl_xor_sync(0xffffffffu, v, 8);
    v += __shfl_xor_sync(0xffffffffu, v, 4);
    v += __shfl_xor_sync(0xffffffffu, v, 2);
    v += __shfl_xor_sync(0xffffffffu, v, 1);
    return v;
}

// ---------------- K0 ----------------
__global__ void k_init(){
    int t = threadIdx.x;
    if (t < BB*NHD*80) g_gram[t] = 0.f;
    if (t < BB*TT)     g_pool[t] = 0.f;
}

// ---------------- K1: LN + 1x1 conv 64 -> 192 ----------------
__global__ void __launch_bounds__(256) k_ln_qkv(const float* __restrict__ x,
                                                const float* __restrict__ gam,
                                                const float* __restrict__ bet,
                                                const float* __restrict__ qw){
    extern __shared__ float wsh[];
    __shared__ float gsh[TT], bsh[TT];
    int tid = threadIdx.x;
    for (int i = tid; i < TT*QKVC; i += 256){
        int t = i / QKVC, o = i - t*QKVC;
        wsh[i] = qw[o*TT + t];
    }
    if (tid < TT){ gsh[tid] = gam[tid]; bsh[tid] = bet[tid]; }
    __syncthreads();

    int b = blockIdx.x >> 9;
    int p = ((blockIdx.x & 511) << 8) + tid;
    const float* xb = x + (size_t)b*TT*CHW + p;

    float xn[TT];
    float mean = 0.f;
#pragma unroll
    for (int t = 0; t < TT; t++){ xn[t] = xb[(size_t)t*CHW]; mean += xn[t]; }
    mean *= (1.f/TT);
    float var = 0.f;
#pragma unroll
    for (int t = 0; t < TT; t++){ float d = xn[t]-mean; var += d*d; }
    float rstd = rsqrtf(var*(1.f/TT) + 1e-5f);
#pragma unroll
    for (int t = 0; t < TT; t++) xn[t] = (xn[t]-mean)*rstd*gsh[t] + bsh[t];

    f16* ob = g_qkv + (size_t)b*QKVC*CHW + p;
    for (int og = 0; og < QKVC; og += 16){
        u64 acc[8];
#pragma unroll
        for (int i = 0; i < 8; i++) acc[i] = 0ull;
#pragma unroll
        for (int t = 0; t < TT; t++){
            u64 xv2 = pack_dup(xn[t]);
            const ulonglong2* wp = (const ulonglong2*)&wsh[t*QKVC + og];
#pragma unroll
            for (int q = 0; q < 4; q++){
                ulonglong2 w = wp[q];
                fma2(acc[2*q  ], w.x, xv2);
                fma2(acc[2*q+1], w.y, xv2);
            }
        }
#pragma unroll
        for (int i = 0; i < 8; i++){
            float2 f = unpack2(acc[i]);
            ob[(size_t)(og+2*i  )*CHW] = __float2half_rn(f.x);
            ob[(size_t)(og+2*i+1)*CHW] = __float2half_rn(f.y);
        }
    }
}

// ---------------- K2: depthwise 3x3 (H,W), smem-staged wide-load version ----------------
__global__ void __launch_bounds__(256) k_dw2d(const float* __restrict__ dww){
    __shared__ __half s[66][80];                  // zero-padded plane tile
    int tid = threadIdx.x;
    int plane = blockIdx.x;                       // (b*192+ch)*32 + c
    int ch = (plane >> 5) % QKVC;
    const f16* ip = g_qkv   + (size_t)plane*HW;
    f16*       op = g_qkvdw + (size_t)plane*HW;

    // zero-fill padded tile (660 uint4)
    uint4 z4; z4.x = z4.y = z4.z = z4.w = 0u;
    for (int i = tid; i < 660; i += 256) ((uint4*)s)[i] = z4;
    __syncthreads();
    // stage plane: 512 uint4 (16B) loads
    for (int i = tid; i < 512; i += 256){
        int r = i >> 3, c8 = i & 7;
        uint4 v = ((const uint4*)(ip + r*64))[c8];
        *(uint4*)&s[1+r][8 + c8*8] = v;
    }

    float wv[9];
#pragma unroll
    for (int k = 0; k < 9; k++) wv[k] = __ldg(&dww[ch*9 + k]);
    __syncthreads();

    int h  = tid >> 2;
    int wq = (tid & 3) << 4;
    float c0[3], c1[3];
#pragma unroll
    for (int dh = 0; dh < 3; dh++){
        c0[dh] = __half2float(s[h+dh][7+wq]);
        c1[dh] = __half2float(s[h+dh][8+wq]);
    }
    __align__(16) __half res[16];
#pragma unroll
    for (int w = 0; w < 16; w++){
        float c2[3];
#pragma unroll
        for (int dh = 0; dh < 3; dh++) c2[dh] = __half2float(s[h+dh][9+wq+w]);
        float o = wv[0]*c0[0] + wv[1]*c1[0] + wv[2]*c2[0]
                + wv[3]*c0[1] + wv[4]*c1[1] + wv[5]*c2[1]
                + wv[6]*c0[2] + wv[7]*c1[2] + wv[8]*c2[2];
        res[w] = __float2half_rn(o);
#pragma unroll
        for (int dh = 0; dh < 3; dh++){ c0[dh] = c1[dh]; c1[dh] = c2[dh]; }
    }
    uint4* o4 = (uint4*)(op + h*64 + wq);
    o4[0] = *(uint4*)&res[0];
    o4[1] = *(uint4*)&res[8];
}

// ---------------- K3: per-head 8x8 Gram, half2 position pairs ----------------
__global__ void __launch_bounds__(256, 2) k_gram(){
    int tid = threadIdx.x;
    int chunk = blockIdx.x;
    int n = blockIdx.y, b = blockIdx.z;
    const f16* qb = g_qkvdw + ((size_t)b*QKVC + 16*n)*CHW;
    const f16* kb = qb + (size_t)64*CHW;

    float S[XD][XD], qq[XD], kk[XD];
#pragma unroll
    for (int xi = 0; xi < XD; xi++){
        qq[xi] = 0.f; kk[xi] = 0.f;
#pragma unroll
        for (int yi = 0; yi < XD; yi++) S[xi][yi] = 0.f;
    }
    int p0 = chunk*2048 + tid*2;
#pragma unroll
    for (int it = 0; it < 4; it++){
        int p = p0 + it*512;
#pragma unroll
        for (int par = 0; par < 2; par++){
            __half2 q2[XD], k2[XD];
#pragma unroll
            for (int xi = 0; xi < XD; xi++){
                q2[xi] = *(const __half2*)(qb + (size_t)(2*xi + par)*CHW + p);
                k2[xi] = *(const __half2*)(kb + (size_t)(2*xi + par)*CHW + p);
            }
            float2 kf[XD];
#pragma unroll
            for (int yi = 0; yi < XD; yi++){
                kf[yi] = __half22float2(k2[yi]);
                kk[yi] = fmaf(kf[yi].x, kf[yi].x, kk[yi]);
                kk[yi] = fmaf(kf[yi].y, kf[yi].y, kk[yi]);
            }
#pragma unroll
            for (int xi = 0; xi < XD; xi++){
                float2 qf = __half22float2(q2[xi]);
                qq[xi] = fmaf(qf.x, qf.x, qq[xi]);
                qq[xi] = fmaf(qf.y, qf.y, qq[xi]);
#pragma unroll
                for (int yi = 0; yi < XD; yi++){
                    S[xi][yi] = fmaf(qf.x, kf[yi].x, S[xi][yi]);
                    S[xi][yi] = fmaf(qf.y, kf[yi].y, S[xi][yi]);
                }
            }
        }
    }
    float* acc = g_gram + (b*NHD + n)*80;
    int lane = tid & 31;
#pragma unroll
    for (int xi = 0; xi < XD; xi++){
#pragma unroll
        for (int yi = 0; yi < XD; yi++){
            float v = warp_sum(S[xi][yi]);
            if (lane == 0) atomicAdd(&acc[xi*8 + yi], v);
        }
        float vq = warp_sum(qq[xi]);
        float vk = warp_sum(kk[xi]);
        if (lane == 0){ atomicAdd(&acc[64 + xi], vq); atomicAdd(&acc[72 + xi], vk); }
    }
}

// ---------------- K4: softmax + effective 64x64 channel matrix ----------------
__global__ void k_weff(const float* __restrict__ temp, const float* __restrict__ aw){
    int b = blockIdx.x, tid = threadIdx.x;
    __shared__ float att[NHD][XD][XD];
    __shared__ float qn[NHD][XD], kn[NHD][XD];
    const float* G = g_gram + b*NHD*80;
    if (tid < 64){
        int i = tid & 31, n = i >> 3, xx = i & 7;
        if (tid < 32) qn[n][xx] = fmaxf(sqrtf(G[n*80 + 64 + xx]), 1e-12f);
        else          kn[n][xx] = fmaxf(sqrtf(G[n*80 + 72 + xx]), 1e-12f);
    }
    __syncthreads();
    if (tid < 32){
        int n = tid >> 3, xx = tid & 7;
        float tpn = temp[n];
        float sc[XD], mx = -1e30f;
#pragma unroll
        for (int y = 0; y < XD; y++){
            sc[y] = G[n*80 + xx*8 + y] / (qn[n][xx]*kn[n][y]) * tpn;
            mx = fmaxf(mx, sc[y]);
        }
        float sum = 0.f;
#pragma unroll
        for (int y = 0; y < XD; y++){ sc[y] = expf(sc[y]-mx); sum += sc[y]; }
        float inv = 1.f/sum;
#pragma unroll
        for (int y = 0; y < XD; y++) att[n][xx][y] = sc[y]*inv;
    }
    __syncthreads();
    for (int e = tid; e < TT*TT; e += blockDim.x){
        int to = e >> 6, tv = e & 63;
        int n = tv >> 4, p = tv & 1, y = (tv >> 1) & 7;
        float s = 0.f;
#pragma unroll
        for (int xx = 0; xx < XD; xx++)
            s = fmaf(aw[to*64 + 16*n + 2*xx + p], att[n][xx][y], s);
        g_weff[b*4096 + e] = s;
    }
}

// ---------------- K5: x + W_eff @ V (prefetched) ----------------
__global__ void __launch_bounds__(256) k_apply(const float* __restrict__ x){
    __shared__ float wsh[TT*TT];                  // [tv][to]
    int tid = threadIdx.x;
    int b = blockIdx.x >> 9;
    for (int i = tid; i < TT*TT; i += 256){
        int tv = i >> 6, to = i & 63;
        wsh[i] = g_weff[b*4096 + to*64 + tv];
    }
    __syncthreads();
    int p = ((blockIdx.x & 511) << 8) + tid;
    const f16* vb = g_qkvdw + ((size_t)b*QKVC + 128)*CHW + p;
    u64 acc[32];
#pragma unroll
    for (int i = 0; i < 32; i++) acc[i] = 0ull;

    f16 pv[8];
#pragma unroll
    for (int i = 0; i < 8; i++) pv[i] = vb[(size_t)i*CHW];
#pragma unroll
    for (int t0 = 0; t0 < TT; t0 += 8){
        f16 nv[8];
        if (t0 < TT-8){
#pragma unroll
            for (int i = 0; i < 8; i++) nv[i] = vb[(size_t)(t0+8+i)*CHW];
        }
#pragma unroll
        for (int i = 0; i < 8; i++){
            u64 v2 = pack_dup(__half2float(pv[i]));
            const ulonglong2* wp = (const ulonglong2*)&wsh[(t0+i)*TT];
#pragma unroll
            for (int q = 0; q < 16; q++){
                ulonglong2 w = wp[q];
                fma2(acc[2*q  ], w.x, v2);
                fma2(acc[2*q+1], w.y, v2);
            }
        }
#pragma unroll
        for (int i = 0; i < 8; i++) pv[i] = nv[i];
    }
    const float* xb = x    + (size_t)b*TT*CHW + p;
    float*       ob = g_xa + (size_t)b*TT*CHW + p;
#pragma unroll
    for (int i = 0; i < 32; i++){
        float2 f = unpack2(acc[i]);
        ob[(size_t)(2*i  )*CHW] = f.x + xb[(size_t)(2*i  )*CHW];
        ob[(size_t)(2*i+1)*CHW] = f.y + xb[(size_t)(2*i+1)*CHW];
    }
}

// ---------------- K6: LN + 1x1 conv 64 -> 340 ----------------
__global__ void __launch_bounds__(256) k_ln_pin(const float* __restrict__ gam,
                                                const float* __restrict__ bet,
                                                const float* __restrict__ pw){
    extern __shared__ float wsh[];
    __shared__ float gsh[TT], bsh[TT];
    int tid = threadIdx.x;
    for (int i = tid; i < TT*PINC; i += 256){
        int t = i / PINC, o = i - t*PINC;
        wsh[i] = pw[o*TT + t];
    }
    if (tid < TT){ gsh[tid] = gam[tid]; bsh[tid] = bet[tid]; }
    __syncthreads();

    int b = blockIdx.x >> 9;
    int p = ((blockIdx.x & 511) << 8) + tid;
    const float* xb = g_xa + (size_t)b*TT*CHW + p;

    float xn[TT];
    float mean = 0.f;
#pragma unroll
    for (int t = 0; t < TT; t++){ xn[t] = xb[(size_t)t*CHW]; mean += xn[t]; }
    mean *= (1.f/TT);
    float var = 0.f;
#pragma unroll
    for (int t = 0; t < TT; t++){ float d = xn[t]-mean; var += d*d; }
    float rstd = rsqrtf(var*(1.f/TT) + 1e-5f);
#pragma unroll
    for (int t = 0; t < TT; t++) xn[t] = (xn[t]-mean)*rstd*gsh[t] + bsh[t];

    f16* ob = g_pin + (size_t)b*PINC*CHW + p;
    for (int og = 0; og < PINC; og += 20){
        u64 acc[10];
#pragma unroll
        for (int i = 0; i < 10; i++) acc[i] = 0ull;
#pragma unroll
        for (int t = 0; t < TT; t++){
            u64 xv2 = pack_dup(xn[t]);
            const ulonglong2* wp = (const ulonglong2*)&wsh[t*PINC + og];
#pragma unroll
            for (int q = 0; q < 5; q++){
                ulonglong2 w = wp[q];
                fma2(acc[2*q  ], w.x, xv2);
                fma2(acc[2*q+1], w.y, xv2);
            }
        }
#pragma unroll
        for (int i = 0; i < 10; i++){
            float2 f = unpack2(acc[i]);
            ob[(size_t)(og+2*i  )*CHW] = __float2half_rn(f.x);
            ob[(size_t)(og+2*i+1)*CHW] = __float2half_rn(f.y);
        }
    }
}

// ---------------- K7: tiled depthwise 3x3x3 + exact GELU gating ----------------
// 64 threads: lanes 0..31 load branch-1 column pairs via half2, lanes 32..63
// branch-2; interleaved packed float2 smem ring (LDS.64 taps in compute).
__global__ void __launch_bounds__(64) k_dw3d(const float* __restrict__ dww){
    __shared__ float2 slP[3][10][68];             // interior cols 2..65, pads 0..1/66..67
    int tid = threadIdx.x;
    int lid = tid & 31;
    int branch = tid >> 5;
    int w  = tid;                                 // compute role: one w column each
    int h0 = blockIdx.x * 8;
    int j  = blockIdx.y, b = blockIdx.z;
    const f16* b1 = g_pin + (size_t)(b*PINC + j)*CHW;
    const f16* b2 = g_pin + (size_t)(b*PINC + j + HIDC)*CHW;
    const f16* src = branch ? b2 : b1;
    f16* op = g_prod + ((size_t)(b*HIDC + j)*CCB)*HW;

    u64 wp[27];
#pragma unroll
    for (int k = 0; k < 27; k++)
        wp[k] = pack2f(__ldg(&dww[j*27 + k]), __ldg(&dww[(j + HIDC)*27 + k]));

    // zero padding columns once (cols 0,1,66,67 of every [s][r])
    for (int i = tid; i < 120; i += 64){
        int s = i/40, rem = i%40, r = rem>>2, c4 = rem&3;
        int col = (c4 < 2) ? c4 : 64 + c4;
        slP[s][r][col].x = 0.f; slP[s][r][col].y = 0.f;
    }

    // loader lambda-equivalent
    float* sbase = &slP[0][0][0].x;
    auto load_slice = [&](int c, int s){
#pragma unroll
        for (int r = 0; r < 10; r++){
            int h = h0 - 1 + r;
            float2 f; f.x = 0.f; f.y = 0.f;
            if (c >= 0 && c < CCB && h >= 0 && h < 64){
                __half2 hv = *(const __half2*)(src + (size_t)c*HW + h*64 + 2*lid);
                f = __half22float2(hv);
            }
            float* rowb = sbase + ((s*10 + r)*68)*2;
            rowb[2*(2 + 2*lid) + branch] = f.x;
            rowb[2*(3 + 2*lid) + branch] = f.y;
        }
    };

    load_slice(-1, 0);
    load_slice( 0, 1);

    for (int cz = 0; cz < 32; cz++){
        __syncthreads();
        load_slice(cz+1, (cz+2)%3);
        __syncthreads();

        u64 rr_[3][9];
#pragma unroll
        for (int dc = 0; dc < 3; dc++){
            int buf = (cz + dc) % 3;
#pragma unroll
            for (int dw = 0; dw < 3; dw++){
                rr_[0][dc*3+dw] = *(const u64*)&slP[buf][0][1 + w + dw];
                rr_[1][dc*3+dw] = *(const u64*)&slP[buf][1][1 + w + dw];
            }
        }
#pragma unroll
        for (int hh = 0; hh < 8; hh++){
            int inw = (hh+2)%3;
#pragma unroll
            for (int dc = 0; dc < 3; dc++){
                int buf = (cz + dc) % 3;
#pragma unroll
                for (int dw = 0; dw < 3; dw++)
                    rr_[inw][dc*3+dw] = *(const u64*)&slP[buf][hh+2][1 + w + dw];
            }
            const u64* rm = rr_[hh%3];
            const u64* rc = rr_[(hh+1)%3];
            const u64* rp = rr_[inw];
            u64 acc = 0ull;
#pragma unroll
            for (int dc = 0; dc < 3; dc++){
#pragma unroll
                for (int dw = 0; dw < 3; dw++){
                    fma2(acc, wp[dc*9 + 0*3 + dw], rm[dc*3+dw]);
                    fma2(acc, wp[dc*9 + 1*3 + dw], rc[dc*3+dw]);
                    fma2(acc, wp[dc*9 + 2*3 + dw], rp[dc*3+dw]);
                }
            }
            float2 a = unpack2(acc);
            float g = 0.5f*a.x*(1.f + erff(a.x*0.70710678118654752f));
            op[(size_t)cz*HW + (h0+hh)*64 + w] = __float2half_rn(g*a.y);
        }
    }
}

// ---------------- K8: 1x1 conv 170->64 + residual + SE pooling (prefetched) ----------------
__global__ void __launch_bounds__(256) k_pout(const float* __restrict__ pw,
                                              float* __restrict__ dout){
    __shared__ float wsh[HIDC*TT];                // [t][o]
    __shared__ float pool[TT];
    int tid = threadIdx.x;
    for (int i = tid; i < HIDC*TT; i += 256){
        int t = i >> 6, o = i & 63;
        wsh[i] = pw[o*HIDC + t];
    }
    if (tid < TT) pool[tid] = 0.f;
    __syncthreads();

    int b = blockIdx.x >> 9;
    int p = ((blockIdx.x & 511) << 8) + tid;
    const f16* pr = g_prod + (size_t)b*HIDC*CHW + p;

    u64 acc[32];
#pragma unroll
    for (int i = 0; i < 32; i++) acc[i] = 0ull;

    f16 pv[10];
#pragma unroll
    for (int i = 0; i < 10; i++) pv[i] = pr[(size_t)i*CHW];
#pragma unroll 1
    for (int t0 = 0; t0 < HIDC; t0 += 10){
        f16 nv[10];
        if (t0 < HIDC-10){
#pragma unroll
            for (int i = 0; i < 10; i++) nv[i] = pr[(size_t)(t0+10+i)*CHW];
        }
#pragma unroll
        for (int i = 0; i < 10; i++){
            u64 v2 = pack_dup(__half2float(pv[i]));
            const ulonglong2* wp = (const ulonglong2*)&wsh[(t0+i)*TT];
#pragma unroll
            for (int q = 0; q < 16; q++){
                ulonglong2 w = wp[q];
                fma2(acc[2*q  ], w.x, v2);
                fma2(acc[2*q+1], w.y, v2);
            }
        }
#pragma unroll
        for (int i = 0; i < 10; i++) pv[i] = nv[i];
    }
    const float* xb = g_xa + (size_t)b*TT*CHW + p;
    float*       ob = dout + (size_t)b*TT*CHW + p;
    int lane = tid & 31;
#pragma unroll
    for (int i = 0; i < 32; i++){
        float2 f = unpack2(acc[i]);
        float r0 = f.x + xb[(size_t)(2*i  )*CHW];
        float r1 = f.y + xb[(size_t)(2*i+1)*CHW];
        ob[(size_t)(2*i  )*CHW] = r0;
        ob[(size_t)(2*i+1)*CHW] = r1;
        float v0 = warp_sum(r0);
        float v1 = warp_sum(r1);
        if (lane == 0){ atomicAdd(&pool[2*i], v0); atomicAdd(&pool[2*i+1], v1); }
    }
    __syncthreads();
    if (tid < TT) atomicAdd(&g_pool[b*TT + tid], pool[tid]);
}

// ---------------- K9: SE gate ----------------
__global__ void k_se(const float* __restrict__ sew, const float* __restrict__ seb){
    int tid = threadIdx.x;
    if (tid >= BB*TT) return;
    int b = tid >> 6, o = tid & 63;
    float s = 0.f;
#pragma unroll
    for (int t = 0; t < TT; t++)
        s = fmaf(sew[o*TT + t], g_pool[b*TT + t]*(1.f/131072.f), s);
    s += seb[o];
    g_se[b*TT + o] = 1.f/(1.f + expf(-s));
}

// ---------------- K10: in-place SE scale ----------------
__global__ void k_final(float* __restrict__ dout){
    int idx = blockIdx.x*256 + threadIdx.x;
    float4* o4 = (float4*)dout;
    float s = g_se[idx >> 15];
    float4 v = o4[idx];
    v.x *= s; v.y *= s; v.z *= s; v.w *= s;
    o4[idx] = v;
}

// ---------------- launch ----------------
extern "C" void kernel_launch(void* const* d_in, const int* in_sizes, int n_in,
                              void* d_out, int out_size){
    const float* x     = (const float*)d_in[0];
    const float* n1g   = (const float*)d_in[1];
    const float* n1b   = (const float*)d_in[2];
    const float* temp  = (const float*)d_in[3];
    const float* qkvw  = (const float*)d_in[4];
    const float* qkvdw = (const float*)d_in[5];
    const float* aow   = (const float*)d_in[6];
    const float* n2g   = (const float*)d_in[7];
    const float* n2b   = (const float*)d_in[8];
    const float* pinw  = (const float*)d_in[9];
    const float* dww   = (const float*)d_in[10];
    const float* poutw = (const float*)d_in[11];
    const float* sew   = (const float*)d_in[12];
    const float* seb   = (const float*)d_in[13];
    float* out = (float*)d_out;

    cudaFuncSetAttribute(k_ln_pin, cudaFuncAttributeMaxDynamicSharedMemorySize,
                         TT*PINC*(int)sizeof(float));
    cudaFuncSetAttribute(k_ln_qkv, cudaFuncAttributeMaxDynamicSharedMemorySize,
                         TT*QKVC*(int)sizeof(float));

    k_init  <<<1, 1024>>>();
    k_ln_qkv<<<1024, 256, TT*QKVC*sizeof(float)>>>(x, n1g, n1b, qkvw);
    k_dw2d  <<<BB*QKVC*CCB, 256>>>(qkvdw);
    k_gram  <<<dim3(64, NHD, BB), 256>>>();
    k_weff  <<<BB, 256>>>(temp, aow);
    k_apply <<<1024, 256>>>(x);
    k_ln_pin<<<1024, 256, TT*PINC*sizeof(float)>>>(n2g, n2b, pinw);
    k_dw3d  <<<dim3(8, HIDC, BB), 64>>>(dww);
    k_pout  <<<1024, 256>>>(poutw, out);
    k_se    <<<1, 128>>>(sew, seb);
    k_final <<<16384, 256>>>(out);
}

// round 13
// speedup vs baseline: 1.2666x; 1.0086x over previous
#include <cuda_runtime.h>
#include <cuda_fp16.h>
#include <math.h>

#define BB   2
#define TT   64
#define CCB  32
#define HW   4096
#define CHW  131072
#define NHD  4
#define XD   8
#define HIDC 170
#define QKVC 192
#define PINC 340

typedef unsigned long long u64;
typedef __half f16;

// ---------------- packed f32x2 helpers ----------------
__device__ __forceinline__ u64 pack2f(float a, float b){
    u64 r;
    asm("mov.b64 %0, {%1, %2};" : "=l"(r)
        : "r"(__float_as_uint(a)), "r"(__float_as_uint(b)));
    return r;
}
__device__ __forceinline__ u64 pack_dup(float a){
    unsigned ai = __float_as_uint(a);
    u64 r;
    asm("mov.b64 %0, {%1, %1};" : "=l"(r) : "r"(ai));
    return r;
}
__device__ __forceinline__ void fma2(u64 &d, u64 a, u64 b){
    asm("fma.rn.f32x2 %0, %1, %2, %0;" : "+l"(d) : "l"(a), "l"(b));
}
__device__ __forceinline__ float2 unpack2(u64 v){
    unsigned lo, hi;
    asm("mov.b64 {%0, %1}, %2;" : "=r"(lo), "=r"(hi) : "l"(v));
    float2 f; f.x = __uint_as_float(lo); f.y = __uint_as_float(hi);
    return f;
}

// ---------------- scratch (static device, allocation-free) ----------------
__device__ f16   g_qkv  [BB*QKVC*CHW];
__device__ f16   g_qkvdw[BB*QKVC*CHW];
__device__ float g_xa   [BB*TT*CHW];
__device__ f16   g_pin  [BB*PINC*CHW];
__device__ f16   g_prod [BB*HIDC*CHW];
__device__ float g_gram [BB*NHD*80];
__device__ float g_weff [BB*TT*TT];
__device__ float g_pool [BB*TT];
__device__ float g_se   [BB*TT];

__device__ __forceinline__ float warp_sum(float v){
    v += __shfl_xor_sync(0xffffffffu, v, 16);
    v += __shfl_xor_sync(0xffffffffu, v, 8);
    v += __shfl_xor_sync(0xffffffffu, v, 4);
    v += __shfl_xor_sync(0xffffffffu, v, 2);
    v += __shfl_xor_sync(0xffffffffu, v, 1);
    return v;
}

// ---------------- K0 ----------------
__global__ void k_init(){
    int t = threadIdx.x;
    if (t < BB*NHD*80) g_gram[t] = 0.f;
    if (t < BB*TT)     g_pool[t] = 0.f;
}

// ---------------- K1: LN + 1x1 conv 64 -> 192 ----------------
__global__ void __launch_bounds__(256) k_ln_qkv(const float* __restrict__ x,
                                                const float* __restrict__ gam,
                                                const float* __restrict__ bet,
                                                const float* __restrict__ qw){
    extern __shared__ float wsh[];
    __shared__ float gsh[TT], bsh[TT];
    int tid = threadIdx.x;
    for (int i = tid; i < TT*QKVC; i += 256){
        int t = i / QKVC, o = i - t*QKVC;
        wsh[i] = qw[o*TT + t];
    }
    if (tid < TT){ gsh[tid] = gam[tid]; bsh[tid] = bet[tid]; }
    __syncthreads();

    int b = blockIdx.x >> 9;
    int p = ((blockIdx.x & 511) << 8) + tid;
    const float* xb = x + (size_t)b*TT*CHW + p;

    float xn[TT];
    float mean = 0.f;
#pragma unroll
    for (int t = 0; t < TT; t++){ xn[t] = xb[(size_t)t*CHW]; mean += xn[t]; }
    mean *= (1.f/TT);
    float var = 0.f;
#pragma unroll
    for (int t = 0; t < TT; t++){ float d = xn[t]-mean; var += d*d; }
    float rstd = rsqrtf(var*(1.f/TT) + 1e-5f);
#pragma unroll
    for (int t = 0; t < TT; t++) xn[t] = (xn[t]-mean)*rstd*gsh[t] + bsh[t];

    f16* ob = g_qkv + (size_t)b*QKVC*CHW + p;
    for (int og = 0; og < QKVC; og += 16){
        u64 acc[8];
#pragma unroll
        for (int i = 0; i < 8; i++) acc[i] = 0ull;
#pragma unroll
        for (int t = 0; t < TT; t++){
            u64 xv2 = pack_dup(xn[t]);
            const ulonglong2* wp = (const ulonglong2*)&wsh[t*QKVC + og];
#pragma unroll
            for (int q = 0; q < 4; q++){
                ulonglong2 w = wp[q];
                fma2(acc[2*q  ], w.x, xv2);
                fma2(acc[2*q+1], w.y, xv2);
            }
        }
#pragma unroll
        for (int i = 0; i < 8; i++){
            float2 f = unpack2(acc[i]);
            ob[(size_t)(og+2*i  )*CHW] = __float2half_rn(f.x);
            ob[(size_t)(og+2*i+1)*CHW] = __float2half_rn(f.y);
        }
    }
}

// ---------------- K2: depthwise 3x3 (H,W), smem-staged wide-load version ----------------
__global__ void __launch_bounds__(256) k_dw2d(const float* __restrict__ dww){
    __shared__ __half s[66][80];                  // zero-padded plane tile
    int tid = threadIdx.x;
    int plane = blockIdx.x;                       // (b*192+ch)*32 + c
    int ch = (plane >> 5) % QKVC;
    const f16* ip = g_qkv   + (size_t)plane*HW;
    f16*       op = g_qkvdw + (size_t)plane*HW;

    // zero-fill padded tile (660 uint4)
    uint4 z4; z4.x = z4.y = z4.z = z4.w = 0u;
    for (int i = tid; i < 660; i += 256) ((uint4*)s)[i] = z4;
    __syncthreads();
    // stage plane: 512 uint4 (16B) loads
    for (int i = tid; i < 512; i += 256){
        int r = i >> 3, c8 = i & 7;
        uint4 v = ((const uint4*)(ip + r*64))[c8];
        *(uint4*)&s[1+r][8 + c8*8] = v;
    }

    float wv[9];
#pragma unroll
    for (int k = 0; k < 9; k++) wv[k] = __ldg(&dww[ch*9 + k]);
    __syncthreads();

    int h  = tid >> 2;
    int wq = (tid & 3) << 4;
    float c0[3], c1[3];
#pragma unroll
    for (int dh = 0; dh < 3; dh++){
        c0[dh] = __half2float(s[h+dh][7+wq]);
        c1[dh] = __half2float(s[h+dh][8+wq]);
    }
    __align__(16) __half res[16];
#pragma unroll
    for (int w = 0; w < 16; w++){
        float c2[3];
#pragma unroll
        for (int dh = 0; dh < 3; dh++) c2[dh] = __half2float(s[h+dh][9+wq+w]);
        float o = wv[0]*c0[0] + wv[1]*c1[0] + wv[2]*c2[0]
                + wv[3]*c0[1] + wv[4]*c1[1] + wv[5]*c2[1]
                + wv[6]*c0[2] + wv[7]*c1[2] + wv[8]*c2[2];
        res[w] = __float2half_rn(o);
#pragma unroll
        for (int dh = 0; dh < 3; dh++){ c0[dh] = c1[dh]; c1[dh] = c2[dh]; }
    }
    uint4* o4 = (uint4*)(op + h*64 + wq);
    o4[0] = *(uint4*)&res[0];
    o4[1] = *(uint4*)&res[8];
}

// ---------------- K3: per-head 8x8 Gram, half2 position pairs ----------------
__global__ void __launch_bounds__(256, 2) k_gram(){
    int tid = threadIdx.x;
    int chunk = blockIdx.x;
    int n = blockIdx.y, b = blockIdx.z;
    const f16* qb = g_qkvdw + ((size_t)b*QKVC + 16*n)*CHW;
    const f16* kb = qb + (size_t)64*CHW;

    float S[XD][XD], qq[XD], kk[XD];
#pragma unroll
    for (int xi = 0; xi < XD; xi++){
        qq[xi] = 0.f; kk[xi] = 0.f;
#pragma unroll
        for (int yi = 0; yi < XD; yi++) S[xi][yi] = 0.f;
    }
    int p0 = chunk*2048 + tid*2;
#pragma unroll
    for (int it = 0; it < 4; it++){
        int p = p0 + it*512;
#pragma unroll
        for (int par = 0; par < 2; par++){
            __half2 q2[XD], k2[XD];
#pragma unroll
            for (int xi = 0; xi < XD; xi++){
                q2[xi] = *(const __half2*)(qb + (size_t)(2*xi + par)*CHW + p);
                k2[xi] = *(const __half2*)(kb + (size_t)(2*xi + par)*CHW + p);
            }
            float2 kf[XD];
#pragma unroll
            for (int yi = 0; yi < XD; yi++){
                kf[yi] = __half22float2(k2[yi]);
                kk[yi] = fmaf(kf[yi].x, kf[yi].x, kk[yi]);
                kk[yi] = fmaf(kf[yi].y, kf[yi].y, kk[yi]);
            }
#pragma unroll
            for (int xi = 0; xi < XD; xi++){
                float2 qf = __half22float2(q2[xi]);
                qq[xi] = fmaf(qf.x, qf.x, qq[xi]);
                qq[xi] = fmaf(qf.y, qf.y, qq[xi]);
#pragma unroll
                for (int yi = 0; yi < XD; yi++){
                    S[xi][yi] = fmaf(qf.x, kf[yi].x, S[xi][yi]);
                    S[xi][yi] = fmaf(qf.y, kf[yi].y, S[xi][yi]);
                }
            }
        }
    }
    float* acc = g_gram + (b*NHD + n)*80;
    int lane = tid & 31;
#pragma unroll
    for (int xi = 0; xi < XD; xi++){
#pragma unroll
        for (int yi = 0; yi < XD; yi++){
            float v = warp_sum(S[xi][yi]);
            if (lane == 0) atomicAdd(&acc[xi*8 + yi], v);
        }
        float vq = warp_sum(qq[xi]);
        float vk = warp_sum(kk[xi]);
        if (lane == 0){ atomicAdd(&acc[64 + xi], vq); atomicAdd(&acc[72 + xi], vk); }
    }
}

// ---------------- K4: softmax + effective 64x64 channel matrix ----------------
__global__ void k_weff(const float* __restrict__ temp, const float* __restrict__ aw){
    int b = blockIdx.x, tid = threadIdx.x;
    __shared__ float att[NHD][XD][XD];
    __shared__ float qn[NHD][XD], kn[NHD][XD];
    const float* G = g_gram + b*NHD*80;
    if (tid < 64){
        int i = tid & 31, n = i >> 3, xx = i & 7;
        if (tid < 32) qn[n][xx] = fmaxf(sqrtf(G[n*80 + 64 + xx]), 1e-12f);
        else          kn[n][xx] = fmaxf(sqrtf(G[n*80 + 72 + xx]), 1e-12f);
    }
    __syncthreads();
    if (tid < 32){
        int n = tid >> 3, xx = tid & 7;
        float tpn = temp[n];
        float sc[XD], mx = -1e30f;
#pragma unroll
        for (int y = 0; y < XD; y++){
            sc[y] = G[n*80 + xx*8 + y] / (qn[n][xx]*kn[n][y]) * tpn;
            mx = fmaxf(mx, sc[y]);
        }
        float sum = 0.f;
#pragma unroll
        for (int y = 0; y < XD; y++){ sc[y] = expf(sc[y]-mx); sum += sc[y]; }
        float inv = 1.f/sum;
#pragma unroll
        for (int y = 0; y < XD; y++) att[n][xx][y] = sc[y]*inv;
    }
    __syncthreads();
    for (int e = tid; e < TT*TT; e += blockDim.x){
        int to = e >> 6, tv = e & 63;
        int n = tv >> 4, p = tv & 1, y = (tv >> 1) & 7;
        float s = 0.f;
#pragma unroll
        for (int xx = 0; xx < XD; xx++)
            s = fmaf(aw[to*64 + 16*n + 2*xx + p], att[n][xx][y], s);
        g_weff[b*4096 + e] = s;
    }
}

// ---------------- K5: x + W_eff @ V (prefetched) ----------------
__global__ void __launch_bounds__(256) k_apply(const float* __restrict__ x){
    __shared__ float wsh[TT*TT];                  // [tv][to]
    int tid = threadIdx.x;
    int b = blockIdx.x >> 9;
    for (int i = tid; i < TT*TT; i += 256){
        int tv = i >> 6, to = i & 63;
        wsh[i] = g_weff[b*4096 + to*64 + tv];
    }
    __syncthreads();
    int p = ((blockIdx.x & 511) << 8) + tid;
    const f16* vb = g_qkvdw + ((size_t)b*QKVC + 128)*CHW + p;
    u64 acc[32];
#pragma unroll
    for (int i = 0; i < 32; i++) acc[i] = 0ull;

    f16 pv[8];
#pragma unroll
    for (int i = 0; i < 8; i++) pv[i] = vb[(size_t)i*CHW];
#pragma unroll
    for (int t0 = 0; t0 < TT; t0 += 8){
        f16 nv[8];
        if (t0 < TT-8){
#pragma unroll
            for (int i = 0; i < 8; i++) nv[i] = vb[(size_t)(t0+8+i)*CHW];
        }
#pragma unroll
        for (int i = 0; i < 8; i++){
            u64 v2 = pack_dup(__half2float(pv[i]));
            const ulonglong2* wp = (const ulonglong2*)&wsh[(t0+i)*TT];
#pragma unroll
            for (int q = 0; q < 16; q++){
                ulonglong2 w = wp[q];
                fma2(acc[2*q  ], w.x, v2);
                fma2(acc[2*q+1], w.y, v2);
            }
        }
#pragma unroll
        for (int i = 0; i < 8; i++) pv[i] = nv[i];
    }
    const float* xb = x    + (size_t)b*TT*CHW + p;
    float*       ob = g_xa + (size_t)b*TT*CHW + p;
#pragma unroll
    for (int i = 0; i < 32; i++){
        float2 f = unpack2(acc[i]);
        ob[(size_t)(2*i  )*CHW] = f.x + xb[(size_t)(2*i  )*CHW];
        ob[(size_t)(2*i+1)*CHW] = f.y + xb[(size_t)(2*i+1)*CHW];
    }
}

// ---------------- K6: LN + 1x1 conv 64 -> 340 ----------------
__global__ void __launch_bounds__(256) k_ln_pin(const float* __restrict__ gam,
                                                const float* __restrict__ bet,
                                                const float* __restrict__ pw){
    extern __shared__ float wsh[];
    __shared__ float gsh[TT], bsh[TT];
    int tid = threadIdx.x;
    for (int i = tid; i < TT*PINC; i += 256){
        int t = i / PINC, o = i - t*PINC;
        wsh[i] = pw[o*TT + t];
    }
    if (tid < TT){ gsh[tid] = gam[tid]; bsh[tid] = bet[tid]; }
    __syncthreads();

    int b = blockIdx.x >> 9;
    int p = ((blockIdx.x & 511) << 8) + tid;
    const float* xb = g_xa + (size_t)b*TT*CHW + p;

    float xn[TT];
    float mean = 0.f;
#pragma unroll
    for (int t = 0; t < TT; t++){ xn[t] = xb[(size_t)t*CHW]; mean += xn[t]; }
    mean *= (1.f/TT);
    float var = 0.f;
#pragma unroll
    for (int t = 0; t < TT; t++){ float d = xn[t]-mean; var += d*d; }
    float rstd = rsqrtf(var*(1.f/TT) + 1e-5f);
#pragma unroll
    for (int t = 0; t < TT; t++) xn[t] = (xn[t]-mean)*rstd*gsh[t] + bsh[t];

    f16* ob = g_pin + (size_t)b*PINC*CHW + p;
    for (int og = 0; og < PINC; og += 20){
        u64 acc[10];
#pragma unroll
        for (int i = 0; i < 10; i++) acc[i] = 0ull;
#pragma unroll
        for (int t = 0; t < TT; t++){
            u64 xv2 = pack_dup(xn[t]);
            const ulonglong2* wp = (const ulonglong2*)&wsh[t*PINC + og];
#pragma unroll
            for (int q = 0; q < 5; q++){
                ulonglong2 w = wp[q];
                fma2(acc[2*q  ], w.x, xv2);
                fma2(acc[2*q+1], w.y, xv2);
            }
        }
#pragma unroll
        for (int i = 0; i < 10; i++){
            float2 f = unpack2(acc[i]);
            ob[(size_t)(og+2*i  )*CHW] = __float2half_rn(f.x);
            ob[(size_t)(og+2*i+1)*CHW] = __float2half_rn(f.y);
        }
    }
}

// ---------------- K7: tiled depthwise 3x3x3 + exact GELU gating ----------------
// 64 threads: lanes 0..31 load branch-1 column pairs via half2, lanes 32..63
// branch-2; interleaved packed float2 smem ring (LDS.64 taps in compute).
__global__ void __launch_bounds__(64) k_dw3d(const float* __restrict__ dww){
    __shared__ float2 slP[3][10][68];             // interior cols 2..65, pads 0..1/66..67
    int tid = threadIdx.x;
    int lid = tid & 31;
    int branch = tid >> 5;
    int w  = tid;                                 // compute role: one w column each
    int h0 = blockIdx.x * 8;
    int j  = blockIdx.y, b = blockIdx.z;
    const f16* b1 = g_pin + (size_t)(b*PINC + j)*CHW;
    const f16* b2 = g_pin + (size_t)(b*PINC + j + HIDC)*CHW;
    const f16* src = branch ? b2 : b1;
    f16* op = g_prod + ((size_t)(b*HIDC + j)*CCB)*HW;

    u64 wp[27];
#pragma unroll
    for (int k = 0; k < 27; k++)
        wp[k] = pack2f(__ldg(&dww[j*27 + k]), __ldg(&dww[(j + HIDC)*27 + k]));

    // zero padding columns once (cols 0,1,66,67 of every [s][r])
    for (int i = tid; i < 120; i += 64){
        int s = i/40, rem = i%40, r = rem>>2, c4 = rem&3;
        int col = (c4 < 2) ? c4 : 64 + c4;
        slP[s][r][col].x = 0.f; slP[s][r][col].y = 0.f;
    }

    // loader lambda-equivalent
    float* sbase = &slP[0][0][0].x;
    auto load_slice = [&](int c, int s){
#pragma unroll
        for (int r = 0; r < 10; r++){
            int h = h0 - 1 + r;
            float2 f; f.x = 0.f; f.y = 0.f;
            if (c >= 0 && c < CCB && h >= 0 && h < 64){
                __half2 hv = *(const __half2*)(src + (size_t)c*HW + h*64 + 2*lid);
                f = __half22float2(hv);
            }
            float* rowb = sbase + ((s*10 + r)*68)*2;
            rowb[2*(2 + 2*lid) + branch] = f.x;
            rowb[2*(3 + 2*lid) + branch] = f.y;
        }
    };

    load_slice(-1, 0);
    load_slice( 0, 1);

    for (int cz = 0; cz < 32; cz++){
        __syncthreads();
        load_slice(cz+1, (cz+2)%3);
        __syncthreads();

        u64 rr_[3][9];
#pragma unroll
        for (int dc = 0; dc < 3; dc++){
            int buf = (cz + dc) % 3;
#pragma unroll
            for (int dw = 0; dw < 3; dw++){
                rr_[0][dc*3+dw] = *(const u64*)&slP[buf][0][1 + w + dw];
                rr_[1][dc*3+dw] = *(const u64*)&slP[buf][1][1 + w + dw];
            }
        }
#pragma unroll
        for (int hh = 0; hh < 8; hh++){
            int inw = (hh+2)%3;
#pragma unroll
            for (int dc = 0; dc < 3; dc++){
                int buf = (cz + dc) % 3;
#pragma unroll
                for (int dw = 0; dw < 3; dw++)
                    rr_[inw][dc*3+dw] = *(const u64*)&slP[buf][hh+2][1 + w + dw];
            }
            const u64* rm = rr_[hh%3];
            const u64* rc = rr_[(hh+1)%3];
            const u64* rp = rr_[inw];
            u64 acc = 0ull;
#pragma unroll
            for (int dc = 0; dc < 3; dc++){
#pragma unroll
                for (int dw = 0; dw < 3; dw++){
                    fma2(acc, wp[dc*9 + 0*3 + dw], rm[dc*3+dw]);
                    fma2(acc, wp[dc*9 + 1*3 + dw], rc[dc*3+dw]);
                    fma2(acc, wp[dc*9 + 2*3 + dw], rp[dc*3+dw]);
                }
            }
            float2 a = unpack2(acc);
            float g = 0.5f*a.x*(1.f + erff(a.x*0.70710678118654752f));
            op[(size_t)cz*HW + (h0+hh)*64 + w] = __float2half_rn(g*a.y);
        }
    }
}

// ---------------- K8: 1x1 conv 170->64 + residual + SE pooling (prefetched) ----------------
__global__ void __launch_bounds__(256) k_pout(const float* __restrict__ pw,
                                              float* __restrict__ dout){
    __shared__ float wsh[HIDC*TT];                // [t][o]
    __shared__ float pool[TT];
    int tid = threadIdx.x;
    for (int i = tid; i < HIDC*TT; i += 256){
        int t = i >> 6, o = i & 63;
        wsh[i] = pw[o*HIDC + t];
    }
    if (tid < TT) pool[tid] = 0.f;
    __syncthreads();

    int b = blockIdx.x >> 9;
    int p = ((blockIdx.x & 511) << 8) + tid;
    const f16* pr = g_prod + (size_t)b*HIDC*CHW + p;

    u64 acc[32];
#pragma unroll
    for (int i = 0; i < 32; i++) acc[i] = 0ull;

    f16 pv[10];
#pragma unroll
    for (int i = 0; i < 10; i++) pv[i] = pr[(size_t)i*CHW];
#pragma unroll 1
    for (int t0 = 0; t0 < HIDC; t0 += 10){
        f16 nv[10];
        if (t0 < HIDC-10){
#pragma unroll
            for (int i = 0; i < 10; i++) nv[i] = pr[(size_t)(t0+10+i)*CHW];
        }
#pragma unroll
        for (int i = 0; i < 10; i++){
            u64 v2 = pack_dup(__half2float(pv[i]));
            const ulonglong2* wp = (const ulonglong2*)&wsh[(t0+i)*TT];
#pragma unroll
            for (int q = 0; q < 16; q++){
                ulonglong2 w = wp[q];
                fma2(acc[2*q  ], w.x, v2);
                fma2(acc[2*q+1], w.y, v2);
            }
        }
#pragma unroll
        for (int i = 0; i < 10; i++) pv[i] = nv[i];
    }
    const float* xb = g_xa + (size_t)b*TT*CHW + p;
    float*       ob = dout + (size_t)b*TT*CHW + p;
    int lane = tid & 31;
#pragma unroll
    for (int i = 0; i < 32; i++){
        float2 f = unpack2(acc[i]);
        float r0 = f.x + xb[(size_t)(2*i  )*CHW];
        float r1 = f.y + xb[(size_t)(2*i+1)*CHW];
        ob[(size_t)(2*i  )*CHW] = r0;
        ob[(size_t)(2*i+1)*CHW] = r1;
        float v0 = warp_sum(r0);
        float v1 = warp_sum(r1);
        if (lane == 0){ atomicAdd(&pool[2*i], v0); atomicAdd(&pool[2*i+1], v1); }
    }
    __syncthreads();
    if (tid < TT) atomicAdd(&g_pool[b*TT + tid], pool[tid]);
}

// ---------------- K9: SE gate ----------------
__global__ void k_se(const float* __restrict__ sew, const float* __restrict__ seb){
    int tid = threadIdx.x;
    if (tid >= BB*TT) return;
    int b = tid >> 6, o = tid & 63;
    float s = 0.f;
#pragma unroll
    for (int t = 0; t < TT; t++)
        s = fmaf(sew[o*TT + t], g_pool[b*TT + t]*(1.f/131072.f), s);
    s += seb[o];
    g_se[b*TT + o] = 1.f/(1.f + expf(-s));
}

// ---------------- K10: in-place SE scale ----------------
__global__ void k_final(float* __restrict__ dout){
    int idx = blockIdx.x*256 + threadIdx.x;
    float4* o4 = (float4*)dout;
    float s = g_se[idx >> 15];
    float4 v = o4[idx];
    v.x *= s; v.y *= s; v.z *= s; v.w *= s;
    o4[idx] = v;
}

// ---------------- launch ----------------
extern "C" void kernel_launch(void* const* d_in, const int* in_sizes, int n_in,
                              void* d_out, int out_size){
    const float* x     = (const float*)d_in[0];
    const float* n1g   = (const float*)d_in[1];
    const float* n1b   = (const float*)d_in[2];
    const float* temp  = (const float*)d_in[3];
    const float* qkvw  = (const float*)d_in[4];
    const float* qkvdw = (const float*)d_in[5];
    const float* aow   = (const float*)d_in[6];
    const float* n2g   = (const float*)d_in[7];
    const float* n2b   = (const float*)d_in[8];
    const float* pinw  = (const float*)d_in[9];
    const float* dww   = (const float*)d_in[10];
    const float* poutw = (const float*)d_in[11];
    const float* sew   = (const float*)d_in[12];
    const float* seb   = (const float*)d_in[13];
    float* out = (float*)d_out;

    cudaFuncSetAttribute(k_ln_pin, cudaFuncAttributeMaxDynamicSharedMemorySize,
                         TT*PINC*(int)sizeof(float));
    cudaFuncSetAttribute(k_ln_qkv, cudaFuncAttributeMaxDynamicSharedMemorySize,
                         TT*QKVC*(int)sizeof(float));

    k_init  <<<1, 1024>>>();
    k_ln_qkv<<<1024, 256, TT*QKVC*sizeof(float)>>>(x, n1g, n1b, qkvw);
    k_dw2d  <<<BB*QKVC*CCB, 256>>>(qkvdw);
    k_gram  <<<dim3(64, NHD, BB), 256>>>();
    k_weff  <<<BB, 256>>>(temp, aow);
    k_apply <<<1024, 256>>>(x);
    k_ln_pin<<<1024, 256, TT*PINC*sizeof(float)>>>(n2g, n2b, pinw);
    k_dw3d  <<<dim3(8, HIDC, BB), 64>>>(dww);
    k_pout  <<<1024, 256>>>(poutw, out);
    k_se    <<<1, 128>>>(sew, seb);
    k_final <<<16384, 256>>>(out);
}

// round 16
// speedup vs baseline: 1.8954x; 1.4964x over previous
#include <cuda_runtime.h>
#include <cuda_fp16.h>
#include <math.h>

#define BB   2
#define TT   64
#define CCB  32
#define HW   4096
#define CHW  131072
#define NHD  4
#define XD   8
#define HIDC 170
#define QKVC 192
#define PINC 340

typedef unsigned long long u64;
typedef __half f16;

// ---------------- packed f32x2 helpers ----------------
__device__ __forceinline__ u64 pack2f(float a, float b){
    u64 r;
    asm("mov.b64 %0, {%1, %2};" : "=l"(r)
        : "r"(__float_as_uint(a)), "r"(__float_as_uint(b)));
    return r;
}
__device__ __forceinline__ u64 pack_dup(float a){
    unsigned ai = __float_as_uint(a);
    u64 r;
    asm("mov.b64 %0, {%1, %1};" : "=l"(r) : "r"(ai));
    return r;
}
__device__ __forceinline__ void fma2(u64 &d, u64 a, u64 b){
    asm("fma.rn.f32x2 %0, %1, %2, %0;" : "+l"(d) : "l"(a), "l"(b));
}
__device__ __forceinline__ float2 unpack2(u64 v){
    unsigned lo, hi;
    asm("mov.b64 {%0, %1}, %2;" : "=r"(lo), "=r"(hi) : "l"(v));
    float2 f; f.x = __uint_as_float(lo); f.y = __uint_as_float(hi);
    return f;
}
__device__ __forceinline__ void mma16816(float&c0,float&c1,float&c2,float&c3,
   unsigned a0,unsigned a1,unsigned a2,unsigned a3,unsigned b0,unsigned b1){
  asm volatile("mma.sync.aligned.m16n8k16.row.col.f32.f16.f16.f32 "
    "{%0,%1,%2,%3}, {%4,%5,%6,%7}, {%8,%9}, {%0,%1,%2,%3};"
    : "+f"(c0),"+f"(c1),"+f"(c2),"+f"(c3)
    : "r"(a0),"r"(a1),"r"(a2),"r"(a3),"r"(b0),"r"(b1));
}

// ---------------- scratch (static device, allocation-free) ----------------
__device__ f16   g_qkv  [BB*QKVC*CHW];
__device__ f16   g_qkvdw[BB*QKVC*CHW];
__device__ float g_xa   [BB*TT*CHW];
__device__ f16   g_pin  [BB*PINC*CHW];
__device__ f16   g_prod [BB*HIDC*CHW];
__device__ float g_gram [BB*NHD*80];
__device__ float g_weff [BB*TT*TT];
__device__ float g_pool [BB*TT];
__device__ float g_se   [BB*TT];

__device__ __forceinline__ float warp_sum(float v){
    v += __shfl_xor_sync(0xffffffffu, v, 16);
    v += __shfl_xor_sync(0xffffffffu, v, 8);
    v += __shfl_xor_sync(0xffffffffu, v, 4);
    v += __shfl_xor_sync(0xffffffffu, v, 2);
    v += __shfl_xor_sync(0xffffffffu, v, 1);
    return v;
}

// ---------------- K0 ----------------
__global__ void k_init(){
    int t = threadIdx.x;
    if (t < BB*NHD*80) g_gram[t] = 0.f;
    if (t < BB*TT)     g_pool[t] = 0.f;
}

// ---------------- K1/K6: LN(channel) + 1x1 conv via tensor-core mma ----------------
// Block: 256 positions (512 blocks per batch!). smem: A [256][72] f16,
// W [NPAD][72] f16 ([o][k] = mma B^T), Cstage [32][264] f16.
template<int NOUT, int NPAD>
__global__ void __launch_bounds__(256) k_ln_gemm(const float* __restrict__ src,
                                                 const float* __restrict__ gam,
                                                 const float* __restrict__ bet,
                                                 const float* __restrict__ wglob,
                                                 f16* __restrict__ dst){
    extern __shared__ f16 sm[];
    f16* smA = sm;                       // 256*72
    f16* smW = sm + 256*72;              // NPAD*72
    f16* smC = smW + NPAD*72;            // 32*264
    __shared__ float gsh[TT], bsh[TT];

    int tid = threadIdx.x, lane = tid & 31, warp = tid >> 5;
    int gid = lane >> 2, qid = lane & 3;

    if (tid < TT){ gsh[tid] = gam[tid]; bsh[tid] = bet[tid]; }

    // stage weights: wglob[o*64+t] -> smW[o][t] fp16, zero pad rows
    for (int i = tid; i < NPAD*64; i += 256){
        int o = i >> 6, t = i & 63;
        float w = (o < NOUT) ? wglob[o*TT + t] : 0.f;
        smW[o*72 + t] = __float2half_rn(w);
    }

    // phase 1: stream x, accumulate LN stats, store raw fp16 to own smA row
    int b  = blockIdx.x >> 9;                     // 512 blocks per batch
    int p0 = (blockIdx.x & 511) << 8;
    const float* xb = src + (size_t)b*TT*CHW + p0 + tid;
    float s = 0.f, s2 = 0.f;
#pragma unroll
    for (int t = 0; t < TT; t += 2){
        float v0 = xb[(size_t)t*CHW], v1 = xb[(size_t)(t+1)*CHW];
        s += v0 + v1;
        s2 = fmaf(v0, v0, fmaf(v1, v1, s2));
        *(half2*)&smA[tid*72 + t] = __floats2half2_rn(v0, v1);
    }
    float mean = s*(1.f/64.f);
    float var  = s2*(1.f/64.f) - mean*mean;
    float rstd = rsqrtf(var + 1e-5f);
    __syncthreads();                     // gsh ready (smA own-row needs no sync)
#pragma unroll
    for (int t = 0; t < TT; t += 2){
        float2 f = __half22float2(*(half2*)&smA[tid*72 + t]);
        f.x = (f.x - mean)*rstd*gsh[t]   + bsh[t];
        f.y = (f.y - mean)*rstd*gsh[t+1] + bsh[t+1];
        *(half2*)&smA[tid*72 + t] = __floats2half2_rn(f.x, f.y);
    }
    __syncthreads();                     // A + W ready for all warps

    const int NT_TILES = NPAD/8;
    f16* ob = dst + (size_t)b*NOUT*CHW + p0;
    for (int g0 = 0; g0 < NT_TILES; g0 += 4){
        int ntg = (NT_TILES - g0 < 4) ? (NT_TILES - g0) : 4;
#pragma unroll
        for (int mt = warp; mt < 16; mt += 8){
            unsigned a[4][4];
#pragma unroll
            for (int ks = 0; ks < 4; ks++){
                int row = mt*16 + gid, col = ks*16 + qid*2;
                a[ks][0] = *(unsigned*)&smA[ row   *72 + col];
                a[ks][1] = *(unsigned*)&smA[(row+8)*72 + col];
                a[ks][2] = *(unsigned*)&smA[ row   *72 + col + 8];
                a[ks][3] = *(unsigned*)&smA[(row+8)*72 + col + 8];
            }
            for (int nt = 0; nt < ntg; nt++){
                int n0 = (g0 + nt)*8;
                float c0=0.f, c1=0.f, c2=0.f, c3=0.f;
#pragma unroll
                for (int ks = 0; ks < 4; ks++){
                    unsigned b0 = *(unsigned*)&smW[(n0+gid)*72 + ks*16 + qid*2];
                    unsigned b1 = *(unsigned*)&smW[(n0+gid)*72 + ks*16 + qid*2 + 8];
                    mma16816(c0,c1,c2,c3, a[ks][0],a[ks][1],a[ks][2],a[ks][3], b0,b1);
                }
                int ol = nt*8 + qid*2, p = mt*16 + gid;
                smC[ ol   *264 + p    ] = __float2half_rn(c0);
                smC[(ol+1)*264 + p    ] = __float2half_rn(c1);
                smC[ ol   *264 + p + 8] = __float2half_rn(c2);
                smC[(ol+1)*264 + p + 8] = __float2half_rn(c3);
            }
        }
        __syncthreads();                 // Cstage complete
        for (int i = tid; i < ntg*8*32; i += 256){
            int o = i >> 5, p16 = i & 31;
            int og_ = g0*8 + o;
            if (og_ < NOUT){
                uint4 v = *(uint4*)&smC[o*264 + p16*8];
                *(uint4*)(ob + (size_t)og_*CHW + p16*8) = v;
            }
        }
        __syncthreads();                 // Cstage free for next group
    }
}

// ---------------- K2: depthwise 3x3 (H,W), smem-staged ----------------
__global__ void __launch_bounds__(256) k_dw2d(const float* __restrict__ dww){
    __shared__ __half s[66][80];
    int tid = threadIdx.x;
    int plane = blockIdx.x;
    int ch = (plane >> 5) % QKVC;
    const f16* ip = g_qkv   + (size_t)plane*HW;
    f16*       op = g_qkvdw + (size_t)plane*HW;

    uint4 z4; z4.x = z4.y = z4.z = z4.w = 0u;
    for (int i = tid; i < 660; i += 256) ((uint4*)s)[i] = z4;
    __syncthreads();
    for (int i = tid; i < 512; i += 256){
        int r = i >> 3, c8 = i & 7;
        uint4 v = ((const uint4*)(ip + r*64))[c8];
        *(uint4*)&s[1+r][8 + c8*8] = v;
    }
    float wv[9];
#pragma unroll
    for (int k = 0; k < 9; k++) wv[k] = __ldg(&dww[ch*9 + k]);
    __syncthreads();

    int h  = tid >> 2;
    int wq = (tid & 3) << 4;
    float c0[3], c1[3];
#pragma unroll
    for (int dh = 0; dh < 3; dh++){
        c0[dh] = __half2float(s[h+dh][7+wq]);
        c1[dh] = __half2float(s[h+dh][8+wq]);
    }
    __align__(16) __half res[16];
#pragma unroll
    for (int w = 0; w < 16; w++){
        float c2[3];
#pragma unroll
        for (int dh = 0; dh < 3; dh++) c2[dh] = __half2float(s[h+dh][9+wq+w]);
        float o = wv[0]*c0[0] + wv[1]*c1[0] + wv[2]*c2[0]
                + wv[3]*c0[1] + wv[4]*c1[1] + wv[5]*c2[1]
                + wv[6]*c0[2] + wv[7]*c1[2] + wv[8]*c2[2];
        res[w] = __float2half_rn(o);
#pragma unroll
        for (int dh = 0; dh < 3; dh++){ c0[dh] = c1[dh]; c1[dh] = c2[dh]; }
    }
    uint4* o4 = (uint4*)(op + h*64 + wq);
    o4[0] = *(uint4*)&res[0];
    o4[1] = *(uint4*)&res[8];
}

// ---------------- K3: per-head 8x8 Gram ----------------
__global__ void __launch_bounds__(256, 2) k_gram(){
    int tid = threadIdx.x;
    int chunk = blockIdx.x;
    int n = blockIdx.y, b = blockIdx.z;
    const f16* qb = g_qkvdw + ((size_t)b*QKVC + 16*n)*CHW;
    const f16* kb = qb + (size_t)64*CHW;

    float S[XD][XD], qq[XD], kk[XD];
#pragma unroll
    for (int xi = 0; xi < XD; xi++){
        qq[xi] = 0.f; kk[xi] = 0.f;
#pragma unroll
        for (int yi = 0; yi < XD; yi++) S[xi][yi] = 0.f;
    }
    int p0 = chunk*2048 + tid*2;
#pragma unroll
    for (int it = 0; it < 4; it++){
        int p = p0 + it*512;
#pragma unroll
        for (int par = 0; par < 2; par++){
            __half2 q2[XD], k2[XD];
#pragma unroll
            for (int xi = 0; xi < XD; xi++){
                q2[xi] = *(const __half2*)(qb + (size_t)(2*xi + par)*CHW + p);
                k2[xi] = *(const __half2*)(kb + (size_t)(2*xi + par)*CHW + p);
            }
            float2 kf[XD];
#pragma unroll
            for (int yi = 0; yi < XD; yi++){
                kf[yi] = __half22float2(k2[yi]);
                kk[yi] = fmaf(kf[yi].x, kf[yi].x, kk[yi]);
                kk[yi] = fmaf(kf[yi].y, kf[yi].y, kk[yi]);
            }
#pragma unroll
            for (int xi = 0; xi < XD; xi++){
                float2 qf = __half22float2(q2[xi]);
                qq[xi] = fmaf(qf.x, qf.x, qq[xi]);
                qq[xi] = fmaf(qf.y, qf.y, qq[xi]);
#pragma unroll
                for (int yi = 0; yi < XD; yi++){
                    S[xi][yi] = fmaf(qf.x, kf[yi].x, S[xi][yi]);
                    S[xi][yi] = fmaf(qf.y, kf[yi].y, S[xi][yi]);
                }
            }
        }
    }
    float* acc = g_gram + (b*NHD + n)*80;
    int lane = tid & 31;
#pragma unroll
    for (int xi = 0; xi < XD; xi++){
#pragma unroll
        for (int yi = 0; yi < XD; yi++){
            float v = warp_sum(S[xi][yi]);
            if (lane == 0) atomicAdd(&acc[xi*8 + yi], v);
        }
        float vq = warp_sum(qq[xi]);
        float vk = warp_sum(kk[xi]);
        if (lane == 0){ atomicAdd(&acc[64 + xi], vq); atomicAdd(&acc[72 + xi], vk); }
    }
}

// ---------------- K4: softmax + effective 64x64 channel matrix ----------------
__global__ void k_weff(const float* __restrict__ temp, const float* __restrict__ aw){
    int b = blockIdx.x, tid = threadIdx.x;
    __shared__ float att[NHD][XD][XD];
    __shared__ float qn[NHD][XD], kn[NHD][XD];
    const float* G = g_gram + b*NHD*80;
    if (tid < 64){
        int i = tid & 31, n = i >> 3, xx = i & 7;
        if (tid < 32) qn[n][xx] = fmaxf(sqrtf(G[n*80 + 64 + xx]), 1e-12f);
        else          kn[n][xx] = fmaxf(sqrtf(G[n*80 + 72 + xx]), 1e-12f);
    }
    __syncthreads();
    if (tid < 32){
        int n = tid >> 3, xx = tid & 7;
        float tpn = temp[n];
        float sc[XD], mx = -1e30f;
#pragma unroll
        for (int y = 0; y < XD; y++){
            sc[y] = G[n*80 + xx*8 + y] / (qn[n][xx]*kn[n][y]) * tpn;
            mx = fmaxf(mx, sc[y]);
        }
        float sum = 0.f;
#pragma unroll
        for (int y = 0; y < XD; y++){ sc[y] = expf(sc[y]-mx); sum += sc[y]; }
        float inv = 1.f/sum;
#pragma unroll
        for (int y = 0; y < XD; y++) att[n][xx][y] = sc[y]*inv;
    }
    __syncthreads();
    for (int e = tid; e < TT*TT; e += blockDim.x){
        int to = e >> 6, tv = e & 63;
        int n = tv >> 4, p = tv & 1, y = (tv >> 1) & 7;
        float s = 0.f;
#pragma unroll
        for (int xx = 0; xx < XD; xx++)
            s = fmaf(aw[to*64 + 16*n + 2*xx + p], att[n][xx][y], s);
        g_weff[b*4096 + e] = s;
    }
}

// ---------------- K5: x + W_eff @ V (prefetched) ----------------
__global__ void __launch_bounds__(256) k_apply(const float* __restrict__ x){
    __shared__ float wsh[TT*TT];
    int tid = threadIdx.x;
    int b = blockIdx.x >> 9;
    for (int i = tid; i < TT*TT; i += 256){
        int tv = i >> 6, to = i & 63;
        wsh[i] = g_weff[b*4096 + to*64 + tv];
    }
    __syncthreads();
    int p = ((blockIdx.x & 511) << 8) + tid;
    const f16* vb = g_qkvdw + ((size_t)b*QKVC + 128)*CHW + p;
    u64 acc[32];
#pragma unroll
    for (int i = 0; i < 32; i++) acc[i] = 0ull;

    f16 pv[8];
#pragma unroll
    for (int i = 0; i < 8; i++) pv[i] = vb[(size_t)i*CHW];
#pragma unroll
    for (int t0 = 0; t0 < TT; t0 += 8){
        f16 nv[8];
        if (t0 < TT-8){
#pragma unroll
            for (int i = 0; i < 8; i++) nv[i] = vb[(size_t)(t0+8+i)*CHW];
        }
#pragma unroll
        for (int i = 0; i < 8; i++){
            u64 v2 = pack_dup(__half2float(pv[i]));
            const ulonglong2* wp = (const ulonglong2*)&wsh[(t0+i)*TT];
#pragma unroll
            for (int q = 0; q < 16; q++){
                ulonglong2 w = wp[q];
                fma2(acc[2*q  ], w.x, v2);
                fma2(acc[2*q+1], w.y, v2);
            }
        }
#pragma unroll
        for (int i = 0; i < 8; i++) pv[i] = nv[i];
    }
    const float* xb = x    + (size_t)b*TT*CHW + p;
    float*       ob = g_xa + (size_t)b*TT*CHW + p;
#pragma unroll
    for (int i = 0; i < 32; i++){
        float2 f = unpack2(acc[i]);
        ob[(size_t)(2*i  )*CHW] = f.x + xb[(size_t)(2*i  )*CHW];
        ob[(size_t)(2*i+1)*CHW] = f.y + xb[(size_t)(2*i+1)*CHW];
    }
}

// ---------------- K7: tiled depthwise 3x3x3 + exact GELU gating ----------------
__global__ void __launch_bounds__(64) k_dw3d(const float* __restrict__ dww){
    __shared__ float2 slP[3][10][68];
    int tid = threadIdx.x;
    int lid = tid & 31;
    int branch = tid >> 5;
    int w  = tid;
    int h0 = blockIdx.x * 8;
    int j  = blockIdx.y, b = blockIdx.z;
    const f16* b1 = g_pin + (size_t)(b*PINC + j)*CHW;
    const f16* b2 = g_pin + (size_t)(b*PINC + j + HIDC)*CHW;
    const f16* src = branch ? b2 : b1;
    f16* op = g_prod + ((size_t)(b*HIDC + j)*CCB)*HW;

    u64 wp[27];
#pragma unroll
    for (int k = 0; k < 27; k++)
        wp[k] = pack2f(__ldg(&dww[j*27 + k]), __ldg(&dww[(j + HIDC)*27 + k]));

    for (int i = tid; i < 120; i += 64){
        int s = i/40, rem = i%40, r = rem>>2, c4 = rem&3;
        int col = (c4 < 2) ? c4 : 64 + c4;
        slP[s][r][col].x = 0.f; slP[s][r][col].y = 0.f;
    }

    float* sbase = &slP[0][0][0].x;
    auto load_slice = [&](int c, int s){
#pragma unroll
        for (int r = 0; r < 10; r++){
            int h = h0 - 1 + r;
            float2 f; f.x = 0.f; f.y = 0.f;
            if (c >= 0 && c < CCB && h >= 0 && h < 64){
                __half2 hv = *(const __half2*)(src + (size_t)c*HW + h*64 + 2*lid);
                f = __half22float2(hv);
            }
            float* rowb = sbase + ((s*10 + r)*68)*2;
            rowb[2*(2 + 2*lid) + branch] = f.x;
            rowb[2*(3 + 2*lid) + branch] = f.y;
        }
    };

    load_slice(-1, 0);
    load_slice( 0, 1);

    for (int cz = 0; cz < 32; cz++){
        __syncthreads();
        load_slice(cz+1, (cz+2)%3);
        __syncthreads();

        u64 rr_[3][9];
#pragma unroll
        for (int dc = 0; dc < 3; dc++){
            int buf = (cz + dc) % 3;
#pragma unroll
            for (int dw = 0; dw < 3; dw++){
                rr_[0][dc*3+dw] = *(const u64*)&slP[buf][0][1 + w + dw];
                rr_[1][dc*3+dw] = *(const u64*)&slP[buf][1][1 + w + dw];
            }
        }
#pragma unroll
        for (int hh = 0; hh < 8; hh++){
            int inw = (hh+2)%3;
#pragma unroll
            for (int dc = 0; dc < 3; dc++){
                int buf = (cz + dc) % 3;
#pragma unroll
                for (int dw = 0; dw < 3; dw++)
                    rr_[inw][dc*3+dw] = *(const u64*)&slP[buf][hh+2][1 + w + dw];
            }
            const u64* rm = rr_[hh%3];
            const u64* rc = rr_[(hh+1)%3];
            const u64* rp = rr_[inw];
            u64 acc = 0ull;
#pragma unroll
            for (int dc = 0; dc < 3; dc++){
#pragma unroll
                for (int dw = 0; dw < 3; dw++){
                    fma2(acc, wp[dc*9 + 0*3 + dw], rm[dc*3+dw]);
                    fma2(acc, wp[dc*9 + 1*3 + dw], rc[dc*3+dw]);
                    fma2(acc, wp[dc*9 + 2*3 + dw], rp[dc*3+dw]);
                }
            }
            float2 a = unpack2(acc);
            float g = 0.5f*a.x*(1.f + erff(a.x*0.70710678118654752f));
            op[(size_t)cz*HW + (h0+hh)*64 + w] = __float2half_rn(g*a.y);
        }
    }
}

// ---------------- K8: 1x1 conv 170->64 + residual + SE pooling ----------------
__global__ void __launch_bounds__(256) k_pout(const float* __restrict__ pw,
                                              float* __restrict__ dout){
    __shared__ float wsh[HIDC*TT];
    __shared__ float pool[TT];
    int tid = threadIdx.x;
    for (int i = tid; i < HIDC*TT; i += 256){
        int t = i >> 6, o = i & 63;
        wsh[i] = pw[o*HIDC + t];
    }
    if (tid < TT) pool[tid] = 0.f;
    __syncthreads();

    int b = blockIdx.x >> 9;
    int p = ((blockIdx.x & 511) << 8) + tid;
    const f16* pr = g_prod + (size_t)b*HIDC*CHW + p;

    u64 acc[32];
#pragma unroll
    for (int i = 0; i < 32; i++) acc[i] = 0ull;

    f16 pv[10];
#pragma unroll
    for (int i = 0; i < 10; i++) pv[i] = pr[(size_t)i*CHW];
#pragma unroll 1
    for (int t0 = 0; t0 < HIDC; t0 += 10){
        f16 nv[10];
        if (t0 < HIDC-10){
#pragma unroll
            for (int i = 0; i < 10; i++) nv[i] = pr[(size_t)(t0+10+i)*CHW];
        }
#pragma unroll
        for (int i = 0; i < 10; i++){
            u64 v2 = pack_dup(__half2float(pv[i]));
            const ulonglong2* wp = (const ulonglong2*)&wsh[(t0+i)*TT];
#pragma unroll
            for (int q = 0; q < 16; q++){
                ulonglong2 w = wp[q];
                fma2(acc[2*q  ], w.x, v2);
                fma2(acc[2*q+1], w.y, v2);
            }
        }
#pragma unroll
        for (int i = 0; i < 10; i++) pv[i] = nv[i];
    }
    const float* xb = g_xa + (size_t)b*TT*CHW + p;
    float*       ob = dout + (size_t)b*TT*CHW + p;
    int lane = tid & 31;
#pragma unroll
    for (int i = 0; i < 32; i++){
        float2 f = unpack2(acc[i]);
        float r0 = f.x + xb[(size_t)(2*i  )*CHW];
        float r1 = f.y + xb[(size_t)(2*i+1)*CHW];
        ob[(size_t)(2*i  )*CHW] = r0;
        ob[(size_t)(2*i+1)*CHW] = r1;
        float v0 = warp_sum(r0);
        float v1 = warp_sum(r1);
        if (lane == 0){ atomicAdd(&pool[2*i], v0); atomicAdd(&pool[2*i+1], v1); }
    }
    __syncthreads();
    if (tid < TT) atomicAdd(&g_pool[b*TT + tid], pool[tid]);
}

// ---------------- K9: SE gate ----------------
__global__ void k_se(const float* __restrict__ sew, const float* __restrict__ seb){
    int tid = threadIdx.x;
    if (tid >= BB*TT) return;
    int b = tid >> 6, o = tid & 63;
    float s = 0.f;
#pragma unroll
    for (int t = 0; t < TT; t++)
        s = fmaf(sew[o*TT + t], g_pool[b*TT + t]*(1.f/131072.f), s);
    s += seb[o];
    g_se[b*TT + o] = 1.f/(1.f + expf(-s));
}

// ---------------- K10: in-place SE scale ----------------
__global__ void k_final(float* __restrict__ dout){
    int idx = blockIdx.x*256 + threadIdx.x;
    float4* o4 = (float4*)dout;
    float s = g_se[idx >> 15];
    float4 v = o4[idx];
    v.x *= s; v.y *= s; v.z *= s; v.w *= s;
    o4[idx] = v;
}

// ---------------- launch ----------------
extern "C" void kernel_launch(void* const* d_in, const int* in_sizes, int n_in,
                              void* d_out, int out_size){
    const float* x     = (const float*)d_in[0];
    const float* n1g   = (const float*)d_in[1];
    const float* n1b   = (const float*)d_in[2];
    const float* temp  = (const float*)d_in[3];
    const float* qkvw  = (const float*)d_in[4];
    const float* qkvdw = (const float*)d_in[5];
    const float* aow   = (const float*)d_in[6];
    const float* n2g   = (const float*)d_in[7];
    const float* n2b   = (const float*)d_in[8];
    const float* pinw  = (const float*)d_in[9];
    const float* dww   = (const float*)d_in[10];
    const float* poutw = (const float*)d_in[11];
    const float* sew   = (const float*)d_in[12];
    const float* seb   = (const float*)d_in[13];
    float* out = (float*)d_out;

    const int SM_QKV = (256*72 + 192*72 + 32*264) * 2;   //  81408 B
    const int SM_PIN = (256*72 + 344*72 + 32*264) * 2;   // 103296 B
    cudaFuncSetAttribute(k_ln_gemm<QKVC,192>,
        cudaFuncAttributeMaxDynamicSharedMemorySize, SM_QKV);
    cudaFuncSetAttribute(k_ln_gemm<PINC,344>,
        cudaFuncAttributeMaxDynamicSharedMemorySize, SM_PIN);

    f16* gq; f16* gp; float* gxa;
    cudaGetSymbolAddress((void**)&gq,  g_qkv);
    cudaGetSymbolAddress((void**)&gp,  g_pin);
    cudaGetSymbolAddress((void**)&gxa, g_xa);

    k_init  <<<1, 1024>>>();
    k_ln_gemm<QKVC,192><<<BB*512, 256, SM_QKV>>>(x, n1g, n1b, qkvw, gq);
    k_dw2d  <<<BB*QKVC*CCB, 256>>>(qkvdw);
    k_gram  <<<dim3(64, NHD, BB), 256>>>();
    k_weff  <<<BB, 256>>>(temp, aow);
    k_apply <<<1024, 256>>>(x);
    k_ln_gemm<PINC,344><<<BB*512, 256, SM_PIN>>>(gxa, n2g, n2b, pinw, gp);
    k_dw3d  <<<dim3(8, HIDC, BB), 64>>>(dww);
    k_pout  <<<1024, 256>>>(poutw, out);
    k_se    <<<1, 128>>>(sew, seb);
    k_final <<<16384, 256>>>(out);
}

// round 17
// speedup vs baseline: 2.1888x; 1.1548x over previous
#include <cuda_runtime.h>
#include <cuda_fp16.h>
#include <math.h>

#define BB   2
#define TT   64
#define CCB  32
#define HW   4096
#define CHW  131072
#define NHD  4
#define XD   8
#define HIDC 170
#define QKVC 192
#define PINC 340

typedef unsigned long long u64;
typedef __half f16;

// ---------------- packed f32x2 helpers ----------------
__device__ __forceinline__ u64 pack2f(float a, float b){
    u64 r;
    asm("mov.b64 %0, {%1, %2};" : "=l"(r)
        : "r"(__float_as_uint(a)), "r"(__float_as_uint(b)));
    return r;
}
__device__ __forceinline__ void fma2(u64 &d, u64 a, u64 b){
    asm("fma.rn.f32x2 %0, %1, %2, %0;" : "+l"(d) : "l"(a), "l"(b));
}
__device__ __forceinline__ float2 unpack2(u64 v){
    unsigned lo, hi;
    asm("mov.b64 {%0, %1}, %2;" : "=r"(lo), "=r"(hi) : "l"(v));
    float2 f; f.x = __uint_as_float(lo); f.y = __uint_as_float(hi);
    return f;
}
__device__ __forceinline__ void mma16816(float&c0,float&c1,float&c2,float&c3,
   unsigned a0,unsigned a1,unsigned a2,unsigned a3,unsigned b0,unsigned b1){
  asm volatile("mma.sync.aligned.m16n8k16.row.col.f32.f16.f16.f32 "
    "{%0,%1,%2,%3}, {%4,%5,%6,%7}, {%8,%9}, {%0,%1,%2,%3};"
    : "+f"(c0),"+f"(c1),"+f"(c2),"+f"(c3)
    : "r"(a0),"r"(a1),"r"(a2),"r"(a3),"r"(b0),"r"(b1));
}

// ---------------- scratch (static device, allocation-free) ----------------
__device__ f16   g_qkv  [BB*QKVC*CHW];
__device__ f16   g_qkvdw[BB*QKVC*CHW];
__device__ float g_xa   [BB*TT*CHW];
__device__ f16   g_pin  [BB*PINC*CHW];
__device__ f16   g_prod [BB*HIDC*CHW];
__device__ float g_gram [BB*NHD*80];
__device__ float g_weff [BB*TT*TT];
__device__ float g_pool [BB*TT];
__device__ float g_se   [BB*TT];

__device__ __forceinline__ float warp_sum(float v){
    v += __shfl_xor_sync(0xffffffffu, v, 16);
    v += __shfl_xor_sync(0xffffffffu, v, 8);
    v += __shfl_xor_sync(0xffffffffu, v, 4);
    v += __shfl_xor_sync(0xffffffffu, v, 2);
    v += __shfl_xor_sync(0xffffffffu, v, 1);
    return v;
}

// ---------------- K0 ----------------
__global__ void k_init(){
    int t = threadIdx.x;
    if (t < BB*NHD*80) g_gram[t] = 0.f;
    if (t < BB*TT)     g_pool[t] = 0.f;
}

// ---------------- K1/K6: LN(channel) + 1x1 conv via tensor-core mma ----------------
template<int NOUT, int NPAD>
__global__ void __launch_bounds__(256) k_ln_gemm(const float* __restrict__ src,
                                                 const float* __restrict__ gam,
                                                 const float* __restrict__ bet,
                                                 const float* __restrict__ wglob,
                                                 f16* __restrict__ dst){
    extern __shared__ f16 sm[];
    f16* smA = sm;                       // 256*72
    f16* smW = sm + 256*72;              // NPAD*72
    f16* smC = smW + NPAD*72;            // 32*264
    __shared__ float gsh[TT], bsh[TT];

    int tid = threadIdx.x, lane = tid & 31, warp = tid >> 5;
    int gid = lane >> 2, qid = lane & 3;

    if (tid < TT){ gsh[tid] = gam[tid]; bsh[tid] = bet[tid]; }

    for (int i = tid; i < NPAD*64; i += 256){
        int o = i >> 6, t = i & 63;
        float w = (o < NOUT) ? wglob[o*TT + t] : 0.f;
        smW[o*72 + t] = __float2half_rn(w);
    }

    int b  = blockIdx.x >> 9;                     // 512 blocks per batch
    int p0 = (blockIdx.x & 511) << 8;
    const float* xb = src + (size_t)b*TT*CHW + p0 + tid;
    float s = 0.f, s2 = 0.f;
#pragma unroll
    for (int t = 0; t < TT; t += 2){
        float v0 = xb[(size_t)t*CHW], v1 = xb[(size_t)(t+1)*CHW];
        s += v0 + v1;
        s2 = fmaf(v0, v0, fmaf(v1, v1, s2));
        *(half2*)&smA[tid*72 + t] = __floats2half2_rn(v0, v1);
    }
    float mean = s*(1.f/64.f);
    float var  = s2*(1.f/64.f) - mean*mean;
    float rstd = rsqrtf(var + 1e-5f);
    __syncthreads();
#pragma unroll
    for (int t = 0; t < TT; t += 2){
        float2 f = __half22float2(*(half2*)&smA[tid*72 + t]);
        f.x = (f.x - mean)*rstd*gsh[t]   + bsh[t];
        f.y = (f.y - mean)*rstd*gsh[t+1] + bsh[t+1];
        *(half2*)&smA[tid*72 + t] = __floats2half2_rn(f.x, f.y);
    }
    __syncthreads();

    const int NT_TILES = NPAD/8;
    f16* ob = dst + (size_t)b*NOUT*CHW + p0;
    for (int g0 = 0; g0 < NT_TILES; g0 += 4){
        int ntg = (NT_TILES - g0 < 4) ? (NT_TILES - g0) : 4;
#pragma unroll
        for (int mt = warp; mt < 16; mt += 8){
            unsigned a[4][4];
#pragma unroll
            for (int ks = 0; ks < 4; ks++){
                int row = mt*16 + gid, col = ks*16 + qid*2;
                a[ks][0] = *(unsigned*)&smA[ row   *72 + col];
                a[ks][1] = *(unsigned*)&smA[(row+8)*72 + col];
                a[ks][2] = *(unsigned*)&smA[ row   *72 + col + 8];
                a[ks][3] = *(unsigned*)&smA[(row+8)*72 + col + 8];
            }
            for (int nt = 0; nt < ntg; nt++){
                int n0 = (g0 + nt)*8;
                float c0=0.f, c1=0.f, c2=0.f, c3=0.f;
#pragma unroll
                for (int ks = 0; ks < 4; ks++){
                    unsigned b0 = *(unsigned*)&smW[(n0+gid)*72 + ks*16 + qid*2];
                    unsigned b1 = *(unsigned*)&smW[(n0+gid)*72 + ks*16 + qid*2 + 8];
                    mma16816(c0,c1,c2,c3, a[ks][0],a[ks][1],a[ks][2],a[ks][3], b0,b1);
                }
                int ol = nt*8 + qid*2, p = mt*16 + gid;
                smC[ ol   *264 + p    ] = __float2half_rn(c0);
                smC[(ol+1)*264 + p    ] = __float2half_rn(c1);
                smC[ ol   *264 + p + 8] = __float2half_rn(c2);
                smC[(ol+1)*264 + p + 8] = __float2half_rn(c3);
            }
        }
        __syncthreads();
        for (int i = tid; i < ntg*8*32; i += 256){
            int o = i >> 5, p16 = i & 31;
            int og_ = g0*8 + o;
            if (og_ < NOUT){
                uint4 v = *(uint4*)&smC[o*264 + p16*8];
                *(uint4*)(ob + (size_t)og_*CHW + p16*8) = v;
            }
        }
        __syncthreads();
    }
}

// ---------------- K2: depthwise 3x3 (H,W), smem-staged ----------------
__global__ void __launch_bounds__(256) k_dw2d(const float* __restrict__ dww){
    __shared__ __half s[66][80];
    int tid = threadIdx.x;
    int plane = blockIdx.x;
    int ch = (plane >> 5) % QKVC;
    const f16* ip = g_qkv   + (size_t)plane*HW;
    f16*       op = g_qkvdw + (size_t)plane*HW;

    uint4 z4; z4.x = z4.y = z4.z = z4.w = 0u;
    for (int i = tid; i < 660; i += 256) ((uint4*)s)[i] = z4;
    __syncthreads();
    for (int i = tid; i < 512; i += 256){
        int r = i >> 3, c8 = i & 7;
        uint4 v = ((const uint4*)(ip + r*64))[c8];
        *(uint4*)&s[1+r][8 + c8*8] = v;
    }
    float wv[9];
#pragma unroll
    for (int k = 0; k < 9; k++) wv[k] = __ldg(&dww[ch*9 + k]);
    __syncthreads();

    int h  = tid >> 2;
    int wq = (tid & 3) << 4;
    float c0[3], c1[3];
#pragma unroll
    for (int dh = 0; dh < 3; dh++){
        c0[dh] = __half2float(s[h+dh][7+wq]);
        c1[dh] = __half2float(s[h+dh][8+wq]);
    }
    __align__(16) __half res[16];
#pragma unroll
    for (int w = 0; w < 16; w++){
        float c2[3];
#pragma unroll
        for (int dh = 0; dh < 3; dh++) c2[dh] = __half2float(s[h+dh][9+wq+w]);
        float o = wv[0]*c0[0] + wv[1]*c1[0] + wv[2]*c2[0]
                + wv[3]*c0[1] + wv[4]*c1[1] + wv[5]*c2[1]
                + wv[6]*c0[2] + wv[7]*c1[2] + wv[8]*c2[2];
        res[w] = __float2half_rn(o);
#pragma unroll
        for (int dh = 0; dh < 3; dh++){ c0[dh] = c1[dh]; c1[dh] = c2[dh]; }
    }
    uint4* o4 = (uint4*)(op + h*64 + wq);
    o4[0] = *(uint4*)&res[0];
    o4[1] = *(uint4*)&res[8];
}

// ---------------- K3: per-head 8x8 Gram ----------------
__global__ void __launch_bounds__(256, 2) k_gram(){
    int tid = threadIdx.x;
    int chunk = blockIdx.x;
    int n = blockIdx.y, b = blockIdx.z;
    const f16* qb = g_qkvdw + ((size_t)b*QKVC + 16*n)*CHW;
    const f16* kb = qb + (size_t)64*CHW;

    float S[XD][XD], qq[XD], kk[XD];
#pragma unroll
    for (int xi = 0; xi < XD; xi++){
        qq[xi] = 0.f; kk[xi] = 0.f;
#pragma unroll
        for (int yi = 0; yi < XD; yi++) S[xi][yi] = 0.f;
    }
    int p0 = chunk*2048 + tid*2;
#pragma unroll
    for (int it = 0; it < 4; it++){
        int p = p0 + it*512;
#pragma unroll
        for (int par = 0; par < 2; par++){
            __half2 q2[XD], k2[XD];
#pragma unroll
            for (int xi = 0; xi < XD; xi++){
                q2[xi] = *(const __half2*)(qb + (size_t)(2*xi + par)*CHW + p);
                k2[xi] = *(const __half2*)(kb + (size_t)(2*xi + par)*CHW + p);
            }
            float2 kf[XD];
#pragma unroll
            for (int yi = 0; yi < XD; yi++){
                kf[yi] = __half22float2(k2[yi]);
                kk[yi] = fmaf(kf[yi].x, kf[yi].x, kk[yi]);
                kk[yi] = fmaf(kf[yi].y, kf[yi].y, kk[yi]);
            }
#pragma unroll
            for (int xi = 0; xi < XD; xi++){
                float2 qf = __half22float2(q2[xi]);
                qq[xi] = fmaf(qf.x, qf.x, qq[xi]);
                qq[xi] = fmaf(qf.y, qf.y, qq[xi]);
#pragma unroll
                for (int yi = 0; yi < XD; yi++){
                    S[xi][yi] = fmaf(qf.x, kf[yi].x, S[xi][yi]);
                    S[xi][yi] = fmaf(qf.y, kf[yi].y, S[xi][yi]);
                }
            }
        }
    }
    float* acc = g_gram + (b*NHD + n)*80;
    int lane = tid & 31;
#pragma unroll
    for (int xi = 0; xi < XD; xi++){
#pragma unroll
        for (int yi = 0; yi < XD; yi++){
            float v = warp_sum(S[xi][yi]);
            if (lane == 0) atomicAdd(&acc[xi*8 + yi], v);
        }
        float vq = warp_sum(qq[xi]);
        float vk = warp_sum(kk[xi]);
        if (lane == 0){ atomicAdd(&acc[64 + xi], vq); atomicAdd(&acc[72 + xi], vk); }
    }
}

// ---------------- K4: softmax + effective 64x64 channel matrix ----------------
__global__ void k_weff(const float* __restrict__ temp, const float* __restrict__ aw){
    int b = blockIdx.x, tid = threadIdx.x;
    __shared__ float att[NHD][XD][XD];
    __shared__ float qn[NHD][XD], kn[NHD][XD];
    const float* G = g_gram + b*NHD*80;
    if (tid < 64){
        int i = tid & 31, n = i >> 3, xx = i & 7;
        if (tid < 32) qn[n][xx] = fmaxf(sqrtf(G[n*80 + 64 + xx]), 1e-12f);
        else          kn[n][xx] = fmaxf(sqrtf(G[n*80 + 72 + xx]), 1e-12f);
    }
    __syncthreads();
    if (tid < 32){
        int n = tid >> 3, xx = tid & 7;
        float tpn = temp[n];
        float sc[XD], mx = -1e30f;
#pragma unroll
        for (int y = 0; y < XD; y++){
            sc[y] = G[n*80 + xx*8 + y] / (qn[n][xx]*kn[n][y]) * tpn;
            mx = fmaxf(mx, sc[y]);
        }
        float sum = 0.f;
#pragma unroll
        for (int y = 0; y < XD; y++){ sc[y] = expf(sc[y]-mx); sum += sc[y]; }
        float inv = 1.f/sum;
#pragma unroll
        for (int y = 0; y < XD; y++) att[n][xx][y] = sc[y]*inv;
    }
    __syncthreads();
    for (int e = tid; e < TT*TT; e += blockDim.x){
        int to = e >> 6, tv = e & 63;
        int n = tv >> 4, p = tv & 1, y = (tv >> 1) & 7;
        float s = 0.f;
#pragma unroll
        for (int xx = 0; xx < XD; xx++)
            s = fmaf(aw[to*64 + 16*n + 2*xx + p], att[n][xx][y], s);
        g_weff[b*4096 + e] = s;
    }
}

// ---------------- K5: x + W_eff @ V via tensor-core mma ----------------
// smem: A [256][72] f16 (V), W [64][72] f16, C [32][264] f16.
__global__ void __launch_bounds__(256) k_apply_mma(const float* __restrict__ x){
    extern __shared__ f16 sm[];
    f16* smA = sm;                       // 256*72
    f16* smW = sm + 256*72;              // 64*72
    f16* smC = smW + 64*72;              // 32*264

    int tid = threadIdx.x, lane = tid & 31, warp = tid >> 5;
    int gid = lane >> 2, qid = lane & 3;
    int b  = blockIdx.x >> 9;
    int p0 = (blockIdx.x & 511) << 8;

    // stage W_eff fp16: [to][tv]
    for (int i = tid; i < TT*TT; i += 256){
        int o = i >> 6, t = i & 63;
        smW[o*72 + t] = __float2half_rn(g_weff[b*4096 + o*64 + t]);
    }
    // stage V: [pos][tv]
    const f16* vb = g_qkvdw + ((size_t)b*QKVC + 128)*CHW + p0;
    for (int i = tid; i < 64*128; i += 256){
        int tv = i >> 7, pp = i & 127;
        __half2 hv = *(const __half2*)(vb + (size_t)tv*CHW + 2*pp);
        smA[(2*pp  )*72 + tv] = __low2half(hv);
        smA[(2*pp+1)*72 + tv] = __high2half(hv);
    }
    __syncthreads();

    const float* xb = x    + (size_t)b*TT*CHW + p0;
    float*       ob = g_xa + (size_t)b*TT*CHW + p0;
    for (int g0 = 0; g0 < 8; g0 += 4){
#pragma unroll
        for (int mt = warp; mt < 16; mt += 8){
            unsigned a[4][4];
#pragma unroll
            for (int ks = 0; ks < 4; ks++){
                int row = mt*16 + gid, col = ks*16 + qid*2;
                a[ks][0] = *(unsigned*)&smA[ row   *72 + col];
                a[ks][1] = *(unsigned*)&smA[(row+8)*72 + col];
                a[ks][2] = *(unsigned*)&smA[ row   *72 + col + 8];
                a[ks][3] = *(unsigned*)&smA[(row+8)*72 + col + 8];
            }
#pragma unroll
            for (int nt = 0; nt < 4; nt++){
                int n0 = (g0 + nt)*8;
                float c0=0.f, c1=0.f, c2=0.f, c3=0.f;
#pragma unroll
                for (int ks = 0; ks < 4; ks++){
                    unsigned b0 = *(unsigned*)&smW[(n0+gid)*72 + ks*16 + qid*2];
                    unsigned b1 = *(unsigned*)&smW[(n0+gid)*72 + ks*16 + qid*2 + 8];
                    mma16816(c0,c1,c2,c3, a[ks][0],a[ks][1],a[ks][2],a[ks][3], b0,b1);
                }
                int ol = nt*8 + qid*2, p = mt*16 + gid;
                smC[ ol   *264 + p    ] = __float2half_rn(c0);
                smC[(ol+1)*264 + p    ] = __float2half_rn(c1);
                smC[ ol   *264 + p + 8] = __float2half_rn(c2);
                smC[(ol+1)*264 + p + 8] = __float2half_rn(c3);
            }
        }
        __syncthreads();
        for (int i = tid; i < 4*8*32; i += 256){
            int o = i >> 5, p16 = i & 31;
            int og_ = g0*8 + o;
            uint4 v = *(uint4*)&smC[o*264 + p16*8];
            const __half* hp = (const __half*)&v;
            const float* xr = xb + (size_t)og_*CHW + p16*8;
            float*       orr= ob + (size_t)og_*CHW + p16*8;
            float4 r0 = *(const float4*)xr;
            float4 r1 = *(const float4*)(xr + 4);
            float4 o0, o1;
            o0.x = __half2float(hp[0]) + r0.x;
            o0.y = __half2float(hp[1]) + r0.y;
            o0.z = __half2float(hp[2]) + r0.z;
            o0.w = __half2float(hp[3]) + r0.w;
            o1.x = __half2float(hp[4]) + r1.x;
            o1.y = __half2float(hp[5]) + r1.y;
            o1.z = __half2float(hp[6]) + r1.z;
            o1.w = __half2float(hp[7]) + r1.w;
            *(float4*)orr       = o0;
            *(float4*)(orr + 4) = o1;
        }
        __syncthreads();
    }
}

// ---------------- K7: tiled depthwise 3x3x3 + exact GELU gating ----------------
__global__ void __launch_bounds__(64) k_dw3d(const float* __restrict__ dww){
    __shared__ float2 slP[3][10][68];
    int tid = threadIdx.x;
    int lid = tid & 31;
    int branch = tid >> 5;
    int w  = tid;
    int h0 = blockIdx.x * 8;
    int j  = blockIdx.y, b = blockIdx.z;
    const f16* b1 = g_pin + (size_t)(b*PINC + j)*CHW;
    const f16* b2 = g_pin + (size_t)(b*PINC + j + HIDC)*CHW;
    const f16* src = branch ? b2 : b1;
    f16* op = g_prod + ((size_t)(b*HIDC + j)*CCB)*HW;

    u64 wp[27];
#pragma unroll
    for (int k = 0; k < 27; k++)
        wp[k] = pack2f(__ldg(&dww[j*27 + k]), __ldg(&dww[(j + HIDC)*27 + k]));

    for (int i = tid; i < 120; i += 64){
        int s = i/40, rem = i%40, r = rem>>2, c4 = rem&3;
        int col = (c4 < 2) ? c4 : 64 + c4;
        slP[s][r][col].x = 0.f; slP[s][r][col].y = 0.f;
    }

    float* sbase = &slP[0][0][0].x;
    auto load_slice = [&](int c, int s){
#pragma unroll
        for (int r = 0; r < 10; r++){
            int h = h0 - 1 + r;
            float2 f; f.x = 0.f; f.y = 0.f;
            if (c >= 0 && c < CCB && h >= 0 && h < 64){
                __half2 hv = *(const __half2*)(src + (size_t)c*HW + h*64 + 2*lid);
                f = __half22float2(hv);
            }
            float* rowb = sbase + ((s*10 + r)*68)*2;
            rowb[2*(2 + 2*lid) + branch] = f.x;
            rowb[2*(3 + 2*lid) + branch] = f.y;
        }
    };

    load_slice(-1, 0);
    load_slice( 0, 1);

    for (int cz = 0; cz < 32; cz++){
        __syncthreads();
        load_slice(cz+1, (cz+2)%3);
        __syncthreads();

        u64 rr_[3][9];
#pragma unroll
        for (int dc = 0; dc < 3; dc++){
            int buf = (cz + dc) % 3;
#pragma unroll
            for (int dw = 0; dw < 3; dw++){
                rr_[0][dc*3+dw] = *(const u64*)&slP[buf][0][1 + w + dw];
                rr_[1][dc*3+dw] = *(const u64*)&slP[buf][1][1 + w + dw];
            }
        }
#pragma unroll
        for (int hh = 0; hh < 8; hh++){
            int inw = (hh+2)%3;
#pragma unroll
            for (int dc = 0; dc < 3; dc++){
                int buf = (cz + dc) % 3;
#pragma unroll
                for (int dw = 0; dw < 3; dw++)
                    rr_[inw][dc*3+dw] = *(const u64*)&slP[buf][hh+2][1 + w + dw];
            }
            const u64* rm = rr_[hh%3];
            const u64* rc = rr_[(hh+1)%3];
            const u64* rp = rr_[inw];
            u64 acc = 0ull;
#pragma unroll
            for (int dc = 0; dc < 3; dc++){
#pragma unroll
                for (int dw = 0; dw < 3; dw++){
                    fma2(acc, wp[dc*9 + 0*3 + dw], rm[dc*3+dw]);
                    fma2(acc, wp[dc*9 + 1*3 + dw], rc[dc*3+dw]);
                    fma2(acc, wp[dc*9 + 2*3 + dw], rp[dc*3+dw]);
                }
            }
            float2 a = unpack2(acc);
            float g = 0.5f*a.x*(1.f + erff(a.x*0.70710678118654752f));
            op[(size_t)cz*HW + (h0+hh)*64 + w] = __float2half_rn(g*a.y);
        }
    }
}

// ---------------- K8: 1x1 conv 170->64 + residual + SE pool via mma ----------------
// smem: A [256][184] f16 (prod, K padded 170->176), W [64][184] f16, C [32][264] f16.
__global__ void __launch_bounds__(256) k_pout_mma(const float* __restrict__ pw,
                                                  float* __restrict__ dout){
    extern __shared__ f16 sm[];
    f16* smA = sm;                       // 256*184
    f16* smW = sm + 256*184;             // 64*184
    f16* smC = smW + 64*184;             // 32*264
    __shared__ float pool[TT];

    int tid = threadIdx.x, lane = tid & 31, warp = tid >> 5;
    int gid = lane >> 2, qid = lane & 3;
    int b  = blockIdx.x >> 9;
    int p0 = (blockIdx.x & 511) << 8;

    if (tid < TT) pool[tid] = 0.f;

    // stage W: [o][t], zero-pad t=170..175
    for (int i = tid; i < 64*176; i += 256){
        int o = i / 176, t = i - o*176;
        float w = (t < HIDC) ? pw[o*HIDC + t] : 0.f;
        smW[o*184 + t] = __float2half_rn(w);
    }
    // zero A pad cols 170..175
    for (int i = tid; i < 256*6; i += 256){
        int p = i / 6, t = 170 + i % 6;
        smA[p*184 + t] = __float2half_rn(0.f);
    }
    // stage A: prod [pos][t]
    const f16* pr = g_prod + (size_t)b*HIDC*CHW + p0;
    for (int i = tid; i < HIDC*128; i += 256){
        int t = i >> 7, pp = i & 127;
        __half2 hv = *(const __half2*)(pr + (size_t)t*CHW + 2*pp);
        smA[(2*pp  )*184 + t] = __low2half(hv);
        smA[(2*pp+1)*184 + t] = __high2half(hv);
    }
    __syncthreads();

    const float* xb = g_xa + (size_t)b*TT*CHW + p0;
    float*       ob = dout + (size_t)b*TT*CHW + p0;
    for (int g0 = 0; g0 < 8; g0 += 4){
#pragma unroll
        for (int mt = warp; mt < 16; mt += 8){
            unsigned a[11][4];
#pragma unroll
            for (int ks = 0; ks < 11; ks++){
                int row = mt*16 + gid, col = ks*16 + qid*2;
                a[ks][0] = *(unsigned*)&smA[ row   *184 + col];
                a[ks][1] = *(unsigned*)&smA[(row+8)*184 + col];
                a[ks][2] = *(unsigned*)&smA[ row   *184 + col + 8];
                a[ks][3] = *(unsigned*)&smA[(row+8)*184 + col + 8];
            }
#pragma unroll
            for (int nt = 0; nt < 4; nt++){
                int n0 = (g0 + nt)*8;
                float c0=0.f, c1=0.f, c2=0.f, c3=0.f;
#pragma unroll
                for (int ks = 0; ks < 11; ks++){
                    unsigned b0 = *(unsigned*)&smW[(n0+gid)*184 + ks*16 + qid*2];
                    unsigned b1 = *(unsigned*)&smW[(n0+gid)*184 + ks*16 + qid*2 + 8];
                    mma16816(c0,c1,c2,c3, a[ks][0],a[ks][1],a[ks][2],a[ks][3], b0,b1);
                }
                int ol = nt*8 + qid*2, p = mt*16 + gid;
                smC[ ol   *264 + p    ] = __float2half_rn(c0);
                smC[(ol+1)*264 + p    ] = __float2half_rn(c1);
                smC[ ol   *264 + p + 8] = __float2half_rn(c2);
                smC[(ol+1)*264 + p + 8] = __float2half_rn(c3);
            }
        }
        __syncthreads();
        for (int i = tid; i < 4*8*32; i += 256){
            int o = i >> 5, p16 = i & 31;
            int og_ = g0*8 + o;
            uint4 v = *(uint4*)&smC[o*264 + p16*8];
            const __half* hp = (const __half*)&v;
            const float* xr = xb + (size_t)og_*CHW + p16*8;
            float*       orr= ob + (size_t)og_*CHW + p16*8;
            float4 r0 = *(const float4*)xr;
            float4 r1 = *(const float4*)(xr + 4);
            float4 o0, o1;
            o0.x = __half2float(hp[0]) + r0.x;
            o0.y = __half2float(hp[1]) + r0.y;
            o0.z = __half2float(hp[2]) + r0.z;
            o0.w = __half2float(hp[3]) + r0.w;
            o1.x = __half2float(hp[4]) + r1.x;
            o1.y = __half2float(hp[5]) + r1.y;
            o1.z = __half2float(hp[6]) + r1.z;
            o1.w = __half2float(hp[7]) + r1.w;
            *(float4*)orr       = o0;
            *(float4*)(orr + 4) = o1;
            float s8 = (o0.x + o0.y) + (o0.z + o0.w)
                     + (o1.x + o1.y) + (o1.z + o1.w);
            atomicAdd(&pool[og_], s8);
        }
        __syncthreads();
    }
    if (tid < TT) atomicAdd(&g_pool[b*TT + tid], pool[tid]);
}

// ---------------- K9: SE gate ----------------
__global__ void k_se(const float* __restrict__ sew, const float* __restrict__ seb){
    int tid = threadIdx.x;
    if (tid >= BB*TT) return;
    int b = tid >> 6, o = tid & 63;
    float s = 0.f;
#pragma unroll
    for (int t = 0; t < TT; t++)
        s = fmaf(sew[o*TT + t], g_pool[b*TT + t]*(1.f/131072.f), s);
    s += seb[o];
    g_se[b*TT + o] = 1.f/(1.f + expf(-s));
}

// ---------------- K10: in-place SE scale ----------------
__global__ void k_final(float* __restrict__ dout){
    int idx = blockIdx.x*256 + threadIdx.x;
    float4* o4 = (float4*)dout;
    float s = g_se[idx >> 15];
    float4 v = o4[idx];
    v.x *= s; v.y *= s; v.z *= s; v.w *= s;
    o4[idx] = v;
}

// ---------------- launch ----------------
extern "C" void kernel_launch(void* const* d_in, const int* in_sizes, int n_in,
                              void* d_out, int out_size){
    const float* x     = (const float*)d_in[0];
    const float* n1g   = (const float*)d_in[1];
    const float* n1b   = (const float*)d_in[2];
    const float* temp  = (const float*)d_in[3];
    const float* qkvw  = (const float*)d_in[4];
    const float* qkvdw = (const float*)d_in[5];
    const float* aow   = (const float*)d_in[6];
    const float* n2g   = (const float*)d_in[7];
    const float* n2b   = (const float*)d_in[8];
    const float* pinw  = (const float*)d_in[9];
    const float* dww   = (const float*)d_in[10];
    const float* poutw = (const float*)d_in[11];
    const float* sew   = (const float*)d_in[12];
    const float* seb   = (const float*)d_in[13];
    float* out = (float*)d_out;

    const int SM_QKV   = (256*72  + 192*72 + 32*264) * 2;   //  81408 B
    const int SM_PIN   = (256*72  + 344*72 + 32*264) * 2;   // 103296 B
    const int SM_APPLY = (256*72  +  64*72 + 32*264) * 2;   //  62976 B
    const int SM_POUT  = (256*184 +  64*184 + 32*264) * 2;  // 134656 B
    cudaFuncSetAttribute(k_ln_gemm<QKVC,192>,
        cudaFuncAttributeMaxDynamicSharedMemorySize, SM_QKV);
    cudaFuncSetAttribute(k_ln_gemm<PINC,344>,
        cudaFuncAttributeMaxDynamicSharedMemorySize, SM_PIN);
    cudaFuncSetAttribute(k_apply_mma,
        cudaFuncAttributeMaxDynamicSharedMemorySize, SM_APPLY);
    cudaFuncSetAttribute(k_pout_mma,
        cudaFuncAttributeMaxDynamicSharedMemorySize, SM_POUT);

    f16* gq; f16* gp; float* gxa;
    cudaGetSymbolAddress((void**)&gq,  g_qkv);
    cudaGetSymbolAddress((void**)&gp,  g_pin);
    cudaGetSymbolAddress((void**)&gxa, g_xa);

    k_init  <<<1, 1024>>>();
    k_ln_gemm<QKVC,192><<<BB*512, 256, SM_QKV>>>(x, n1g, n1b, qkvw, gq);
    k_dw2d  <<<BB*QKVC*CCB, 256>>>(qkvdw);
    k_gram  <<<dim3(64, NHD, BB), 256>>>();
    k_weff  <<<BB, 256>>>(temp, aow);
    k_apply_mma<<<BB*512, 256, SM_APPLY>>>(x);
    k_ln_gemm<PINC,344><<<BB*512, 256, SM_PIN>>>(gxa, n2g, n2b, pinw, gp);
    k_dw3d  <<<dim3(8, HIDC, BB), 64>>>(dww);
    k_pout_mma<<<BB*512, 256, SM_POUT>>>(poutw, out);
    k_se    <<<1, 128>>>(sew, seb);
    k_final <<<16384, 256>>>(out);
}